// round 1
// baseline (speedup 1.0000x reference)
#include <cuda_runtime.h>
#include <math.h>

#define D    128
#define HH   256
#define TT   3
#define GG   64
#define EMAX 100000

// ---------------- device scratch (no allocations allowed) ----------------
__device__ float g_link [EMAX * D];   // evolving link_state
__device__ float g_edges[EMAX * D];   // segment-summed messages
__device__ float g_gs   [GG * D];     // graph_state

// ---------------- utility kernels ----------------
__global__ void zero_kernel(float4* p, int n4) {
    int i = blockIdx.x * blockDim.x + threadIdx.x;
    if (i < n4) p[i] = make_float4(0.f, 0.f, 0.f, 0.f);
}

__global__ void copy_kernel(float4* dst, const float4* __restrict__ src, int n4) {
    int i = blockIdx.x * blockDim.x + threadIdx.x;
    if (i < n4) dst[i] = src[i];
}

// ---------------- message MLP + scatter ----------------
// Block: 256 threads, 64 messages. smem holds gathered X [64][256] (64KB dynamic),
// then reused for H1 [64][256].
#define BM 64
__global__ __launch_bounds__(256) void msg_kernel(
    const float* __restrict__ link,
    const int*   __restrict__ sf,
    const int*   __restrict__ ss,
    const float* __restrict__ W1, const float* __restrict__ b1,
    const float* __restrict__ W2, const float* __restrict__ b2,
    float* __restrict__ edges, int M)
{
    extern __shared__ __align__(16) float smem[];          // 64*256 floats
    __shared__ int s_sf[BM];
    __shared__ int s_ss[BM];
    float4* xs4 = (float4*)smem;                           // [64][64] float4

    const int tid = threadIdx.x;
    const int m0  = blockIdx.x * BM;

    if (tid < BM) {
        int mg = m0 + tid;
        int a = -1, b = -1;
        if (mg < M) { a = sf[mg]; b = ss[mg]; }
        s_sf[tid] = a;
        s_ss[tid] = b;
    }
    __syncthreads();

    // gather X: row m = [link[sf[m]] (128) | link[ss[m]] (128)] as 64 float4
    #pragma unroll
    for (int it = 0; it < 16; it++) {
        int idx = it * 256 + tid;            // 0..4095
        int m = idx >> 6;
        int q = idx & 63;
        int e = (q < 32) ? s_sf[m] : s_ss[m];
        float4 v = make_float4(0.f, 0.f, 0.f, 0.f);
        if (e >= 0) v = ((const float4*)link)[e * 32 + (q & 31)];
        xs4[idx] = v;
    }
    __syncthreads();

    // ---- layer 1: h1[m][tid] = relu(b1[tid] + sum_k X[m][k] * W1[k][tid]) ----
    float acc[BM];
    {
        const float bb = b1[tid];
        #pragma unroll
        for (int m = 0; m < BM; m++) acc[m] = bb;
    }
    for (int kb = 0; kb < 2 * D; kb += 4) {
        float w0 = W1[(kb + 0) * HH + tid];
        float w1 = W1[(kb + 1) * HH + tid];
        float w2 = W1[(kb + 2) * HH + tid];
        float w3 = W1[(kb + 3) * HH + tid];
        int q = kb >> 2;
        #pragma unroll
        for (int m = 0; m < BM; m++) {
            float4 x = xs4[m * 64 + q];
            float a = acc[m];
            a = fmaf(x.x, w0, a);
            a = fmaf(x.y, w1, a);
            a = fmaf(x.z, w2, a);
            a = fmaf(x.w, w3, a);
            acc[m] = a;
        }
    }
    __syncthreads();                     // everyone done reading xs
    #pragma unroll
    for (int m = 0; m < BM; m++) smem[m * HH + tid] = fmaxf(acc[m], 0.f);
    __syncthreads();

    // ---- layer 2 + scatter: out[m][col] = relu(b2 + sum_j h1[m][j]*W2[j][col]) ----
    const int col    = tid & (D - 1);
    const int mstart = (tid >> 7) * 32;          // 0 or 32
    float acc2[32];
    {
        const float bb = b2[col];
        #pragma unroll
        for (int m = 0; m < 32; m++) acc2[m] = bb;
    }
    const float4* h1s4 = (const float4*)smem;
    for (int jb = 0; jb < HH; jb += 4) {
        float w0 = W2[(jb + 0) * D + col];
        float w1 = W2[(jb + 1) * D + col];
        float w2 = W2[(jb + 2) * D + col];
        float w3 = W2[(jb + 3) * D + col];
        int q = jb >> 2;
        #pragma unroll
        for (int m = 0; m < 32; m++) {
            float4 h = h1s4[(mstart + m) * 64 + q];
            float a = acc2[m];
            a = fmaf(h.x, w0, a);
            a = fmaf(h.y, w1, a);
            a = fmaf(h.z, w2, a);
            a = fmaf(h.w, w3, a);
            acc2[m] = a;
        }
    }
    #pragma unroll
    for (int m = 0; m < 32; m++) {
        int e = s_ss[mstart + m];
        if (e >= 0) atomicAdd(&edges[e * D + col], fmaxf(acc2[m], 0.f));
    }
}

// ---------------- GRU update (in-place on link_state) ----------------
// Block: 128 threads (one per column), 16 rows.
#define GB 16
__global__ __launch_bounds__(128) void gru_kernel(
    const float* __restrict__ x,           // edges_inputs [E][D]
    float*       __restrict__ h,           // link_state   [E][D], updated in place
    const float* __restrict__ K,           // [D][3D]
    const float* __restrict__ R,           // [D][3D]
    const float* __restrict__ bias,        // [2][3D]
    int E)
{
    __shared__ __align__(16) float xs[GB][D];
    __shared__ __align__(16) float hs[GB][D];
    const int tid = threadIdx.x;
    const int r0  = blockIdx.x * GB;

    #pragma unroll
    for (int it = 0; it < (GB * 32) / 128; it++) {
        int idx = it * 128 + tid;
        int m = idx >> 5, q = idx & 31;
        int e = r0 + m;
        float4 xv = make_float4(0.f, 0.f, 0.f, 0.f);
        float4 hv = xv;
        if (e < E) {
            xv = ((const float4*)x)[e * 32 + q];
            hv = ((const float4*)h)[e * 32 + q];
        }
        ((float4*)xs[m])[q] = xv;
        ((float4*)hs[m])[q] = hv;
    }
    __syncthreads();

    float az[GB], ar[GB], ah[GB], bz[GB], br[GB], bh[GB];
    {
        float b0z = bias[tid],           b0r = bias[D + tid],       b0h = bias[2 * D + tid];
        float b1z = bias[3 * D + tid],   b1r = bias[4 * D + tid],   b1h = bias[5 * D + tid];
        #pragma unroll
        for (int m = 0; m < GB; m++) {
            az[m] = b0z; ar[m] = b0r; ah[m] = b0h;
            bz[m] = b1z; br[m] = b1r; bh[m] = b1h;
        }
    }

    for (int kb = 0; kb < D; kb += 4) {
        float kz[4], kr[4], kh[4], rz[4], rr[4], rh[4];
        #pragma unroll
        for (int i = 0; i < 4; i++) {
            int k = kb + i;
            kz[i] = K[k * 3 * D + tid];
            kr[i] = K[k * 3 * D + D + tid];
            kh[i] = K[k * 3 * D + 2 * D + tid];
            rz[i] = R[k * 3 * D + tid];
            rr[i] = R[k * 3 * D + D + tid];
            rh[i] = R[k * 3 * D + 2 * D + tid];
        }
        int q = kb >> 2;
        #pragma unroll
        for (int m = 0; m < GB; m++) {
            float4 xv = ((const float4*)xs[m])[q];
            float4 hv = ((const float4*)hs[m])[q];
            az[m] = fmaf(xv.x, kz[0], az[m]); az[m] = fmaf(xv.y, kz[1], az[m]);
            az[m] = fmaf(xv.z, kz[2], az[m]); az[m] = fmaf(xv.w, kz[3], az[m]);
            ar[m] = fmaf(xv.x, kr[0], ar[m]); ar[m] = fmaf(xv.y, kr[1], ar[m]);
            ar[m] = fmaf(xv.z, kr[2], ar[m]); ar[m] = fmaf(xv.w, kr[3], ar[m]);
            ah[m] = fmaf(xv.x, kh[0], ah[m]); ah[m] = fmaf(xv.y, kh[1], ah[m]);
            ah[m] = fmaf(xv.z, kh[2], ah[m]); ah[m] = fmaf(xv.w, kh[3], ah[m]);
            bz[m] = fmaf(hv.x, rz[0], bz[m]); bz[m] = fmaf(hv.y, rz[1], bz[m]);
            bz[m] = fmaf(hv.z, rz[2], bz[m]); bz[m] = fmaf(hv.w, rz[3], bz[m]);
            br[m] = fmaf(hv.x, rr[0], br[m]); br[m] = fmaf(hv.y, rr[1], br[m]);
            br[m] = fmaf(hv.z, rr[2], br[m]); br[m] = fmaf(hv.w, rr[3], br[m]);
            bh[m] = fmaf(hv.x, rh[0], bh[m]); bh[m] = fmaf(hv.y, rh[1], bh[m]);
            bh[m] = fmaf(hv.z, rh[2], bh[m]); bh[m] = fmaf(hv.w, rh[3], bh[m]);
        }
    }

    #pragma unroll
    for (int m = 0; m < GB; m++) {
        int e = r0 + m;
        if (e < E) {
            float z  = 1.f / (1.f + expf(-(az[m] + bz[m])));
            float r  = 1.f / (1.f + expf(-(ar[m] + br[m])));
            float hc = tanhf(ah[m] + r * bh[m]);
            float ho = hs[m][tid];
            h[e * D + tid] = z * ho + (1.f - z) * hc;
        }
    }
}

// ---------------- graph segment-sum (sorted graph ids) ----------------
#define GSROWS 512
__global__ __launch_bounds__(128) void graph_sum_kernel(
    const float* __restrict__ link,
    const int*   __restrict__ gid,
    float*       __restrict__ gs, int E)
{
    int tid = threadIdx.x;                  // column 0..127
    int r0 = blockIdx.x * GSROWS;
    if (r0 >= E) return;
    int r1 = min(r0 + GSROWS, E);
    float acc = 0.f;
    int cur = gid[r0];
    for (int r = r0; r < r1; r++) {
        int g = gid[r];
        if (g != cur) {
            atomicAdd(&gs[cur * D + tid], acc);
            acc = 0.f;
            cur = g;
        }
        acc += link[r * D + tid];
    }
    atomicAdd(&gs[cur * D + tid], acc);
}

// ---------------- readout MLP (one block per graph) ----------------
__global__ __launch_bounds__(256) void readout_kernel(
    const float* __restrict__ gs,
    const float* __restrict__ rW1, const float* __restrict__ rb1,
    const float* __restrict__ rW2, const float* __restrict__ rb2,
    const float* __restrict__ rW3, const float* __restrict__ rb3,
    float* __restrict__ out)
{
    __shared__ float s_in[D];
    __shared__ float s_r1[HH];
    __shared__ float s_r2[HH];
    const int g = blockIdx.x;
    const int t = threadIdx.x;

    if (t < D) s_in[t] = gs[g * D + t];
    __syncthreads();

    float a = rb1[t];
    #pragma unroll 4
    for (int k = 0; k < D; k++) a = fmaf(s_in[k], rW1[k * HH + t], a);
    s_r1[t] = fmaxf(a, 0.f);
    __syncthreads();

    float b = rb2[t];
    #pragma unroll 4
    for (int k = 0; k < HH; k++) b = fmaf(s_r1[k], rW2[k * HH + t], b);
    s_r2[t] = fmaxf(b, 0.f) * rW3[t];
    __syncthreads();

    for (int s = 128; s > 0; s >>= 1) {
        if (t < s) s_r2[t] += s_r2[t + s];
        __syncthreads();
    }
    if (t == 0) out[g] = s_r2[0] + rb3[0];
}

// ---------------- launch ----------------
extern "C" void kernel_launch(void* const* d_in, const int* in_sizes, int n_in,
                              void* d_out, int out_size)
{
    const float* link0 = (const float*)d_in[0];
    const int*   sf    = (const int*)  d_in[1];
    const int*   ss    = (const int*)  d_in[2];
    const int*   gid   = (const int*)  d_in[3];
    // d_in[4] = sates_num_edges (scalar, unused; E derived from graph_ids length)
    const float* mW1 = (const float*)d_in[5];
    const float* mb1 = (const float*)d_in[6];
    const float* mW2 = (const float*)d_in[7];
    const float* mb2 = (const float*)d_in[8];
    const float* gk  = (const float*)d_in[9];
    const float* gr  = (const float*)d_in[10];
    const float* gb  = (const float*)d_in[11];
    const float* rW1 = (const float*)d_in[12];
    const float* rb1 = (const float*)d_in[13];
    const float* rW2 = (const float*)d_in[14];
    const float* rb2 = (const float*)d_in[15];
    const float* rW3 = (const float*)d_in[16];
    const float* rb3 = (const float*)d_in[17];
    float* out = (float*)d_out;

    const int M = in_sizes[1];
    const int E = in_sizes[3] <= EMAX ? in_sizes[3] : EMAX;

    float *link, *edges, *gs;
    cudaGetSymbolAddress((void**)&link,  g_link);
    cudaGetSymbolAddress((void**)&edges, g_edges);
    cudaGetSymbolAddress((void**)&gs,    g_gs);

    cudaFuncSetAttribute(msg_kernel, cudaFuncAttributeMaxDynamicSharedMemorySize,
                         BM * 2 * D * (int)sizeof(float));

    const int n4 = E * (D / 4);
    copy_kernel<<<(n4 + 255) / 256, 256>>>((float4*)link, (const float4*)link0, n4);

    for (int t = 0; t < TT; t++) {
        zero_kernel<<<(n4 + 255) / 256, 256>>>((float4*)edges, n4);
        msg_kernel<<<(M + BM - 1) / BM, 256, BM * 2 * D * sizeof(float)>>>(
            link, sf, ss, mW1, mb1, mW2, mb2, edges, M);
        gru_kernel<<<(E + GB - 1) / GB, 128>>>(edges, link, gk, gr, gb, E);
    }

    const int gs4 = GG * D / 4;
    zero_kernel<<<(gs4 + 255) / 256, 256>>>((float4*)gs, gs4);
    graph_sum_kernel<<<(E + GSROWS - 1) / GSROWS, 128>>>(link, gid, gs, E);
    readout_kernel<<<GG, 256>>>(gs, rW1, rb1, rW2, rb2, rW3, rb3, out);
}

// round 4
// speedup vs baseline: 2.3265x; 2.3265x over previous
#include <cuda_runtime.h>
#include <math.h>
#include <stdint.h>

#define D    128
#define HH   256
#define TT   3
#define GG   64
#define EMAX 100000

#define XP   260   // smem stride (floats) for X / XH tiles  (260 % 32 == 4 -> conflict-free frags)
#define WP1  260   // smem stride for 256-wide W chunks
#define WP2  132   // smem stride for 128-wide W chunks

// ---------------- device scratch (no allocations allowed) ----------------
__device__ float g_link [EMAX * D];
__device__ float g_edges[EMAX * D];
__device__ float g_gs   [GG * D];
__device__ float g_w1c  [256 * 256];   // mW1 tf32-rounded
__device__ float g_w2c  [256 * 128];   // mW2 tf32-rounded
__device__ float g_wgc  [256 * 384];   // [gru_kernel ; gru_recurrent] tf32-rounded

// ---------------- PTX helpers (baseline, sm_80+ portable) ----------------
__device__ __forceinline__ uint32_t smem_u32(const void* p) {
    uint32_t a;
    asm("{ .reg .u64 t; cvta.to.shared.u64 t, %1; cvt.u32.u64 %0, t; }" : "=r"(a) : "l"(p));
    return a;
}
__device__ __forceinline__ uint32_t tf32r(float f) {
    uint32_t u; asm("cvt.rna.tf32.f32 %0, %1;" : "=r"(u) : "f"(f)); return u;
}
#define CP16(dst, src) \
    asm volatile("cp.async.ca.shared.global [%0], [%1], 16;" :: "r"(dst), "l"(src) : "memory")
#define CP_COMMIT() asm volatile("cp.async.commit_group;" ::: "memory")
#define CP_WAIT0()  asm volatile("cp.async.wait_group 0;" ::: "memory")

__device__ __forceinline__ void mma_tf32(float d[4],
                                         uint32_t a0, uint32_t a1, uint32_t a2, uint32_t a3,
                                         uint32_t b0, uint32_t b1) {
    asm volatile(
        "mma.sync.aligned.m16n8k8.row.col.f32.tf32.tf32.f32 "
        "{%0,%1,%2,%3}, {%4,%5,%6,%7}, {%8,%9}, {%0,%1,%2,%3};\n"
        : "+f"(d[0]), "+f"(d[1]), "+f"(d[2]), "+f"(d[3])
        : "r"(a0), "r"(a1), "r"(a2), "r"(a3), "r"(b0), "r"(b1));
}

// ---------------- utility kernels ----------------
__global__ void zero_kernel(float4* p, int n4) {
    int i = blockIdx.x * blockDim.x + threadIdx.x;
    if (i < n4) p[i] = make_float4(0.f, 0.f, 0.f, 0.f);
}
__global__ void copy_kernel(float4* dst, const float4* __restrict__ src, int n4) {
    int i = blockIdx.x * blockDim.x + threadIdx.x;
    if (i < n4) dst[i] = src[i];
}
__global__ void prep_tf32(const float* __restrict__ in, float* __restrict__ out, int n) {
    int i = blockIdx.x * blockDim.x + threadIdx.x;
    if (i < n) out[i] = __uint_as_float(tf32r(in[i]));
}
__global__ void prep_wg(const float* __restrict__ gk, const float* __restrict__ gr,
                        float* __restrict__ wgc) {
    int i = blockIdx.x * blockDim.x + threadIdx.x;
    if (i >= 256 * 384) return;
    int k = i / 384, n = i % 384;
    float v = (k < 128) ? gk[k * 384 + n] : gr[(k - 128) * 384 + n];
    wgc[i] = __uint_as_float(tf32r(v));
}

// =====================================================================
// message MLP: gather -> GEMM1(relu) -> GEMM2(relu) -> atomic scatter
// 512 threads, block tile = 128 messages
// =====================================================================
#define MSG_SMEM (2560 + 128 * XP * 4 + 2 * 32 * WP1 * 4)
__global__ __launch_bounds__(512, 1) void msg_mma_kernel(
    const float* __restrict__ link,
    const int*   __restrict__ sf,
    const int*   __restrict__ ss,
    const float* __restrict__ w1c, const float* __restrict__ b1,
    const float* __restrict__ w2c, const float* __restrict__ b2,
    float*       __restrict__ edges, int M)
{
    extern __shared__ __align__(16) char smem[];
    int*      s_sf = (int*)smem;
    int*      s_ss = (int*)(smem + 512);
    float*    s_b1 = (float*)(smem + 1024);
    float*    s_b2 = (float*)(smem + 2048);
    uint32_t* Xs   = (uint32_t*)(smem + 2560);                 // [128][XP]
    uint32_t* Wk   = (uint32_t*)(smem + 2560 + 128 * XP * 4);  // 2 buffers
    const uint32_t u_W = smem_u32(smem) + 2560 + 128 * XP * 4;

    const int tid  = threadIdx.x;
    const int lane = tid & 31;
    const int gid  = lane >> 2, tin = lane & 3;
    const int wid  = tid >> 5;
    const int wm   = wid & 1;       // M half (rows wm*64)
    const int wn   = wid >> 1;      // 0..7
    const int m0   = blockIdx.x * 128;

    if (tid < 128) {
        int mg = m0 + tid;
        s_sf[tid] = (mg < M) ? sf[mg] : -1;
        s_ss[tid] = (mg < M) ? ss[mg] : -1;
    }
    if (tid < 256) s_b1[tid] = b1[tid];
    if (tid < 128) s_b2[tid] = b2[tid];
    __syncthreads();

    // ---- gather X[128][256] (tf32) ----
    const float4* link4 = (const float4*)link;
    #pragma unroll
    for (int it = 0; it < 16; it++) {
        int idx = it * 512 + tid;           // 8192 = 128 rows x 64 f4
        int m = idx >> 6, q = idx & 63;
        int e = (q < 32) ? s_sf[m] : s_ss[m];
        float4 v = make_float4(0.f, 0.f, 0.f, 0.f);
        if (e >= 0) v = link4[e * 32 + (q & 31)];
        uint4 t;
        t.x = tf32r(v.x); t.y = tf32r(v.y); t.z = tf32r(v.z); t.w = tf32r(v.w);
        *(uint4*)&Xs[m * XP + q * 4] = t;
    }

    // ---- W1 chunk loader: chunk c -> buf (32 rows x 256 cols) ----
    auto ldW1 = [&](int c, int buf) {
        const float4* src = (const float4*)w1c + c * 2048;
        #pragma unroll
        for (int i = 0; i < 4; i++) {
            int idx = i * 512 + tid;        // 2048 f4
            uint32_t dst = u_W + (uint32_t)buf * (32 * WP1 * 4)
                         + (uint32_t)(((idx >> 6) * WP1 + (idx & 63) * 4) * 4);
            CP16(dst, src + idx);
        }
    };
    auto ldW2 = [&](int c, int buf) {
        const float4* src = (const float4*)w2c + c * 1024;
        #pragma unroll
        for (int i = 0; i < 2; i++) {
            int idx = i * 512 + tid;        // 1024 f4
            uint32_t dst = u_W + (uint32_t)buf * (32 * WP1 * 4)
                         + (uint32_t)(((idx >> 5) * WP2 + (idx & 31) * 4) * 4);
            CP16(dst, src + idx);
        }
    };

    // ================= GEMM1: H1[128,256] = X @ W1 =================
    float acc[4][4][4];
    #pragma unroll
    for (int a = 0; a < 4; a++)
        #pragma unroll
        for (int b = 0; b < 4; b++)
            #pragma unroll
            for (int i = 0; i < 4; i++) acc[a][b][i] = 0.f;

    ldW1(0, 0); CP_COMMIT();
    for (int c = 0; c < 8; c++) {
        CP_WAIT0(); __syncthreads();
        if (c < 7) { ldW1(c + 1, (c + 1) & 1); CP_COMMIT(); }
        const uint32_t* Ws = Wk + (c & 1) * (32 * WP1);
        #pragma unroll
        for (int ks = 0; ks < 4; ks++) {
            const int kk = c * 32 + ks * 8;      // global k into X  (BUG FIX: was ks*8)
            const int kl = ks * 8;               // chunk-local k into W
            uint32_t afr[4][4];
            #pragma unroll
            for (int mt = 0; mt < 4; mt++) {
                int r = wm * 64 + mt * 16 + gid;
                afr[mt][0] = Xs[r * XP + kk + tin];
                afr[mt][1] = Xs[(r + 8) * XP + kk + tin];
                afr[mt][2] = Xs[r * XP + kk + tin + 4];
                afr[mt][3] = Xs[(r + 8) * XP + kk + tin + 4];
            }
            #pragma unroll
            for (int nt = 0; nt < 4; nt++) {
                int n = wn * 32 + nt * 8 + gid;
                uint32_t b0 = Ws[(kl + tin) * WP1 + n];
                uint32_t b1f = Ws[(kl + tin + 4) * WP1 + n];
                #pragma unroll
                for (int mt = 0; mt < 4; mt++)
                    mma_tf32(acc[mt][nt], afr[mt][0], afr[mt][1], afr[mt][2], afr[mt][3], b0, b1f);
            }
        }
    }
    __syncthreads();   // everyone done reading X

    // ---- epilogue1: H1 = tf32(relu(acc + b1)) back into Xs ----
    #pragma unroll
    for (int mt = 0; mt < 4; mt++)
        #pragma unroll
        for (int nt = 0; nt < 4; nt++) {
            int r = wm * 64 + mt * 16 + gid;
            int cb = wn * 32 + nt * 8 + tin * 2;
            Xs[r * XP + cb]           = tf32r(fmaxf(acc[mt][nt][0] + s_b1[cb], 0.f));
            Xs[r * XP + cb + 1]       = tf32r(fmaxf(acc[mt][nt][1] + s_b1[cb + 1], 0.f));
            Xs[(r + 8) * XP + cb]     = tf32r(fmaxf(acc[mt][nt][2] + s_b1[cb], 0.f));
            Xs[(r + 8) * XP + cb + 1] = tf32r(fmaxf(acc[mt][nt][3] + s_b1[cb + 1], 0.f));
        }
    __syncthreads();

    // ================= GEMM2: OUT[128,128] = H1 @ W2 =================
    float ac2[4][2][4];
    #pragma unroll
    for (int a = 0; a < 4; a++)
        #pragma unroll
        for (int b = 0; b < 2; b++)
            #pragma unroll
            for (int i = 0; i < 4; i++) ac2[a][b][i] = 0.f;

    ldW2(0, 0); CP_COMMIT();
    for (int c = 0; c < 8; c++) {
        CP_WAIT0(); __syncthreads();
        if (c < 7) { ldW2(c + 1, (c + 1) & 1); CP_COMMIT(); }
        const uint32_t* Ws = Wk + (c & 1) * (32 * WP1);
        #pragma unroll
        for (int ks = 0; ks < 4; ks++) {
            const int kk = c * 32 + ks * 8;        // H1 k index
            const int kl = ks * 8;                 // chunk-local
            uint32_t afr[4][4];
            #pragma unroll
            for (int mt = 0; mt < 4; mt++) {
                int r = wm * 64 + mt * 16 + gid;
                afr[mt][0] = Xs[r * XP + kk + tin];
                afr[mt][1] = Xs[(r + 8) * XP + kk + tin];
                afr[mt][2] = Xs[r * XP + kk + tin + 4];
                afr[mt][3] = Xs[(r + 8) * XP + kk + tin + 4];
            }
            #pragma unroll
            for (int nt = 0; nt < 2; nt++) {
                int n = wn * 16 + nt * 8 + gid;
                uint32_t b0 = Ws[(kl + tin) * WP2 + n];
                uint32_t b1f = Ws[(kl + tin + 4) * WP2 + n];
                #pragma unroll
                for (int mt = 0; mt < 4; mt++)
                    mma_tf32(ac2[mt][nt], afr[mt][0], afr[mt][1], afr[mt][2], afr[mt][3], b0, b1f);
            }
        }
    }

    // ---- epilogue2: relu + bias + atomic scatter ----
    #pragma unroll
    for (int mt = 0; mt < 4; mt++)
        #pragma unroll
        for (int nt = 0; nt < 2; nt++) {
            int r  = wm * 64 + mt * 16 + gid;
            int cb = wn * 16 + nt * 8 + tin * 2;
            int e0 = s_ss[r], e1 = s_ss[r + 8];
            if (e0 >= 0) {
                atomicAdd(&edges[e0 * D + cb],     fmaxf(ac2[mt][nt][0] + s_b2[cb], 0.f));
                atomicAdd(&edges[e0 * D + cb + 1], fmaxf(ac2[mt][nt][1] + s_b2[cb + 1], 0.f));
            }
            if (e1 >= 0) {
                atomicAdd(&edges[e1 * D + cb],     fmaxf(ac2[mt][nt][2] + s_b2[cb], 0.f));
                atomicAdd(&edges[e1 * D + cb + 1], fmaxf(ac2[mt][nt][3] + s_b2[cb + 1], 0.f));
            }
        }
}

// =====================================================================
// GRU: [x|h][64,256] @ [K;R] -> z,r,ah,bh ; gate math ; in-place update
// =====================================================================
#define GRU_SMEM (2048 + 64 * XP * 4 + 2 * 32 * WP2 * 4)
__global__ __launch_bounds__(256, 1) void gru_mma_kernel(
    const float* __restrict__ x,            // edges_inputs [E][D]
    float*       __restrict__ h,            // link_state   [E][D]
    const float* __restrict__ wgc,          // [256][384] tf32
    const float* __restrict__ gbias,        // [2][384]
    int E)
{
    extern __shared__ __align__(16) char smem[];
    float*    s_bz  = (float*)smem;                    // [128]
    float*    s_br  = (float*)(smem + 512);
    float*    s_bah = (float*)(smem + 1024);
    float*    s_bbh = (float*)(smem + 1536);
    uint32_t* XH    = (uint32_t*)(smem + 2048);        // [64][XP]
    uint32_t* Wk    = (uint32_t*)(smem + 2048 + 64 * XP * 4);
    const uint32_t u_W = smem_u32(smem) + 2048 + 64 * XP * 4;

    const int tid  = threadIdx.x;
    const int lane = tid & 31;
    const int gid  = lane >> 2, tin = lane & 3;
    const int wid  = tid >> 5;
    const int wm   = wid & 1;       // rows wm*32
    const int wn   = wid >> 1;      // 0..3 cols wn*32
    const int e0   = blockIdx.x * 64;

    if (tid < 128) {
        s_bz[tid]  = gbias[tid]       + gbias[384 + tid];
        s_br[tid]  = gbias[128 + tid] + gbias[512 + tid];
        s_bah[tid] = gbias[256 + tid];
        s_bbh[tid] = gbias[640 + tid];
    }

    // ---- load XH (x cols 0-127 from edges, h cols 128-255 from link), tf32 ----
    const float4* xe4 = (const float4*)x;
    const float4* ln4 = (const float4*)h;
    #pragma unroll
    for (int it = 0; it < 16; it++) {
        int idx = it * 256 + tid;          // 4096 = 64 rows x 64 f4
        int m = idx >> 6, q = idx & 63;
        int e = e0 + m;
        float4 v = make_float4(0.f, 0.f, 0.f, 0.f);
        if (e < E) v = (q < 32) ? xe4[e * 32 + q] : ln4[e * 32 + (q - 32)];
        uint4 t;
        t.x = tf32r(v.x); t.y = tf32r(v.y); t.z = tf32r(v.z); t.w = tf32r(v.w);
        *(uint4*)&XH[m * XP + q * 4] = t;
    }
    __syncthreads();

    auto ldWg = [&](int krow0, int col0, int buf) {
        const float4* src = (const float4*)wgc;
        #pragma unroll
        for (int i = 0; i < 4; i++) {
            int idx = i * 256 + tid;       // 1024 = 32 rows x 32 f4
            int kr = idx >> 5, q = idx & 31;
            uint32_t dst = u_W + (uint32_t)buf * (32 * WP2 * 4)
                         + (uint32_t)((kr * WP2 + q * 4) * 4);
            CP16(dst, src + (krow0 + kr) * 96 + (col0 >> 2) + q);
        }
    };

    float accZ[2][4][4], accR[2][4][4], accA[2][4][4], accB[2][4][4];

    auto gemm_pass = [&](float (&acc)[2][4][4], int col0, int kAoff, int krow0, int nc) {
        #pragma unroll
        for (int a = 0; a < 2; a++)
            #pragma unroll
            for (int b = 0; b < 4; b++)
                #pragma unroll
                for (int i = 0; i < 4; i++) acc[a][b][i] = 0.f;
        ldWg(krow0, col0, 0); CP_COMMIT();
        for (int c = 0; c < nc; c++) {
            CP_WAIT0(); __syncthreads();
            if (c + 1 < nc) { ldWg(krow0 + (c + 1) * 32, col0, (c + 1) & 1); CP_COMMIT(); }
            const uint32_t* Ws = Wk + (c & 1) * (32 * WP2);
            #pragma unroll
            for (int ks = 0; ks < 4; ks++) {
                const int kk = kAoff + c * 32 + ks * 8;
                const int kl = ks * 8;
                uint32_t afr[2][4];
                #pragma unroll
                for (int mt = 0; mt < 2; mt++) {
                    int r = wm * 32 + mt * 16 + gid;
                    afr[mt][0] = XH[r * XP + kk + tin];
                    afr[mt][1] = XH[(r + 8) * XP + kk + tin];
                    afr[mt][2] = XH[r * XP + kk + tin + 4];
                    afr[mt][3] = XH[(r + 8) * XP + kk + tin + 4];
                }
                #pragma unroll
                for (int nt = 0; nt < 4; nt++) {
                    int n = wn * 32 + nt * 8 + gid;
                    uint32_t b0 = Ws[(kl + tin) * WP2 + n];
                    uint32_t b1f = Ws[(kl + tin + 4) * WP2 + n];
                    #pragma unroll
                    for (int mt = 0; mt < 2; mt++)
                        mma_tf32(acc[mt][nt], afr[mt][0], afr[mt][1], afr[mt][2], afr[mt][3], b0, b1f);
                }
            }
        }
        __syncthreads();
    };

    gemm_pass(accZ, 0,   0,   0,   8);   // z  : [x|h] @ [Kz;Rz]
    gemm_pass(accR, 128, 0,   0,   8);   // r  : [x|h] @ [Kr;Rr]
    gemm_pass(accA, 256, 0,   0,   4);   // ah : x @ Kh
    gemm_pass(accB, 256, 128, 128, 4);   // bh : h @ Rh

    // ---- gate math + in-place update ----
    #pragma unroll
    for (int mt = 0; mt < 2; mt++)
        #pragma unroll
        for (int nt = 0; nt < 4; nt++) {
            int cb = wn * 32 + nt * 8 + tin * 2;
            #pragma unroll
            for (int half = 0; half < 2; half++) {
                int r = wm * 32 + mt * 16 + gid + half * 8;
                int e = e0 + r;
                if (e < E) {
                    int i0 = half * 2;
                    float2 ho = *(const float2*)&h[e * D + cb];
                    float z0 = 1.f / (1.f + expf(-(accZ[mt][nt][i0]     + s_bz[cb])));
                    float z1 = 1.f / (1.f + expf(-(accZ[mt][nt][i0 + 1] + s_bz[cb + 1])));
                    float r0 = 1.f / (1.f + expf(-(accR[mt][nt][i0]     + s_br[cb])));
                    float r1 = 1.f / (1.f + expf(-(accR[mt][nt][i0 + 1] + s_br[cb + 1])));
                    float h0 = tanhf(accA[mt][nt][i0]     + s_bah[cb]     + r0 * (accB[mt][nt][i0]     + s_bbh[cb]));
                    float h1 = tanhf(accA[mt][nt][i0 + 1] + s_bah[cb + 1] + r1 * (accB[mt][nt][i0 + 1] + s_bbh[cb + 1]));
                    float2 o;
                    o.x = z0 * ho.x + (1.f - z0) * h0;
                    o.y = z1 * ho.y + (1.f - z1) * h1;
                    *(float2*)&h[e * D + cb] = o;
                }
            }
        }
}

// ---------------- graph segment-sum (sorted graph ids) ----------------
#define GSROWS 512
__global__ __launch_bounds__(128) void graph_sum_kernel(
    const float* __restrict__ link, const int* __restrict__ gid,
    float* __restrict__ gs, int E)
{
    int tid = threadIdx.x;
    int r0 = blockIdx.x * GSROWS;
    if (r0 >= E) return;
    int r1 = min(r0 + GSROWS, E);
    float acc = 0.f;
    int cur = gid[r0];
    for (int r = r0; r < r1; r++) {
        int g = gid[r];
        if (g != cur) {
            atomicAdd(&gs[cur * D + tid], acc);
            acc = 0.f;
            cur = g;
        }
        acc += link[r * D + tid];
    }
    atomicAdd(&gs[cur * D + tid], acc);
}

// ---------------- readout MLP ----------------
__global__ __launch_bounds__(256) void readout_kernel(
    const float* __restrict__ gs,
    const float* __restrict__ rW1, const float* __restrict__ rb1,
    const float* __restrict__ rW2, const float* __restrict__ rb2,
    const float* __restrict__ rW3, const float* __restrict__ rb3,
    float* __restrict__ out)
{
    __shared__ float s_in[D];
    __shared__ float s_r1[HH];
    __shared__ float s_r2[HH];
    const int g = blockIdx.x;
    const int t = threadIdx.x;

    if (t < D) s_in[t] = gs[g * D + t];
    __syncthreads();

    float a = rb1[t];
    #pragma unroll 4
    for (int k = 0; k < D; k++) a = fmaf(s_in[k], rW1[k * HH + t], a);
    s_r1[t] = fmaxf(a, 0.f);
    __syncthreads();

    float b = rb2[t];
    #pragma unroll 4
    for (int k = 0; k < HH; k++) b = fmaf(s_r1[k], rW2[k * HH + t], b);
    s_r2[t] = fmaxf(b, 0.f) * rW3[t];
    __syncthreads();

    for (int s = 128; s > 0; s >>= 1) {
        if (t < s) s_r2[t] += s_r2[t + s];
        __syncthreads();
    }
    if (t == 0) out[g] = s_r2[0] + rb3[0];
}

// ---------------- launch ----------------
extern "C" void kernel_launch(void* const* d_in, const int* in_sizes, int n_in,
                              void* d_out, int out_size)
{
    const float* link0 = (const float*)d_in[0];
    const int*   sf    = (const int*)  d_in[1];
    const int*   ss    = (const int*)  d_in[2];
    const int*   gid   = (const int*)  d_in[3];
    const float* mW1 = (const float*)d_in[5];
    const float* mb1 = (const float*)d_in[6];
    const float* mW2 = (const float*)d_in[7];
    const float* mb2 = (const float*)d_in[8];
    const float* gk  = (const float*)d_in[9];
    const float* gr  = (const float*)d_in[10];
    const float* gb  = (const float*)d_in[11];
    const float* rW1 = (const float*)d_in[12];
    const float* rb1 = (const float*)d_in[13];
    const float* rW2 = (const float*)d_in[14];
    const float* rb2 = (const float*)d_in[15];
    const float* rW3 = (const float*)d_in[16];
    const float* rb3 = (const float*)d_in[17];
    float* out = (float*)d_out;

    const int M = in_sizes[1];
    const int E = in_sizes[3] <= EMAX ? in_sizes[3] : EMAX;

    float *link, *edges, *gs, *w1c, *w2c, *wgc;
    cudaGetSymbolAddress((void**)&link,  g_link);
    cudaGetSymbolAddress((void**)&edges, g_edges);
    cudaGetSymbolAddress((void**)&gs,    g_gs);
    cudaGetSymbolAddress((void**)&w1c,   g_w1c);
    cudaGetSymbolAddress((void**)&w2c,   g_w2c);
    cudaGetSymbolAddress((void**)&wgc,   g_wgc);

    cudaFuncSetAttribute(msg_mma_kernel, cudaFuncAttributeMaxDynamicSharedMemorySize, MSG_SMEM);
    cudaFuncSetAttribute(gru_mma_kernel, cudaFuncAttributeMaxDynamicSharedMemorySize, GRU_SMEM);

    const int n4 = E * (D / 4);
    copy_kernel<<<(n4 + 255) / 256, 256>>>((float4*)link, (const float4*)link0, n4);
    prep_tf32<<<(256 * 256 + 255) / 256, 256>>>(mW1, w1c, 256 * 256);
    prep_tf32<<<(256 * 128 + 255) / 256, 256>>>(mW2, w2c, 256 * 128);
    prep_wg  <<<(256 * 384 + 255) / 256, 256>>>(gk, gr, wgc);

    const int mblocks = (M + 127) / 128;
    const int gblocks = (E + 63) / 64;
    for (int t = 0; t < TT; t++) {
        zero_kernel<<<(n4 + 255) / 256, 256>>>((float4*)edges, n4);
        msg_mma_kernel<<<mblocks, 512, MSG_SMEM>>>(link, sf, ss, w1c, mb1, w2c, mb2, edges, M);
        gru_mma_kernel<<<gblocks, 256, GRU_SMEM>>>(edges, link, wgc, gb, E);
    }

    const int gs4 = GG * D / 4;
    zero_kernel<<<(gs4 + 255) / 256, 256>>>((float4*)gs, gs4);
    graph_sum_kernel<<<(E + GSROWS - 1) / GSROWS, 128>>>(link, gid, gs, E);
    readout_kernel<<<GG, 256>>>(gs, rW1, rb1, rW2, rb2, rW3, rb3, out);
}

// round 5
// speedup vs baseline: 2.3546x; 1.0121x over previous
#include <cuda_runtime.h>
#include <math.h>
#include <stdint.h>

#define D    128
#define HH   256
#define TT   3
#define GG   64
#define EMAX 100000

#define XP   260   // smem stride (floats) for X / XH tiles
#define WP1  260   // smem stride for 256-wide W chunks
#define WP2  132   // smem stride for 128-wide W chunks

// ---------------- device scratch (no allocations allowed) ----------------
__device__ float g_link [EMAX * D];
__device__ float g_edges[EMAX * D];
__device__ float g_gs   [GG * D];
__device__ float g_w1c  [256 * 256];   // mW1 tf32-rounded
__device__ float g_w2c  [256 * 128];   // mW2 tf32-rounded
__device__ float g_wgc  [256 * 384];   // [gru_kernel ; gru_recurrent] tf32-rounded

// ---------------- PTX helpers (baseline, sm_80+/sm_90+ portable) ----------------
__device__ __forceinline__ uint32_t smem_u32(const void* p) {
    uint32_t a;
    asm("{ .reg .u64 t; cvta.to.shared.u64 t, %1; cvt.u32.u64 %0, t; }" : "=r"(a) : "l"(p));
    return a;
}
__device__ __forceinline__ uint32_t tf32r(float f) {
    uint32_t u; asm("cvt.rna.tf32.f32 %0, %1;" : "=r"(u) : "f"(f)); return u;
}
#define CP16(dst, src) \
    asm volatile("cp.async.ca.shared.global [%0], [%1], 16;" :: "r"(dst), "l"(src) : "memory")
#define CP_COMMIT() asm volatile("cp.async.commit_group;" ::: "memory")
#define CP_WAIT0()  asm volatile("cp.async.wait_group 0;" ::: "memory")

#define REDV2(addr, a, b) \
    asm volatile("red.global.add.v2.f32 [%0], {%1, %2};" :: "l"(addr), "f"(a), "f"(b) : "memory")

__device__ __forceinline__ void mma_tf32(float d[4],
                                         uint32_t a0, uint32_t a1, uint32_t a2, uint32_t a3,
                                         uint32_t b0, uint32_t b1) {
    asm volatile(
        "mma.sync.aligned.m16n8k8.row.col.f32.tf32.tf32.f32 "
        "{%0,%1,%2,%3}, {%4,%5,%6,%7}, {%8,%9}, {%0,%1,%2,%3};\n"
        : "+f"(d[0]), "+f"(d[1]), "+f"(d[2]), "+f"(d[3])
        : "r"(a0), "r"(a1), "r"(a2), "r"(a3), "r"(b0), "r"(b1));
}

// ---------------- utility kernels ----------------
__global__ void zero_kernel(float4* p, int n4) {
    int i = blockIdx.x * blockDim.x + threadIdx.x;
    if (i < n4) p[i] = make_float4(0.f, 0.f, 0.f, 0.f);
}
__global__ void copy_kernel(float4* dst, const float4* __restrict__ src, int n4) {
    int i = blockIdx.x * blockDim.x + threadIdx.x;
    if (i < n4) dst[i] = src[i];
}
__global__ void prep_tf32(const float* __restrict__ in, float* __restrict__ out, int n) {
    int i = blockIdx.x * blockDim.x + threadIdx.x;
    if (i < n) out[i] = __uint_as_float(tf32r(in[i]));
}
__global__ void prep_wg(const float* __restrict__ gk, const float* __restrict__ gr,
                        float* __restrict__ wgc) {
    int i = blockIdx.x * blockDim.x + threadIdx.x;
    if (i >= 256 * 384) return;
    int k = i / 384, n = i % 384;
    float v = (k < 128) ? gk[k * 384 + n] : gr[(k - 128) * 384 + n];
    wgc[i] = __uint_as_float(tf32r(v));
}

// =====================================================================
// message MLP: gather -> GEMM1(relu) -> GEMM2(relu) -> vector-red scatter
// 512 threads, block tile = 128 messages
// =====================================================================
#define MSG_SMEM (2560 + 128 * XP * 4 + 2 * 32 * WP1 * 4)
__global__ __launch_bounds__(512, 1) void msg_mma_kernel(
    const float* __restrict__ link,
    const int*   __restrict__ sf,
    const int*   __restrict__ ss,
    const float* __restrict__ w1c, const float* __restrict__ b1,
    const float* __restrict__ w2c, const float* __restrict__ b2,
    float*       __restrict__ edges, int M)
{
    extern __shared__ __align__(16) char smem[];
    int*      s_sf = (int*)smem;
    int*      s_ss = (int*)(smem + 512);
    float*    s_b1 = (float*)(smem + 1024);
    float*    s_b2 = (float*)(smem + 2048);
    uint32_t* Xs   = (uint32_t*)(smem + 2560);                 // [128][XP]
    uint32_t* Wk   = (uint32_t*)(smem + 2560 + 128 * XP * 4);  // 2 buffers
    const uint32_t u_W = smem_u32(smem) + 2560 + 128 * XP * 4;

    const int tid  = threadIdx.x;
    const int lane = tid & 31;
    const int gid  = lane >> 2, tin = lane & 3;
    const int wid  = tid >> 5;
    const int wm   = wid & 1;       // M half (rows wm*64)
    const int wn   = wid >> 1;      // 0..7
    const int m0   = blockIdx.x * 128;

    if (tid < 128) {
        int mg = m0 + tid;
        s_sf[tid] = (mg < M) ? sf[mg] : -1;
        s_ss[tid] = (mg < M) ? ss[mg] : -1;
    }
    if (tid < 256) s_b1[tid] = b1[tid];
    if (tid < 128) s_b2[tid] = b2[tid];
    __syncthreads();

    // ---- gather X[128][256] (tf32, rna-rounded) ----
    const float4* link4 = (const float4*)link;
    #pragma unroll
    for (int it = 0; it < 16; it++) {
        int idx = it * 512 + tid;           // 8192 = 128 rows x 64 f4
        int m = idx >> 6, q = idx & 63;
        int e = (q < 32) ? s_sf[m] : s_ss[m];
        float4 v = make_float4(0.f, 0.f, 0.f, 0.f);
        if (e >= 0) v = link4[e * 32 + (q & 31)];
        uint4 t;
        t.x = tf32r(v.x); t.y = tf32r(v.y); t.z = tf32r(v.z); t.w = tf32r(v.w);
        *(uint4*)&Xs[m * XP + q * 4] = t;
    }

    auto ldW1 = [&](int c, int buf) {
        const float4* src = (const float4*)w1c + c * 2048;
        #pragma unroll
        for (int i = 0; i < 4; i++) {
            int idx = i * 512 + tid;        // 2048 f4
            uint32_t dst = u_W + (uint32_t)buf * (32 * WP1 * 4)
                         + (uint32_t)(((idx >> 6) * WP1 + (idx & 63) * 4) * 4);
            CP16(dst, src + idx);
        }
    };
    auto ldW2 = [&](int c, int buf) {
        const float4* src = (const float4*)w2c + c * 1024;
        #pragma unroll
        for (int i = 0; i < 2; i++) {
            int idx = i * 512 + tid;        // 1024 f4
            uint32_t dst = u_W + (uint32_t)buf * (32 * WP1 * 4)
                         + (uint32_t)(((idx >> 5) * WP2 + (idx & 31) * 4) * 4);
            CP16(dst, src + idx);
        }
    };

    // ================= GEMM1: H1[128,256] = X @ W1 =================
    float acc[4][4][4];
    #pragma unroll
    for (int a = 0; a < 4; a++)
        #pragma unroll
        for (int b = 0; b < 4; b++)
            #pragma unroll
            for (int i = 0; i < 4; i++) acc[a][b][i] = 0.f;

    ldW1(0, 0); CP_COMMIT();
    for (int c = 0; c < 8; c++) {
        CP_WAIT0(); __syncthreads();
        if (c < 7) { ldW1(c + 1, (c + 1) & 1); CP_COMMIT(); }
        const uint32_t* Ws = Wk + (c & 1) * (32 * WP1);
        #pragma unroll
        for (int ks = 0; ks < 4; ks++) {
            const int kk = c * 32 + ks * 8;      // global k into X
            const int kl = ks * 8;               // chunk-local k into W
            uint32_t afr[4][4];
            #pragma unroll
            for (int mt = 0; mt < 4; mt++) {
                int r = wm * 64 + mt * 16 + gid;
                afr[mt][0] = Xs[r * XP + kk + tin];
                afr[mt][1] = Xs[(r + 8) * XP + kk + tin];
                afr[mt][2] = Xs[r * XP + kk + tin + 4];
                afr[mt][3] = Xs[(r + 8) * XP + kk + tin + 4];
            }
            #pragma unroll
            for (int nt = 0; nt < 4; nt++) {
                int n = wn * 32 + nt * 8 + gid;
                uint32_t b0 = Ws[(kl + tin) * WP1 + n];
                uint32_t b1f = Ws[(kl + tin + 4) * WP1 + n];
                #pragma unroll
                for (int mt = 0; mt < 4; mt++)
                    mma_tf32(acc[mt][nt], afr[mt][0], afr[mt][1], afr[mt][2], afr[mt][3], b0, b1f);
            }
        }
    }
    __syncthreads();

    // ---- epilogue1: H1 = tf32(relu(acc + b1)) back into Xs ----
    #pragma unroll
    for (int mt = 0; mt < 4; mt++)
        #pragma unroll
        for (int nt = 0; nt < 4; nt++) {
            int r = wm * 64 + mt * 16 + gid;
            int cb = wn * 32 + nt * 8 + tin * 2;
            Xs[r * XP + cb]           = tf32r(fmaxf(acc[mt][nt][0] + s_b1[cb], 0.f));
            Xs[r * XP + cb + 1]       = tf32r(fmaxf(acc[mt][nt][1] + s_b1[cb + 1], 0.f));
            Xs[(r + 8) * XP + cb]     = tf32r(fmaxf(acc[mt][nt][2] + s_b1[cb], 0.f));
            Xs[(r + 8) * XP + cb + 1] = tf32r(fmaxf(acc[mt][nt][3] + s_b1[cb + 1], 0.f));
        }
    __syncthreads();

    // ================= GEMM2: OUT[128,128] = H1 @ W2 =================
    float ac2[4][2][4];
    #pragma unroll
    for (int a = 0; a < 4; a++)
        #pragma unroll
        for (int b = 0; b < 2; b++)
            #pragma unroll
            for (int i = 0; i < 4; i++) ac2[a][b][i] = 0.f;

    ldW2(0, 0); CP_COMMIT();
    for (int c = 0; c < 8; c++) {
        CP_WAIT0(); __syncthreads();
        if (c < 7) { ldW2(c + 1, (c + 1) & 1); CP_COMMIT(); }
        const uint32_t* Ws = Wk + (c & 1) * (32 * WP1);
        #pragma unroll
        for (int ks = 0; ks < 4; ks++) {
            const int kk = c * 32 + ks * 8;
            const int kl = ks * 8;
            uint32_t afr[4][4];
            #pragma unroll
            for (int mt = 0; mt < 4; mt++) {
                int r = wm * 64 + mt * 16 + gid;
                afr[mt][0] = Xs[r * XP + kk + tin];
                afr[mt][1] = Xs[(r + 8) * XP + kk + tin];
                afr[mt][2] = Xs[r * XP + kk + tin + 4];
                afr[mt][3] = Xs[(r + 8) * XP + kk + tin + 4];
            }
            #pragma unroll
            for (int nt = 0; nt < 2; nt++) {
                int n = wn * 16 + nt * 8 + gid;
                uint32_t b0 = Ws[(kl + tin) * WP2 + n];
                uint32_t b1f = Ws[(kl + tin + 4) * WP2 + n];
                #pragma unroll
                for (int mt = 0; mt < 4; mt++)
                    mma_tf32(ac2[mt][nt], afr[mt][0], afr[mt][1], afr[mt][2], afr[mt][3], b0, b1f);
            }
        }
    }

    // ---- epilogue2: relu + bias + vector red scatter ----
    #pragma unroll
    for (int mt = 0; mt < 4; mt++)
        #pragma unroll
        for (int nt = 0; nt < 2; nt++) {
            int r  = wm * 64 + mt * 16 + gid;
            int cb = wn * 16 + nt * 8 + tin * 2;
            int e0 = s_ss[r], e1 = s_ss[r + 8];
            if (e0 >= 0) {
                float v0 = fmaxf(ac2[mt][nt][0] + s_b2[cb], 0.f);
                float v1 = fmaxf(ac2[mt][nt][1] + s_b2[cb + 1], 0.f);
                REDV2(&edges[e0 * D + cb], v0, v1);
            }
            if (e1 >= 0) {
                float v0 = fmaxf(ac2[mt][nt][2] + s_b2[cb], 0.f);
                float v1 = fmaxf(ac2[mt][nt][3] + s_b2[cb + 1], 0.f);
                REDV2(&edges[e1 * D + cb], v0, v1);
            }
        }
}

// =====================================================================
// GRU: 256 threads, 64-row tile, TWO fused passes:
//   pass1: (z | r) = [x|h] @ [Kz Kr ; Rz Rr]   (K=256, N=256)
//   pass2: ah = x@Kh (chunks 0-1), bh = h@Rh (chunks 2-3)  (N=128)
// Column layout arranged so each thread's z/r cols == its h cols.
// =====================================================================
#define GRU_SMEM (2048 + 64 * XP * 4 + 2 * 64 * WP1 * 4)
__global__ __launch_bounds__(256, 1) void gru_mma_kernel(
    const float* __restrict__ x,            // edges_inputs [E][D]
    float*       __restrict__ h,            // link_state   [E][D]
    const float* __restrict__ wgc,          // [256][384] tf32
    const float* __restrict__ gbias,        // [2][384]
    int E)
{
    extern __shared__ __align__(16) char smem[];
    float*    s_bz  = (float*)smem;                    // [128]
    float*    s_br  = (float*)(smem + 512);
    float*    s_bah = (float*)(smem + 1024);
    float*    s_bbh = (float*)(smem + 1536);
    uint32_t* XH    = (uint32_t*)(smem + 2048);        // [64][XP]
    uint32_t* Wk    = (uint32_t*)(smem + 2048 + 64 * XP * 4);
    const uint32_t u_W = smem_u32(smem) + 2048 + 64 * XP * 4;

    const int tid  = threadIdx.x;
    const int lane = tid & 31;
    const int gid  = lane >> 2, tin = lane & 3;
    const int wid  = tid >> 5;
    const int wm   = wid & 1;       // rows wm*32
    const int wn   = wid >> 1;      // 0..3, 32-col group
    const int e0   = blockIdx.x * 64;

    if (tid < 128) {
        s_bz[tid]  = gbias[tid]       + gbias[384 + tid];
        s_br[tid]  = gbias[128 + tid] + gbias[512 + tid];
        s_bah[tid] = gbias[256 + tid];
        s_bbh[tid] = gbias[640 + tid];
    }

    // ---- load XH (x cols 0-127, h cols 128-255), tf32 rna ----
    const float4* xe4 = (const float4*)x;
    const float4* ln4 = (const float4*)h;
    #pragma unroll
    for (int it = 0; it < 16; it++) {
        int idx = it * 256 + tid;          // 4096 = 64 rows x 64 f4
        int m = idx >> 6, q = idx & 63;
        int e = e0 + m;
        float4 v = make_float4(0.f, 0.f, 0.f, 0.f);
        if (e < E) v = (q < 32) ? xe4[e * 32 + q] : ln4[e * 32 + (q - 32)];
        uint4 t;
        t.x = tf32r(v.x); t.y = tf32r(v.y); t.z = tf32r(v.z); t.w = tf32r(v.w);
        *(uint4*)&XH[m * XP + q * 4] = t;
    }

    // chunk loaders: 64 k-rows per chunk
    auto ldW1g = [&](int c, int buf) {      // cols 0..255 (z|r)
        const float4* src = (const float4*)wgc;
        #pragma unroll
        for (int i = 0; i < 16; i++) {
            int idx = i * 256 + tid;        // 4096 f4 = 64 x 64
            int kr = idx >> 6, q = idx & 63;
            uint32_t dst = u_W + (uint32_t)buf * (64 * WP1 * 4)
                         + (uint32_t)((kr * WP1 + q * 4) * 4);
            CP16(dst, src + (c * 64 + kr) * 96 + q);
        }
    };
    auto ldW2g = [&](int c, int buf) {      // cols 256..383 (h)
        const float4* src = (const float4*)wgc;
        #pragma unroll
        for (int i = 0; i < 8; i++) {
            int idx = i * 256 + tid;        // 2048 f4 = 64 x 32
            int kr = idx >> 5, q = idx & 31;
            uint32_t dst = u_W + (uint32_t)buf * (64 * WP1 * 4)
                         + (uint32_t)((kr * WP2 + q * 4) * 4);
            CP16(dst, src + (c * 64 + kr) * 96 + 64 + q);
        }
    };

    // ---- pass1: z|r, acc1[mt][j]: j<4 -> z col wn*32+j*8, j>=4 -> r col 128+wn*32+(j-4)*8
    float acc1[2][8][4];
    #pragma unroll
    for (int a = 0; a < 2; a++)
        #pragma unroll
        for (int b = 0; b < 8; b++)
            #pragma unroll
            for (int i = 0; i < 4; i++) acc1[a][b][i] = 0.f;

    ldW1g(0, 0); CP_COMMIT();
    for (int c = 0; c < 4; c++) {
        CP_WAIT0(); __syncthreads();
        if (c < 3) { ldW1g(c + 1, (c + 1) & 1); CP_COMMIT(); }
        else       { ldW2g(0, 0); CP_COMMIT(); }
        const uint32_t* Ws = Wk + (c & 1) * (64 * WP1);
        #pragma unroll
        for (int ks = 0; ks < 8; ks++) {
            const int kk = c * 64 + ks * 8;
            const int kl = ks * 8;
            uint32_t afr[2][4];
            #pragma unroll
            for (int mt = 0; mt < 2; mt++) {
                int r = wm * 32 + mt * 16 + gid;
                afr[mt][0] = XH[r * XP + kk + tin];
                afr[mt][1] = XH[(r + 8) * XP + kk + tin];
                afr[mt][2] = XH[r * XP + kk + tin + 4];
                afr[mt][3] = XH[(r + 8) * XP + kk + tin + 4];
            }
            #pragma unroll
            for (int j = 0; j < 8; j++) {
                int n = (j < 4) ? (wn * 32 + j * 8 + gid)
                                : (128 + wn * 32 + (j - 4) * 8 + gid);
                uint32_t b0 = Ws[(kl + tin) * WP1 + n];
                uint32_t b1f = Ws[(kl + tin + 4) * WP1 + n];
                #pragma unroll
                for (int mt = 0; mt < 2; mt++)
                    mma_tf32(acc1[mt][j], afr[mt][0], afr[mt][1], afr[mt][2], afr[mt][3], b0, b1f);
            }
        }
    }

    // ---- pass2: ah (chunks 0-1, x@Kh), bh (chunks 2-3, h@Rh) ----
    float accA[2][4][4], accB[2][4][4];
    #pragma unroll
    for (int a = 0; a < 2; a++)
        #pragma unroll
        for (int b = 0; b < 4; b++)
            #pragma unroll
            for (int i = 0; i < 4; i++) { accA[a][b][i] = 0.f; accB[a][b][i] = 0.f; }

    for (int c = 0; c < 4; c++) {
        CP_WAIT0(); __syncthreads();
        if (c < 3) { ldW2g(c + 1, (c + 1) & 1); CP_COMMIT(); }
        const uint32_t* Ws = Wk + (c & 1) * (64 * WP1);
        #pragma unroll
        for (int ks = 0; ks < 8; ks++) {
            const int kk = c * 64 + ks * 8;
            const int kl = ks * 8;
            uint32_t afr[2][4];
            #pragma unroll
            for (int mt = 0; mt < 2; mt++) {
                int r = wm * 32 + mt * 16 + gid;
                afr[mt][0] = XH[r * XP + kk + tin];
                afr[mt][1] = XH[(r + 8) * XP + kk + tin];
                afr[mt][2] = XH[r * XP + kk + tin + 4];
                afr[mt][3] = XH[(r + 8) * XP + kk + tin + 4];
            }
            #pragma unroll
            for (int nt = 0; nt < 4; nt++) {
                int n = wn * 32 + nt * 8 + gid;
                uint32_t b0 = Ws[(kl + tin) * WP2 + n];
                uint32_t b1f = Ws[(kl + tin + 4) * WP2 + n];
                if (c < 2) {
                    #pragma unroll
                    for (int mt = 0; mt < 2; mt++)
                        mma_tf32(accA[mt][nt], afr[mt][0], afr[mt][1], afr[mt][2], afr[mt][3], b0, b1f);
                } else {
                    #pragma unroll
                    for (int mt = 0; mt < 2; mt++)
                        mma_tf32(accB[mt][nt], afr[mt][0], afr[mt][1], afr[mt][2], afr[mt][3], b0, b1f);
                }
            }
        }
    }

    // ---- gate math + in-place update (z/r/ah/bh all at same (row,col) per thread) ----
    #pragma unroll
    for (int mt = 0; mt < 2; mt++)
        #pragma unroll
        for (int nt = 0; nt < 4; nt++) {
            int cb = wn * 32 + nt * 8 + tin * 2;
            #pragma unroll
            for (int half = 0; half < 2; half++) {
                int r = wm * 32 + mt * 16 + gid + half * 8;
                int e = e0 + r;
                if (e < E) {
                    int i0 = half * 2;
                    float2 ho = *(const float2*)&h[e * D + cb];
                    float z0 = 1.f / (1.f + expf(-(acc1[mt][nt][i0]         + s_bz[cb])));
                    float z1 = 1.f / (1.f + expf(-(acc1[mt][nt][i0 + 1]     + s_bz[cb + 1])));
                    float r0 = 1.f / (1.f + expf(-(acc1[mt][nt + 4][i0]     + s_br[cb])));
                    float r1 = 1.f / (1.f + expf(-(acc1[mt][nt + 4][i0 + 1] + s_br[cb + 1])));
                    float h0 = tanhf(accA[mt][nt][i0]     + s_bah[cb]     + r0 * (accB[mt][nt][i0]     + s_bbh[cb]));
                    float h1 = tanhf(accA[mt][nt][i0 + 1] + s_bah[cb + 1] + r1 * (accB[mt][nt][i0 + 1] + s_bbh[cb + 1]));
                    float2 o;
                    o.x = z0 * ho.x + (1.f - z0) * h0;
                    o.y = z1 * ho.y + (1.f - z1) * h1;
                    *(float2*)&h[e * D + cb] = o;
                }
            }
        }
}

// ---------------- graph segment-sum (sorted graph ids) ----------------
#define GSROWS 512
__global__ __launch_bounds__(128) void graph_sum_kernel(
    const float* __restrict__ link, const int* __restrict__ gid,
    float* __restrict__ gs, int E)
{
    int tid = threadIdx.x;
    int r0 = blockIdx.x * GSROWS;
    if (r0 >= E) return;
    int r1 = min(r0 + GSROWS, E);
    float acc = 0.f;
    int cur = gid[r0];
    for (int r = r0; r < r1; r++) {
        int g = gid[r];
        if (g != cur) {
            atomicAdd(&gs[cur * D + tid], acc);
            acc = 0.f;
            cur = g;
        }
        acc += link[r * D + tid];
    }
    atomicAdd(&gs[cur * D + tid], acc);
}

// ---------------- readout MLP ----------------
__global__ __launch_bounds__(256) void readout_kernel(
    const float* __restrict__ gs,
    const float* __restrict__ rW1, const float* __restrict__ rb1,
    const float* __restrict__ rW2, const float* __restrict__ rb2,
    const float* __restrict__ rW3, const float* __restrict__ rb3,
    float* __restrict__ out)
{
    __shared__ float s_in[D];
    __shared__ float s_r1[HH];
    __shared__ float s_r2[HH];
    const int g = blockIdx.x;
    const int t = threadIdx.x;

    if (t < D) s_in[t] = gs[g * D + t];
    __syncthreads();

    float a = rb1[t];
    #pragma unroll 4
    for (int k = 0; k < D; k++) a = fmaf(s_in[k], rW1[k * HH + t], a);
    s_r1[t] = fmaxf(a, 0.f);
    __syncthreads();

    float b = rb2[t];
    #pragma unroll 4
    for (int k = 0; k < HH; k++) b = fmaf(s_r1[k], rW2[k * HH + t], b);
    s_r2[t] = fmaxf(b, 0.f) * rW3[t];
    __syncthreads();

    for (int s = 128; s > 0; s >>= 1) {
        if (t < s) s_r2[t] += s_r2[t + s];
        __syncthreads();
    }
    if (t == 0) out[g] = s_r2[0] + rb3[0];
}

// ---------------- launch ----------------
extern "C" void kernel_launch(void* const* d_in, const int* in_sizes, int n_in,
                              void* d_out, int out_size)
{
    const float* link0 = (const float*)d_in[0];
    const int*   sf    = (const int*)  d_in[1];
    const int*   ss    = (const int*)  d_in[2];
    const int*   gid   = (const int*)  d_in[3];
    const float* mW1 = (const float*)d_in[5];
    const float* mb1 = (const float*)d_in[6];
    const float* mW2 = (const float*)d_in[7];
    const float* mb2 = (const float*)d_in[8];
    const float* gk  = (const float*)d_in[9];
    const float* gr  = (const float*)d_in[10];
    const float* gb  = (const float*)d_in[11];
    const float* rW1 = (const float*)d_in[12];
    const float* rb1 = (const float*)d_in[13];
    const float* rW2 = (const float*)d_in[14];
    const float* rb2 = (const float*)d_in[15];
    const float* rW3 = (const float*)d_in[16];
    const float* rb3 = (const float*)d_in[17];
    float* out = (float*)d_out;

    const int M = in_sizes[1];
    const int E = in_sizes[3] <= EMAX ? in_sizes[3] : EMAX;

    float *link, *edges, *gs, *w1c, *w2c, *wgc;
    cudaGetSymbolAddress((void**)&link,  g_link);
    cudaGetSymbolAddress((void**)&edges, g_edges);
    cudaGetSymbolAddress((void**)&gs,    g_gs);
    cudaGetSymbolAddress((void**)&w1c,   g_w1c);
    cudaGetSymbolAddress((void**)&w2c,   g_w2c);
    cudaGetSymbolAddress((void**)&wgc,   g_wgc);

    cudaFuncSetAttribute(msg_mma_kernel, cudaFuncAttributeMaxDynamicSharedMemorySize, MSG_SMEM);
    cudaFuncSetAttribute(gru_mma_kernel, cudaFuncAttributeMaxDynamicSharedMemorySize, GRU_SMEM);

    const int n4 = E * (D / 4);
    copy_kernel<<<(n4 + 255) / 256, 256>>>((float4*)link, (const float4*)link0, n4);
    prep_tf32<<<(256 * 256 + 255) / 256, 256>>>(mW1, w1c, 256 * 256);
    prep_tf32<<<(256 * 128 + 255) / 256, 256>>>(mW2, w2c, 256 * 128);
    prep_wg  <<<(256 * 384 + 255) / 256, 256>>>(gk, gr, wgc);

    const int mblocks = (M + 127) / 128;
    const int gblocks = (E + 63) / 64;
    for (int t = 0; t < TT; t++) {
        zero_kernel<<<(n4 + 255) / 256, 256>>>((float4*)edges, n4);
        msg_mma_kernel<<<mblocks, 512, MSG_SMEM>>>(link, sf, ss, w1c, mb1, w2c, mb2, edges, M);
        gru_mma_kernel<<<gblocks, 256, GRU_SMEM>>>(edges, link, wgc, gb, E);
    }

    const int gs4 = GG * D / 4;
    zero_kernel<<<(gs4 + 255) / 256, 256>>>((float4*)gs, gs4);
    graph_sum_kernel<<<(E + GSROWS - 1) / GSROWS, 128>>>(link, gid, gs, E);
    readout_kernel<<<GG, 256>>>(gs, rW1, rb1, rW2, rb2, rW3, rb3, out);
}

// round 6
// speedup vs baseline: 3.2456x; 1.3784x over previous
#include <cuda_runtime.h>
#include <cuda_fp16.h>
#include <math.h>
#include <stdint.h>

#define D    128
#define HH   256
#define TT   3
#define GG   64
#define EMAX 100000

#define XSU  132   // u32 stride of X/XH rows (264 halves) -> banks 4*gid+tin, conflict-free
#define WRU  20    // u32 stride of W chunk rows (32 halves + pad)

// ---------------- device scratch (no allocations allowed) ----------------
__device__ float  g_link [EMAX * D];
__device__ float  g_edges[EMAX * D];
__device__ float  g_gs   [GG * D];
__device__ __half g_w1h  [256 * 256];   // mW1^T  [n][k] half
__device__ __half g_w2h  [128 * 256];   // mW2^T  [n][k] half
__device__ __half g_wgh  [384 * 256];   // [Kz|Kr|Kh ; Rz|Rr|Rh]^T [n=384][k=256] half

// ---------------- PTX helpers (baseline sm_80+/sm_90+) ----------------
__device__ __forceinline__ uint32_t smem_u32(const void* p) {
    uint32_t a;
    asm("{ .reg .u64 t; cvta.to.shared.u64 t, %1; cvt.u32.u64 %0, t; }" : "=r"(a) : "l"(p));
    return a;
}
__device__ __forceinline__ uint32_t packh2(float a, float b) {
    __half2 h = __floats2half2_rn(a, b);
    return *(uint32_t*)&h;
}
#define CP16(dst, src) \
    asm volatile("cp.async.ca.shared.global [%0], [%1], 16;" :: "r"(dst), "l"(src) : "memory")
#define CP_COMMIT() asm volatile("cp.async.commit_group;" ::: "memory")
#define CP_WAIT0()  asm volatile("cp.async.wait_group 0;" ::: "memory")
#define REDV2(addr, a, b) \
    asm volatile("red.global.add.v2.f32 [%0], {%1, %2};" :: "l"(addr), "f"(a), "f"(b) : "memory")

__device__ __forceinline__ void mma_f16(float d[4],
                                        uint32_t a0, uint32_t a1, uint32_t a2, uint32_t a3,
                                        uint32_t b0, uint32_t b1) {
    asm volatile(
        "mma.sync.aligned.m16n8k16.row.col.f32.f16.f16.f32 "
        "{%0,%1,%2,%3}, {%4,%5,%6,%7}, {%8,%9}, {%0,%1,%2,%3};\n"
        : "+f"(d[0]), "+f"(d[1]), "+f"(d[2]), "+f"(d[3])
        : "r"(a0), "r"(a1), "r"(a2), "r"(a3), "r"(b0), "r"(b1));
}

// ---------------- utility kernels ----------------
__global__ void zero_kernel(float4* p, int n4) {
    int i = blockIdx.x * blockDim.x + threadIdx.x;
    if (i < n4) p[i] = make_float4(0.f, 0.f, 0.f, 0.f);
}
__global__ void copy_kernel(float4* dst, const float4* __restrict__ src, int n4) {
    int i = blockIdx.x * blockDim.x + threadIdx.x;
    if (i < n4) dst[i] = src[i];
}
// single prep kernel: transpose + fp16-round all weight matrices
__global__ void prep_all(const float* __restrict__ mW1, const float* __restrict__ mW2,
                         const float* __restrict__ gk,  const float* __restrict__ gr,
                         __half* __restrict__ w1h, __half* __restrict__ w2h,
                         __half* __restrict__ wgh) {
    int i = blockIdx.x * blockDim.x + threadIdx.x;
    if (i < 65536) {                       // W1: [k=256][n=256] -> [n][k]
        int k = i >> 8, n = i & 255;
        w1h[n * 256 + k] = __float2half_rn(mW1[k * 256 + n]);
    } else if (i < 98304) {                // W2: [k=256][n=128] -> [n][k]
        int j = i - 65536;
        int k = j >> 7, n = j & 127;
        w2h[n * 256 + k] = __float2half_rn(mW2[k * 128 + n]);
    } else if (i < 196608) {               // GRU: [n=384][k=256]
        int j = i - 98304;
        int n = j >> 8, k = j & 255;
        float v = (k < 128) ? gk[k * 384 + n] : gr[(k - 128) * 384 + n];
        wgh[n * 256 + k] = __float2half_rn(v);
    }
}

// =====================================================================
// message MLP (fp16 MMA): gather -> GEMM1(relu) -> GEMM2(relu) -> red.v2
// 512 threads, block tile = 128 messages
// smem: ids/biases 2560 | X half [128][264] 67584 | W 2x[256][20u32] 40960
// =====================================================================
#define MSG_SMEM (2560 + 128 * XSU * 4 + 2 * 256 * WRU * 4)
__global__ __launch_bounds__(512, 1) void msg_mma_kernel(
    const float*  __restrict__ link,
    const int*    __restrict__ sf,
    const int*    __restrict__ ss,
    const __half* __restrict__ w1h, const float* __restrict__ b1,
    const __half* __restrict__ w2h, const float* __restrict__ b2,
    float*        __restrict__ edges, int M)
{
    extern __shared__ __align__(16) char smem[];
    int*      s_sf = (int*)smem;
    int*      s_ss = (int*)(smem + 512);
    float*    s_b1 = (float*)(smem + 1024);
    float*    s_b2 = (float*)(smem + 2048);
    uint32_t* Xs   = (uint32_t*)(smem + 2560);                  // [128][XSU]
    uint32_t* Wk   = (uint32_t*)(smem + 2560 + 128 * XSU * 4);
    const uint32_t u_W = smem_u32(smem) + 2560 + 128 * XSU * 4;

    const int tid  = threadIdx.x;
    const int lane = tid & 31;
    const int gid  = lane >> 2, tin = lane & 3;
    const int wid  = tid >> 5;
    const int wm   = wid & 1;       // rows wm*64
    const int wn   = wid >> 1;      // 0..7
    const int m0   = blockIdx.x * 128;

    if (tid < 128) {
        int mg = m0 + tid;
        s_sf[tid] = (mg < M) ? sf[mg] : -1;
        s_ss[tid] = (mg < M) ? ss[mg] : -1;
    }
    if (tid < 256) s_b1[tid] = b1[tid];
    if (tid < 128) s_b2[tid] = b2[tid];
    __syncthreads();

    // ---- gather X[128][256] -> half ----
    const float4* link4 = (const float4*)link;
    #pragma unroll
    for (int it = 0; it < 16; it++) {
        int idx = it * 512 + tid;           // 8192 = 128 rows x 64 f4
        int m = idx >> 6, q = idx & 63;
        int e = (q < 32) ? s_sf[m] : s_ss[m];
        float4 v = make_float4(0.f, 0.f, 0.f, 0.f);
        if (e >= 0) v = link4[e * 32 + (q & 31)];
        uint2 t;
        t.x = packh2(v.x, v.y);
        t.y = packh2(v.z, v.w);
        *(uint2*)&Xs[m * XSU + q * 2] = t;
    }

    // W chunk loaders: 32-k slice, rows [n][32 halves] at 80B stride
    auto ldW1 = [&](int c, int buf) {       // 256 rows, 2 CP16/thread
        #pragma unroll
        for (int i = 0; i < 2; i++) {
            int idx = i * 512 + tid;        // 1024 = 256 rows x 4 segs
            int row = idx >> 2, seg = idx & 3;
            uint32_t dst = u_W + (uint32_t)buf * (256 * WRU * 4)
                         + (uint32_t)(row * WRU * 4 + seg * 16);
            CP16(dst, (const char*)w1h + (row * 256 + c * 32 + seg * 8) * 2);
        }
    };
    auto ldW2 = [&](int c, int buf) {       // 128 rows, 1 CP16/thread
        int row = tid >> 2, seg = tid & 3;
        uint32_t dst = u_W + (uint32_t)buf * (256 * WRU * 4)
                     + (uint32_t)(row * WRU * 4 + seg * 16);
        CP16(dst, (const char*)w2h + (row * 256 + c * 32 + seg * 8) * 2);
    };

    // ================= GEMM1: H1[128,256] = X @ W1 =================
    float acc[4][4][4];
    #pragma unroll
    for (int a = 0; a < 4; a++)
        #pragma unroll
        for (int b = 0; b < 4; b++)
            #pragma unroll
            for (int i = 0; i < 4; i++) acc[a][b][i] = 0.f;

    ldW1(0, 0); CP_COMMIT();
    for (int c = 0; c < 8; c++) {
        CP_WAIT0(); __syncthreads();
        if (c < 7) { ldW1(c + 1, (c + 1) & 1); CP_COMMIT(); }
        else       { ldW2(0, 0); CP_COMMIT(); }
        const uint32_t* Ws = Wk + (c & 1) * (256 * WRU);
        #pragma unroll
        for (int ks = 0; ks < 2; ks++) {
            const int ku = c * 16 + ks * 8;      // global k (u32 units)
            const int kl = ks * 8;               // chunk-local (u32)
            uint32_t afr[4][4];
            #pragma unroll
            for (int mt = 0; mt < 4; mt++) {
                int r = wm * 64 + mt * 16 + gid;
                afr[mt][0] = Xs[r * XSU + ku + tin];
                afr[mt][1] = Xs[(r + 8) * XSU + ku + tin];
                afr[mt][2] = Xs[r * XSU + ku + tin + 4];
                afr[mt][3] = Xs[(r + 8) * XSU + ku + tin + 4];
            }
            #pragma unroll
            for (int nt = 0; nt < 4; nt++) {
                int n = wn * 32 + nt * 8 + gid;
                uint32_t b0 = Ws[n * WRU + kl + tin];
                uint32_t b1f = Ws[n * WRU + kl + tin + 4];
                #pragma unroll
                for (int mt = 0; mt < 4; mt++)
                    mma_f16(acc[mt][nt], afr[mt][0], afr[mt][1], afr[mt][2], afr[mt][3], b0, b1f);
            }
        }
    }
    __syncthreads();

    // ---- epilogue1: H1 = half(relu(acc + b1)) back into Xs ----
    #pragma unroll
    for (int mt = 0; mt < 4; mt++)
        #pragma unroll
        for (int nt = 0; nt < 4; nt++) {
            int r  = wm * 64 + mt * 16 + gid;
            int cb = wn * 32 + nt * 8 + tin * 2;
            int cu = cb >> 1;                       // u32 col
            Xs[r * XSU + cu]       = packh2(fmaxf(acc[mt][nt][0] + s_b1[cb], 0.f),
                                            fmaxf(acc[mt][nt][1] + s_b1[cb + 1], 0.f));
            Xs[(r + 8) * XSU + cu] = packh2(fmaxf(acc[mt][nt][2] + s_b1[cb], 0.f),
                                            fmaxf(acc[mt][nt][3] + s_b1[cb + 1], 0.f));
        }
    __syncthreads();

    // ================= GEMM2: OUT[128,128] = H1 @ W2 =================
    float ac2[4][2][4];
    #pragma unroll
    for (int a = 0; a < 4; a++)
        #pragma unroll
        for (int b = 0; b < 2; b++)
            #pragma unroll
            for (int i = 0; i < 4; i++) ac2[a][b][i] = 0.f;

    for (int c = 0; c < 8; c++) {
        CP_WAIT0(); __syncthreads();
        if (c < 7) { ldW2(c + 1, (c + 1) & 1); CP_COMMIT(); }
        const uint32_t* Ws = Wk + (c & 1) * (256 * WRU);
        #pragma unroll
        for (int ks = 0; ks < 2; ks++) {
            const int ku = c * 16 + ks * 8;
            const int kl = ks * 8;
            uint32_t afr[4][4];
            #pragma unroll
            for (int mt = 0; mt < 4; mt++) {
                int r = wm * 64 + mt * 16 + gid;
                afr[mt][0] = Xs[r * XSU + ku + tin];
                afr[mt][1] = Xs[(r + 8) * XSU + ku + tin];
                afr[mt][2] = Xs[r * XSU + ku + tin + 4];
                afr[mt][3] = Xs[(r + 8) * XSU + ku + tin + 4];
            }
            #pragma unroll
            for (int nt = 0; nt < 2; nt++) {
                int n = wn * 16 + nt * 8 + gid;
                uint32_t b0 = Ws[n * WRU + kl + tin];
                uint32_t b1f = Ws[n * WRU + kl + tin + 4];
                #pragma unroll
                for (int mt = 0; mt < 4; mt++)
                    mma_f16(ac2[mt][nt], afr[mt][0], afr[mt][1], afr[mt][2], afr[mt][3], b0, b1f);
            }
        }
    }

    // ---- epilogue2: relu + bias + vector red scatter ----
    #pragma unroll
    for (int mt = 0; mt < 4; mt++)
        #pragma unroll
        for (int nt = 0; nt < 2; nt++) {
            int r  = wm * 64 + mt * 16 + gid;
            int cb = wn * 16 + nt * 8 + tin * 2;
            int e0 = s_ss[r], e1 = s_ss[r + 8];
            if (e0 >= 0) {
                float v0 = fmaxf(ac2[mt][nt][0] + s_b2[cb], 0.f);
                float v1 = fmaxf(ac2[mt][nt][1] + s_b2[cb + 1], 0.f);
                REDV2(&edges[e0 * D + cb], v0, v1);
            }
            if (e1 >= 0) {
                float v0 = fmaxf(ac2[mt][nt][2] + s_b2[cb], 0.f);
                float v1 = fmaxf(ac2[mt][nt][3] + s_b2[cb + 1], 0.f);
                REDV2(&edges[e1 * D + cb], v0, v1);
            }
        }
}

// =====================================================================
// GRU (fp16 MMA): 256 threads, 64-row tile, two fused passes
// smem: biases 2048 | XH half [64][264] 33792 | W 2x[256][20u32] 40960
// =====================================================================
#define GRU_SMEM (2048 + 64 * XSU * 4 + 2 * 256 * WRU * 4)
__global__ __launch_bounds__(256, 1) void gru_mma_kernel(
    const float*  __restrict__ x,            // edges_inputs [E][D]
    float*        __restrict__ h,            // link_state   [E][D]
    const __half* __restrict__ wgh,          // [384][256] half
    const float*  __restrict__ gbias,        // [2][384]
    int E)
{
    extern __shared__ __align__(16) char smem[];
    float*    s_bz  = (float*)smem;
    float*    s_br  = (float*)(smem + 512);
    float*    s_bah = (float*)(smem + 1024);
    float*    s_bbh = (float*)(smem + 1536);
    uint32_t* XH    = (uint32_t*)(smem + 2048);        // [64][XSU]
    uint32_t* Wk    = (uint32_t*)(smem + 2048 + 64 * XSU * 4);
    const uint32_t u_W = smem_u32(smem) + 2048 + 64 * XSU * 4;

    const int tid  = threadIdx.x;
    const int lane = tid & 31;
    const int gid  = lane >> 2, tin = lane & 3;
    const int wid  = tid >> 5;
    const int wm   = wid & 1;       // rows wm*32
    const int wn   = wid >> 1;      // 0..3
    const int e0   = blockIdx.x * 64;

    if (tid < 128) {
        s_bz[tid]  = gbias[tid]       + gbias[384 + tid];
        s_br[tid]  = gbias[128 + tid] + gbias[512 + tid];
        s_bah[tid] = gbias[256 + tid];
        s_bbh[tid] = gbias[640 + tid];
    }

    // ---- load XH (x cols 0-127, h cols 128-255) -> half ----
    const float4* xe4 = (const float4*)x;
    const float4* ln4 = (const float4*)h;
    #pragma unroll
    for (int it = 0; it < 16; it++) {
        int idx = it * 256 + tid;          // 4096 = 64 rows x 64 f4
        int m = idx >> 6, q = idx & 63;
        int e = e0 + m;
        float4 v = make_float4(0.f, 0.f, 0.f, 0.f);
        if (e < E) v = (q < 32) ? xe4[e * 32 + q] : ln4[e * 32 + (q - 32)];
        uint2 t;
        t.x = packh2(v.x, v.y);
        t.y = packh2(v.z, v.w);
        *(uint2*)&XH[m * XSU + q * 2] = t;
    }

    auto ldP1 = [&](int c, int buf) {       // rows 0..255 (z|r), 4 CP16/thread
        #pragma unroll
        for (int i = 0; i < 4; i++) {
            int idx = i * 256 + tid;
            int row = idx >> 2, seg = idx & 3;
            uint32_t dst = u_W + (uint32_t)buf * (256 * WRU * 4)
                         + (uint32_t)(row * WRU * 4 + seg * 16);
            CP16(dst, (const char*)wgh + (row * 256 + c * 32 + seg * 8) * 2);
        }
    };
    auto ldP2 = [&](int c, int buf) {       // rows 256..383 (h), 2 CP16/thread
        #pragma unroll
        for (int i = 0; i < 2; i++) {
            int idx = i * 256 + tid;
            int row = idx >> 2, seg = idx & 3;
            uint32_t dst = u_W + (uint32_t)buf * (256 * WRU * 4)
                         + (uint32_t)(row * WRU * 4 + seg * 16);
            CP16(dst, (const char*)wgh + ((256 + row) * 256 + c * 32 + seg * 8) * 2);
        }
    };

    // ---- pass1: z|r  (N=256, K=256) ----
    float acc1[2][8][4];
    #pragma unroll
    for (int a = 0; a < 2; a++)
        #pragma unroll
        for (int b = 0; b < 8; b++)
            #pragma unroll
            for (int i = 0; i < 4; i++) acc1[a][b][i] = 0.f;

    ldP1(0, 0); CP_COMMIT();
    for (int c = 0; c < 8; c++) {
        CP_WAIT0(); __syncthreads();
        if (c < 7) { ldP1(c + 1, (c + 1) & 1); CP_COMMIT(); }
        else       { ldP2(0, 0); CP_COMMIT(); }
        const uint32_t* Ws = Wk + (c & 1) * (256 * WRU);
        #pragma unroll
        for (int ks = 0; ks < 2; ks++) {
            const int ku = c * 16 + ks * 8;
            const int kl = ks * 8;
            uint32_t afr[2][4];
            #pragma unroll
            for (int mt = 0; mt < 2; mt++) {
                int r = wm * 32 + mt * 16 + gid;
                afr[mt][0] = XH[r * XSU + ku + tin];
                afr[mt][1] = XH[(r + 8) * XSU + ku + tin];
                afr[mt][2] = XH[r * XSU + ku + tin + 4];
                afr[mt][3] = XH[(r + 8) * XSU + ku + tin + 4];
            }
            #pragma unroll
            for (int j = 0; j < 8; j++) {
                int n = (j < 4) ? (wn * 32 + j * 8 + gid)
                                : (128 + wn * 32 + (j - 4) * 8 + gid);
                uint32_t b0 = Ws[n * WRU + kl + tin];
                uint32_t b1f = Ws[n * WRU + kl + tin + 4];
                #pragma unroll
                for (int mt = 0; mt < 2; mt++)
                    mma_f16(acc1[mt][j], afr[mt][0], afr[mt][1], afr[mt][2], afr[mt][3], b0, b1f);
            }
        }
    }

    // ---- pass2: ah (chunks 0-3, x@Kh) / bh (chunks 4-7, h@Rh) ----
    float accA[2][4][4], accB[2][4][4];
    #pragma unroll
    for (int a = 0; a < 2; a++)
        #pragma unroll
        for (int b = 0; b < 4; b++)
            #pragma unroll
            for (int i = 0; i < 4; i++) { accA[a][b][i] = 0.f; accB[a][b][i] = 0.f; }

    for (int c = 0; c < 8; c++) {
        CP_WAIT0(); __syncthreads();
        if (c < 7) { ldP2(c + 1, (c + 1) & 1); CP_COMMIT(); }
        const uint32_t* Ws = Wk + (c & 1) * (256 * WRU);
        #pragma unroll
        for (int ks = 0; ks < 2; ks++) {
            const int ku = c * 16 + ks * 8;
            const int kl = ks * 8;
            uint32_t afr[2][4];
            #pragma unroll
            for (int mt = 0; mt < 2; mt++) {
                int r = wm * 32 + mt * 16 + gid;
                afr[mt][0] = XH[r * XSU + ku + tin];
                afr[mt][1] = XH[(r + 8) * XSU + ku + tin];
                afr[mt][2] = XH[r * XSU + ku + tin + 4];
                afr[mt][3] = XH[(r + 8) * XSU + ku + tin + 4];
            }
            #pragma unroll
            for (int nt = 0; nt < 4; nt++) {
                int n = wn * 32 + nt * 8 + gid;
                uint32_t b0 = Ws[n * WRU + kl + tin];
                uint32_t b1f = Ws[n * WRU + kl + tin + 4];
                if (c < 4) {
                    #pragma unroll
                    for (int mt = 0; mt < 2; mt++)
                        mma_f16(accA[mt][nt], afr[mt][0], afr[mt][1], afr[mt][2], afr[mt][3], b0, b1f);
                } else {
                    #pragma unroll
                    for (int mt = 0; mt < 2; mt++)
                        mma_f16(accB[mt][nt], afr[mt][0], afr[mt][1], afr[mt][2], afr[mt][3], b0, b1f);
                }
            }
        }
    }

    // ---- gate math + in-place update ----
    #pragma unroll
    for (int mt = 0; mt < 2; mt++)
        #pragma unroll
        for (int nt = 0; nt < 4; nt++) {
            int cb = wn * 32 + nt * 8 + tin * 2;
            #pragma unroll
            for (int half_ = 0; half_ < 2; half_++) {
                int r = wm * 32 + mt * 16 + gid + half_ * 8;
                int e = e0 + r;
                if (e < E) {
                    int i0 = half_ * 2;
                    float2 ho = *(const float2*)&h[e * D + cb];
                    float z0 = 1.f / (1.f + expf(-(acc1[mt][nt][i0]         + s_bz[cb])));
                    float z1 = 1.f / (1.f + expf(-(acc1[mt][nt][i0 + 1]     + s_bz[cb + 1])));
                    float r0 = 1.f / (1.f + expf(-(acc1[mt][nt + 4][i0]     + s_br[cb])));
                    float r1 = 1.f / (1.f + expf(-(acc1[mt][nt + 4][i0 + 1] + s_br[cb + 1])));
                    float h0 = tanhf(accA[mt][nt][i0]     + s_bah[cb]     + r0 * (accB[mt][nt][i0]     + s_bbh[cb]));
                    float h1 = tanhf(accA[mt][nt][i0 + 1] + s_bah[cb + 1] + r1 * (accB[mt][nt][i0 + 1] + s_bbh[cb + 1]));
                    float2 o;
                    o.x = z0 * ho.x + (1.f - z0) * h0;
                    o.y = z1 * ho.y + (1.f - z1) * h1;
                    *(float2*)&h[e * D + cb] = o;
                }
            }
        }
}

// ---------------- graph segment-sum (sorted graph ids) ----------------
#define GSROWS 512
__global__ __launch_bounds__(128) void graph_sum_kernel(
    const float* __restrict__ link, const int* __restrict__ gid,
    float* __restrict__ gs, int E)
{
    int tid = threadIdx.x;
    int r0 = blockIdx.x * GSROWS;
    if (r0 >= E) return;
    int r1 = min(r0 + GSROWS, E);
    float acc = 0.f;
    int cur = gid[r0];
    for (int r = r0; r < r1; r++) {
        int g = gid[r];
        if (g != cur) {
            atomicAdd(&gs[cur * D + tid], acc);
            acc = 0.f;
            cur = g;
        }
        acc += link[r * D + tid];
    }
    atomicAdd(&gs[cur * D + tid], acc);
}

// ---------------- readout MLP ----------------
__global__ __launch_bounds__(256) void readout_kernel(
    const float* __restrict__ gs,
    const float* __restrict__ rW1, const float* __restrict__ rb1,
    const float* __restrict__ rW2, const float* __restrict__ rb2,
    const float* __restrict__ rW3, const float* __restrict__ rb3,
    float* __restrict__ out)
{
    __shared__ float s_in[D];
    __shared__ float s_r1[HH];
    __shared__ float s_r2[HH];
    const int g = blockIdx.x;
    const int t = threadIdx.x;

    if (t < D) s_in[t] = gs[g * D + t];
    __syncthreads();

    float a = rb1[t];
    #pragma unroll 4
    for (int k = 0; k < D; k++) a = fmaf(s_in[k], rW1[k * HH + t], a);
    s_r1[t] = fmaxf(a, 0.f);
    __syncthreads();

    float b = rb2[t];
    #pragma unroll 4
    for (int k = 0; k < HH; k++) b = fmaf(s_r1[k], rW2[k * HH + t], b);
    s_r2[t] = fmaxf(b, 0.f) * rW3[t];
    __syncthreads();

    for (int s = 128; s > 0; s >>= 1) {
        if (t < s) s_r2[t] += s_r2[t + s];
        __syncthreads();
    }
    if (t == 0) out[g] = s_r2[0] + rb3[0];
}

// ---------------- launch ----------------
extern "C" void kernel_launch(void* const* d_in, const int* in_sizes, int n_in,
                              void* d_out, int out_size)
{
    const float* link0 = (const float*)d_in[0];
    const int*   sf    = (const int*)  d_in[1];
    const int*   ss    = (const int*)  d_in[2];
    const int*   gid   = (const int*)  d_in[3];
    const float* mW1 = (const float*)d_in[5];
    const float* mb1 = (const float*)d_in[6];
    const float* mW2 = (const float*)d_in[7];
    const float* mb2 = (const float*)d_in[8];
    const float* gk  = (const float*)d_in[9];
    const float* gr  = (const float*)d_in[10];
    const float* gb  = (const float*)d_in[11];
    const float* rW1 = (const float*)d_in[12];
    const float* rb1 = (const float*)d_in[13];
    const float* rW2 = (const float*)d_in[14];
    const float* rb2 = (const float*)d_in[15];
    const float* rW3 = (const float*)d_in[16];
    const float* rb3 = (const float*)d_in[17];
    float* out = (float*)d_out;

    const int M = in_sizes[1];
    const int E = in_sizes[3] <= EMAX ? in_sizes[3] : EMAX;

    float *link, *edges, *gs;
    __half *w1h, *w2h, *wgh;
    cudaGetSymbolAddress((void**)&link,  g_link);
    cudaGetSymbolAddress((void**)&edges, g_edges);
    cudaGetSymbolAddress((void**)&gs,    g_gs);
    cudaGetSymbolAddress((void**)&w1h,   g_w1h);
    cudaGetSymbolAddress((void**)&w2h,   g_w2h);
    cudaGetSymbolAddress((void**)&wgh,   g_wgh);

    cudaFuncSetAttribute(msg_mma_kernel, cudaFuncAttributeMaxDynamicSharedMemorySize, MSG_SMEM);
    cudaFuncSetAttribute(gru_mma_kernel, cudaFuncAttributeMaxDynamicSharedMemorySize, GRU_SMEM);

    const int n4 = E * (D / 4);
    copy_kernel<<<(n4 + 255) / 256, 256>>>((float4*)link, (const float4*)link0, n4);
    prep_all<<<768, 256>>>(mW1, mW2, gk, gr, w1h, w2h, wgh);

    const int mblocks = (M + 127) / 128;
    const int gblocks = (E + 63) / 64;
    for (int t = 0; t < TT; t++) {
        zero_kernel<<<(n4 + 255) / 256, 256>>>((float4*)edges, n4);
        msg_mma_kernel<<<mblocks, 512, MSG_SMEM>>>(link, sf, ss, w1h, mb1, w2h, mb2, edges, M);
        gru_mma_kernel<<<gblocks, 256, GRU_SMEM>>>(edges, link, wgh, gb, E);
    }

    const int gs4 = GG * D / 4;
    zero_kernel<<<(gs4 + 255) / 256, 256>>>((float4*)gs, gs4);
    graph_sum_kernel<<<(E + GSROWS - 1) / GSROWS, 128>>>(link, gid, gs, E);
    readout_kernel<<<GG, 256>>>(gs, rW1, rb1, rW2, rb2, rW3, rb3, out);
}

// round 7
// speedup vs baseline: 3.5657x; 1.0986x over previous
#include <cuda_runtime.h>
#include <cuda_fp16.h>
#include <math.h>
#include <stdint.h>

#define D    128
#define HH   256
#define TT   3
#define GG   64
#define EMAX 100000

#define XSU  132   // u32 stride of X/XH rows (264 halves)
#define WRU  20    // u32 stride of W chunk rows (32 halves + pad)

// ---------------- device scratch (no allocations allowed) ----------------
__device__ float  g_link [EMAX * D];
__device__ float  g_edges[EMAX * D];
__device__ float  g_gs   [GG * D];
__device__ __half g_w1h  [256 * 256];   // mW1^T  [n][k] half
__device__ __half g_w2h  [128 * 256];   // mW2^T  [n][k] half
__device__ __half g_wgh  [384 * 256];   // GRU weights^T [n=384][k=256] half

// ---------------- PTX helpers (baseline sm_80+/sm_90+) ----------------
__device__ __forceinline__ uint32_t smem_u32(const void* p) {
    uint32_t a;
    asm("{ .reg .u64 t; cvta.to.shared.u64 t, %1; cvt.u32.u64 %0, t; }" : "=r"(a) : "l"(p));
    return a;
}
__device__ __forceinline__ uint32_t packh2(float a, float b) {
    __half2 h = __floats2half2_rn(a, b);
    return *(uint32_t*)&h;
}
#define CP16(dst, src) \
    asm volatile("cp.async.ca.shared.global [%0], [%1], 16;" :: "r"(dst), "l"(src) : "memory")
#define CP_COMMIT() asm volatile("cp.async.commit_group;" ::: "memory")
#define CP_WAIT0()  asm volatile("cp.async.wait_group 0;" ::: "memory")
#define REDV2(addr, a, b) \
    asm volatile("red.global.add.v2.f32 [%0], {%1, %2};" :: "l"(addr), "f"(a), "f"(b) : "memory")

#define LDSM4(r0, r1, r2, r3, addr) \
    asm volatile("ldmatrix.sync.aligned.m8n8.x4.shared.b16 {%0,%1,%2,%3}, [%4];" \
        : "=r"(r0), "=r"(r1), "=r"(r2), "=r"(r3) : "r"(addr))

__device__ __forceinline__ void mma_f16(float d[4],
                                        uint32_t a0, uint32_t a1, uint32_t a2, uint32_t a3,
                                        uint32_t b0, uint32_t b1) {
    asm volatile(
        "mma.sync.aligned.m16n8k16.row.col.f32.f16.f16.f32 "
        "{%0,%1,%2,%3}, {%4,%5,%6,%7}, {%8,%9}, {%0,%1,%2,%3};\n"
        : "+f"(d[0]), "+f"(d[1]), "+f"(d[2]), "+f"(d[3])
        : "r"(a0), "r"(a1), "r"(a2), "r"(a3), "r"(b0), "r"(b1));
}

// ---------------- utility kernels ----------------
__global__ void zero_kernel(float4* p, int n4) {
    int i = blockIdx.x * blockDim.x + threadIdx.x;
    if (i < n4) p[i] = make_float4(0.f, 0.f, 0.f, 0.f);
}
__global__ void copy_kernel(float4* dst, const float4* __restrict__ src, int n4) {
    int i = blockIdx.x * blockDim.x + threadIdx.x;
    if (i < n4) dst[i] = src[i];
}
__global__ void prep_all(const float* __restrict__ mW1, const float* __restrict__ mW2,
                         const float* __restrict__ gk,  const float* __restrict__ gr,
                         __half* __restrict__ w1h, __half* __restrict__ w2h,
                         __half* __restrict__ wgh) {
    int i = blockIdx.x * blockDim.x + threadIdx.x;
    if (i < 65536) {
        int k = i >> 8, n = i & 255;
        w1h[n * 256 + k] = __float2half_rn(mW1[k * 256 + n]);
    } else if (i < 98304) {
        int j = i - 65536;
        int k = j >> 7, n = j & 127;
        w2h[n * 256 + k] = __float2half_rn(mW2[k * 128 + n]);
    } else if (i < 196608) {
        int j = i - 98304;
        int n = j >> 8, k = j & 255;
        float v = (k < 128) ? gk[k * 384 + n] : gr[(k - 128) * 384 + n];
        wgh[n * 256 + k] = __float2half_rn(v);
    }
}

// =====================================================================
// message MLP (fp16 MMA + ldmatrix): gather -> GEMM1 -> GEMM2 -> red.v2
// 512 threads, block tile = 128 messages
// =====================================================================
#define MSG_SMEM (2560 + 128 * XSU * 4 + 2 * 256 * WRU * 4)
__global__ __launch_bounds__(512, 1) void msg_mma_kernel(
    const float*  __restrict__ link,
    const int*    __restrict__ sf,
    const int*    __restrict__ ss,
    const __half* __restrict__ w1h, const float* __restrict__ b1,
    const __half* __restrict__ w2h, const float* __restrict__ b2,
    float*        __restrict__ edges, int M)
{
    extern __shared__ __align__(16) char smem[];
    int*      s_sf = (int*)smem;
    int*      s_ss = (int*)(smem + 512);
    float*    s_b1 = (float*)(smem + 1024);
    float*    s_b2 = (float*)(smem + 2048);
    uint32_t* Xs   = (uint32_t*)(smem + 2560);
    const uint32_t u_base = smem_u32(smem);
    const uint32_t u_X = u_base + 2560;
    const uint32_t u_W = u_base + 2560 + 128 * XSU * 4;

    const int tid  = threadIdx.x;
    const int lane = tid & 31;
    const int gid  = lane >> 2, tin = lane & 3;
    const int lrow = (lane & 7) + ((lane >> 3) & 1) * 8;  // ldmatrix row-in-16
    const int lcol = (lane >> 4) * 4;                     // ldmatrix u32 col off
    const int wid  = tid >> 5;
    const int wm   = wid & 1;
    const int wn   = wid >> 1;
    const int m0   = blockIdx.x * 128;

    if (tid < 128) {
        int mg = m0 + tid;
        s_sf[tid] = (mg < M) ? sf[mg] : -1;
        s_ss[tid] = (mg < M) ? ss[mg] : -1;
    }
    if (tid < 256) s_b1[tid] = b1[tid];
    if (tid < 128) s_b2[tid] = b2[tid];
    __syncthreads();

    // ---- gather X[128][256] -> half ----
    const float4* link4 = (const float4*)link;
    #pragma unroll
    for (int it = 0; it < 16; it++) {
        int idx = it * 512 + tid;
        int m = idx >> 6, q = idx & 63;
        int e = (q < 32) ? s_sf[m] : s_ss[m];
        float4 v = make_float4(0.f, 0.f, 0.f, 0.f);
        if (e >= 0) v = link4[e * 32 + (q & 31)];
        uint2 t;
        t.x = packh2(v.x, v.y);
        t.y = packh2(v.z, v.w);
        *(uint2*)&Xs[m * XSU + q * 2] = t;
    }

    auto ldW1 = [&](int c, int buf) {
        #pragma unroll
        for (int i = 0; i < 2; i++) {
            int idx = i * 512 + tid;
            int row = idx >> 2, seg = idx & 3;
            uint32_t dst = u_W + (uint32_t)buf * (256 * WRU * 4)
                         + (uint32_t)(row * WRU * 4 + seg * 16);
            CP16(dst, (const char*)w1h + (row * 256 + c * 32 + seg * 8) * 2);
        }
    };
    auto ldW2 = [&](int c, int buf) {
        int row = tid >> 2, seg = tid & 3;
        uint32_t dst = u_W + (uint32_t)buf * (256 * WRU * 4)
                     + (uint32_t)(row * WRU * 4 + seg * 16);
        CP16(dst, (const char*)w2h + (row * 256 + c * 32 + seg * 8) * 2);
    };

    // A-fragment smem base for this lane (row part)
    const uint32_t u_A = u_X + (uint32_t)((wm * 64 + lrow) * XSU + lcol) * 4;

    // ================= GEMM1: H1[128,256] = X @ W1 =================
    float acc[4][4][4];
    #pragma unroll
    for (int a = 0; a < 4; a++)
        #pragma unroll
        for (int b = 0; b < 4; b++)
            #pragma unroll
            for (int i = 0; i < 4; i++) acc[a][b][i] = 0.f;

    ldW1(0, 0); CP_COMMIT();
    for (int c = 0; c < 8; c++) {
        CP_WAIT0(); __syncthreads();
        if (c < 7) { ldW1(c + 1, (c + 1) & 1); CP_COMMIT(); }
        else       { ldW2(0, 0); CP_COMMIT(); }
        const uint32_t u_Wc = u_W + (uint32_t)(c & 1) * (256 * WRU * 4);
        #pragma unroll
        for (int ks = 0; ks < 2; ks++) {
            const int ku = c * 16 + ks * 8;
            const int kl = ks * 8;
            uint32_t afr[4][4];
            #pragma unroll
            for (int mt = 0; mt < 4; mt++)
                LDSM4(afr[mt][0], afr[mt][1], afr[mt][2], afr[mt][3],
                      u_A + (uint32_t)(mt * 16 * XSU + ku) * 4);
            uint32_t bfr[4][2];
            #pragma unroll
            for (int np = 0; np < 2; np++) {
                int n0 = wn * 32 + np * 16;
                uint32_t r0, r1, r2, r3;
                LDSM4(r0, r1, r2, r3,
                      u_Wc + (uint32_t)((n0 + lrow) * WRU + kl + lcol) * 4);
                bfr[2 * np][0] = r0; bfr[2 * np + 1][0] = r1;
                bfr[2 * np][1] = r2; bfr[2 * np + 1][1] = r3;
            }
            #pragma unroll
            for (int nt = 0; nt < 4; nt++)
                #pragma unroll
                for (int mt = 0; mt < 4; mt++)
                    mma_f16(acc[mt][nt], afr[mt][0], afr[mt][1], afr[mt][2], afr[mt][3],
                            bfr[nt][0], bfr[nt][1]);
        }
    }
    __syncthreads();

    // ---- epilogue1: H1 = half(relu(acc + b1)) back into Xs ----
    #pragma unroll
    for (int mt = 0; mt < 4; mt++)
        #pragma unroll
        for (int nt = 0; nt < 4; nt++) {
            int r  = wm * 64 + mt * 16 + gid;
            int cb = wn * 32 + nt * 8 + tin * 2;
            int cu = cb >> 1;
            Xs[r * XSU + cu]       = packh2(fmaxf(acc[mt][nt][0] + s_b1[cb], 0.f),
                                            fmaxf(acc[mt][nt][1] + s_b1[cb + 1], 0.f));
            Xs[(r + 8) * XSU + cu] = packh2(fmaxf(acc[mt][nt][2] + s_b1[cb], 0.f),
                                            fmaxf(acc[mt][nt][3] + s_b1[cb + 1], 0.f));
        }
    __syncthreads();

    // ================= GEMM2: OUT[128,128] = H1 @ W2 =================
    float ac2[4][2][4];
    #pragma unroll
    for (int a = 0; a < 4; a++)
        #pragma unroll
        for (int b = 0; b < 2; b++)
            #pragma unroll
            for (int i = 0; i < 4; i++) ac2[a][b][i] = 0.f;

    for (int c = 0; c < 8; c++) {
        CP_WAIT0(); __syncthreads();
        if (c < 7) { ldW2(c + 1, (c + 1) & 1); CP_COMMIT(); }
        const uint32_t u_Wc = u_W + (uint32_t)(c & 1) * (256 * WRU * 4);
        #pragma unroll
        for (int ks = 0; ks < 2; ks++) {
            const int ku = c * 16 + ks * 8;
            const int kl = ks * 8;
            uint32_t afr[4][4];
            #pragma unroll
            for (int mt = 0; mt < 4; mt++)
                LDSM4(afr[mt][0], afr[mt][1], afr[mt][2], afr[mt][3],
                      u_A + (uint32_t)(mt * 16 * XSU + ku) * 4);
            uint32_t bfr[2][2];
            {
                int n0 = wn * 16;
                uint32_t r0, r1, r2, r3;
                LDSM4(r0, r1, r2, r3,
                      u_Wc + (uint32_t)((n0 + lrow) * WRU + kl + lcol) * 4);
                bfr[0][0] = r0; bfr[1][0] = r1;
                bfr[0][1] = r2; bfr[1][1] = r3;
            }
            #pragma unroll
            for (int nt = 0; nt < 2; nt++)
                #pragma unroll
                for (int mt = 0; mt < 4; mt++)
                    mma_f16(ac2[mt][nt], afr[mt][0], afr[mt][1], afr[mt][2], afr[mt][3],
                            bfr[nt][0], bfr[nt][1]);
        }
    }

    // ---- epilogue2: relu + bias + vector red scatter ----
    #pragma unroll
    for (int mt = 0; mt < 4; mt++)
        #pragma unroll
        for (int nt = 0; nt < 2; nt++) {
            int r  = wm * 64 + mt * 16 + gid;
            int cb = wn * 16 + nt * 8 + tin * 2;
            int e0 = s_ss[r], e1 = s_ss[r + 8];
            if (e0 >= 0) {
                float v0 = fmaxf(ac2[mt][nt][0] + s_b2[cb], 0.f);
                float v1 = fmaxf(ac2[mt][nt][1] + s_b2[cb + 1], 0.f);
                REDV2(&edges[e0 * D + cb], v0, v1);
            }
            if (e1 >= 0) {
                float v0 = fmaxf(ac2[mt][nt][2] + s_b2[cb], 0.f);
                float v1 = fmaxf(ac2[mt][nt][3] + s_b2[cb + 1], 0.f);
                REDV2(&edges[e1 * D + cb], v0, v1);
            }
        }
}

// =====================================================================
// GRU (fp16 MMA + ldmatrix): 256 threads, 64-row tile, two fused passes
// =====================================================================
#define GRU_SMEM (2048 + 64 * XSU * 4 + 2 * 256 * WRU * 4)
__global__ __launch_bounds__(256, 1) void gru_mma_kernel(
    const float*  __restrict__ x,
    float*        __restrict__ h,
    const __half* __restrict__ wgh,
    const float*  __restrict__ gbias,
    int E)
{
    extern __shared__ __align__(16) char smem[];
    float*    s_bz  = (float*)smem;
    float*    s_br  = (float*)(smem + 512);
    float*    s_bah = (float*)(smem + 1024);
    float*    s_bbh = (float*)(smem + 1536);
    uint32_t* XH    = (uint32_t*)(smem + 2048);
    const uint32_t u_base = smem_u32(smem);
    const uint32_t u_X = u_base + 2048;
    const uint32_t u_W = u_base + 2048 + 64 * XSU * 4;

    const int tid  = threadIdx.x;
    const int lane = tid & 31;
    const int gid  = lane >> 2, tin = lane & 3;
    const int lrow = (lane & 7) + ((lane >> 3) & 1) * 8;
    const int lcol = (lane >> 4) * 4;
    const int wid  = tid >> 5;
    const int wm   = wid & 1;
    const int wn   = wid >> 1;
    const int e0   = blockIdx.x * 64;

    if (tid < 128) {
        s_bz[tid]  = gbias[tid]       + gbias[384 + tid];
        s_br[tid]  = gbias[128 + tid] + gbias[512 + tid];
        s_bah[tid] = gbias[256 + tid];
        s_bbh[tid] = gbias[640 + tid];
    }

    const float4* xe4 = (const float4*)x;
    const float4* ln4 = (const float4*)h;
    #pragma unroll
    for (int it = 0; it < 16; it++) {
        int idx = it * 256 + tid;
        int m = idx >> 6, q = idx & 63;
        int e = e0 + m;
        float4 v = make_float4(0.f, 0.f, 0.f, 0.f);
        if (e < E) v = (q < 32) ? xe4[e * 32 + q] : ln4[e * 32 + (q - 32)];
        uint2 t;
        t.x = packh2(v.x, v.y);
        t.y = packh2(v.z, v.w);
        *(uint2*)&XH[m * XSU + q * 2] = t;
    }

    auto ldP1 = [&](int c, int buf) {
        #pragma unroll
        for (int i = 0; i < 4; i++) {
            int idx = i * 256 + tid;
            int row = idx >> 2, seg = idx & 3;
            uint32_t dst = u_W + (uint32_t)buf * (256 * WRU * 4)
                         + (uint32_t)(row * WRU * 4 + seg * 16);
            CP16(dst, (const char*)wgh + (row * 256 + c * 32 + seg * 8) * 2);
        }
    };
    auto ldP2 = [&](int c, int buf) {
        #pragma unroll
        for (int i = 0; i < 2; i++) {
            int idx = i * 256 + tid;
            int row = idx >> 2, seg = idx & 3;
            uint32_t dst = u_W + (uint32_t)buf * (256 * WRU * 4)
                         + (uint32_t)(row * WRU * 4 + seg * 16);
            CP16(dst, (const char*)wgh + ((256 + row) * 256 + c * 32 + seg * 8) * 2);
        }
    };

    const uint32_t u_A = u_X + (uint32_t)((wm * 32 + lrow) * XSU + lcol) * 4;

    // ---- pass1: z|r (N=256, K=256) ----
    float acc1[2][8][4];
    #pragma unroll
    for (int a = 0; a < 2; a++)
        #pragma unroll
        for (int b = 0; b < 8; b++)
            #pragma unroll
            for (int i = 0; i < 4; i++) acc1[a][b][i] = 0.f;

    ldP1(0, 0); CP_COMMIT();
    for (int c = 0; c < 8; c++) {
        CP_WAIT0(); __syncthreads();
        if (c < 7) { ldP1(c + 1, (c + 1) & 1); CP_COMMIT(); }
        else       { ldP2(0, 0); CP_COMMIT(); }
        const uint32_t u_Wc = u_W + (uint32_t)(c & 1) * (256 * WRU * 4);
        #pragma unroll
        for (int ks = 0; ks < 2; ks++) {
            const int ku = c * 16 + ks * 8;
            const int kl = ks * 8;
            uint32_t afr[2][4];
            #pragma unroll
            for (int mt = 0; mt < 2; mt++)
                LDSM4(afr[mt][0], afr[mt][1], afr[mt][2], afr[mt][3],
                      u_A + (uint32_t)(mt * 16 * XSU + ku) * 4);
            uint32_t bfr[8][2];
            #pragma unroll
            for (int jp = 0; jp < 4; jp++) {     // j pairs (0,1),(2,3),(4,5),(6,7)
                int n0 = (jp < 2) ? (wn * 32 + jp * 16)
                                  : (128 + wn * 32 + (jp - 2) * 16);
                uint32_t r0, r1, r2, r3;
                LDSM4(r0, r1, r2, r3,
                      u_Wc + (uint32_t)((n0 + lrow) * WRU + kl + lcol) * 4);
                bfr[2 * jp][0] = r0; bfr[2 * jp + 1][0] = r1;
                bfr[2 * jp][1] = r2; bfr[2 * jp + 1][1] = r3;
            }
            #pragma unroll
            for (int j = 0; j < 8; j++)
                #pragma unroll
                for (int mt = 0; mt < 2; mt++)
                    mma_f16(acc1[mt][j], afr[mt][0], afr[mt][1], afr[mt][2], afr[mt][3],
                            bfr[j][0], bfr[j][1]);
        }
    }

    // ---- pass2: ah (chunks 0-3, x@Kh) / bh (chunks 4-7, h@Rh) ----
    float accA[2][4][4], accB[2][4][4];
    #pragma unroll
    for (int a = 0; a < 2; a++)
        #pragma unroll
        for (int b = 0; b < 4; b++)
            #pragma unroll
            for (int i = 0; i < 4; i++) { accA[a][b][i] = 0.f; accB[a][b][i] = 0.f; }

    for (int c = 0; c < 8; c++) {
        CP_WAIT0(); __syncthreads();
        if (c < 7) { ldP2(c + 1, (c + 1) & 1); CP_COMMIT(); }
        const uint32_t u_Wc = u_W + (uint32_t)(c & 1) * (256 * WRU * 4);
        #pragma unroll
        for (int ks = 0; ks < 2; ks++) {
            const int ku = c * 16 + ks * 8;
            const int kl = ks * 8;
            uint32_t afr[2][4];
            #pragma unroll
            for (int mt = 0; mt < 2; mt++)
                LDSM4(afr[mt][0], afr[mt][1], afr[mt][2], afr[mt][3],
                      u_A + (uint32_t)(mt * 16 * XSU + ku) * 4);
            uint32_t bfr[4][2];
            #pragma unroll
            for (int np = 0; np < 2; np++) {
                int n0 = wn * 32 + np * 16;
                uint32_t r0, r1, r2, r3;
                LDSM4(r0, r1, r2, r3,
                      u_Wc + (uint32_t)((n0 + lrow) * WRU + kl + lcol) * 4);
                bfr[2 * np][0] = r0; bfr[2 * np + 1][0] = r1;
                bfr[2 * np][1] = r2; bfr[2 * np + 1][1] = r3;
            }
            if (c < 4) {
                #pragma unroll
                for (int nt = 0; nt < 4; nt++)
                    #pragma unroll
                    for (int mt = 0; mt < 2; mt++)
                        mma_f16(accA[mt][nt], afr[mt][0], afr[mt][1], afr[mt][2], afr[mt][3],
                                bfr[nt][0], bfr[nt][1]);
            } else {
                #pragma unroll
                for (int nt = 0; nt < 4; nt++)
                    #pragma unroll
                    for (int mt = 0; mt < 2; mt++)
                        mma_f16(accB[mt][nt], afr[mt][0], afr[mt][1], afr[mt][2], afr[mt][3],
                                bfr[nt][0], bfr[nt][1]);
            }
        }
    }

    // ---- gate math + in-place update ----
    #pragma unroll
    for (int mt = 0; mt < 2; mt++)
        #pragma unroll
        for (int nt = 0; nt < 4; nt++) {
            int cb = wn * 32 + nt * 8 + tin * 2;
            #pragma unroll
            for (int half_ = 0; half_ < 2; half_++) {
                int r = wm * 32 + mt * 16 + gid + half_ * 8;
                int e = e0 + r;
                if (e < E) {
                    int i0 = half_ * 2;
                    float2 ho = *(const float2*)&h[e * D + cb];
                    float z0 = 1.f / (1.f + expf(-(acc1[mt][nt][i0]         + s_bz[cb])));
                    float z1 = 1.f / (1.f + expf(-(acc1[mt][nt][i0 + 1]     + s_bz[cb + 1])));
                    float r0 = 1.f / (1.f + expf(-(acc1[mt][nt + 4][i0]     + s_br[cb])));
                    float r1 = 1.f / (1.f + expf(-(acc1[mt][nt + 4][i0 + 1] + s_br[cb + 1])));
                    float h0 = tanhf(accA[mt][nt][i0]     + s_bah[cb]     + r0 * (accB[mt][nt][i0]     + s_bbh[cb]));
                    float h1 = tanhf(accA[mt][nt][i0 + 1] + s_bah[cb + 1] + r1 * (accB[mt][nt][i0 + 1] + s_bbh[cb + 1]));
                    float2 o;
                    o.x = z0 * ho.x + (1.f - z0) * h0;
                    o.y = z1 * ho.y + (1.f - z1) * h1;
                    *(float2*)&h[e * D + cb] = o;
                }
            }
        }
}

// ---------------- graph segment-sum (sorted graph ids) ----------------
#define GSROWS 512
__global__ __launch_bounds__(128) void graph_sum_kernel(
    const float* __restrict__ link, const int* __restrict__ gid,
    float* __restrict__ gs, int E)
{
    int tid = threadIdx.x;
    int r0 = blockIdx.x * GSROWS;
    if (r0 >= E) return;
    int r1 = min(r0 + GSROWS, E);
    float acc = 0.f;
    int cur = gid[r0];
    for (int r = r0; r < r1; r++) {
        int g = gid[r];
        if (g != cur) {
            atomicAdd(&gs[cur * D + tid], acc);
            acc = 0.f;
            cur = g;
        }
        acc += link[r * D + tid];
    }
    atomicAdd(&gs[cur * D + tid], acc);
}

// ---------------- readout MLP ----------------
__global__ __launch_bounds__(256) void readout_kernel(
    const float* __restrict__ gs,
    const float* __restrict__ rW1, const float* __restrict__ rb1,
    const float* __restrict__ rW2, const float* __restrict__ rb2,
    const float* __restrict__ rW3, const float* __restrict__ rb3,
    float* __restrict__ out)
{
    __shared__ float s_in[D];
    __shared__ float s_r1[HH];
    __shared__ float s_r2[HH];
    const int g = blockIdx.x;
    const int t = threadIdx.x;

    if (t < D) s_in[t] = gs[g * D + t];
    __syncthreads();

    float a = rb1[t];
    #pragma unroll 4
    for (int k = 0; k < D; k++) a = fmaf(s_in[k], rW1[k * HH + t], a);
    s_r1[t] = fmaxf(a, 0.f);
    __syncthreads();

    float b = rb2[t];
    #pragma unroll 4
    for (int k = 0; k < HH; k++) b = fmaf(s_r1[k], rW2[k * HH + t], b);
    s_r2[t] = fmaxf(b, 0.f) * rW3[t];
    __syncthreads();

    for (int s = 128; s > 0; s >>= 1) {
        if (t < s) s_r2[t] += s_r2[t + s];
        __syncthreads();
    }
    if (t == 0) out[g] = s_r2[0] + rb3[0];
}

// ---------------- launch ----------------
extern "C" void kernel_launch(void* const* d_in, const int* in_sizes, int n_in,
                              void* d_out, int out_size)
{
    const float* link0 = (const float*)d_in[0];
    const int*   sf    = (const int*)  d_in[1];
    const int*   ss    = (const int*)  d_in[2];
    const int*   gid   = (const int*)  d_in[3];
    const float* mW1 = (const float*)d_in[5];
    const float* mb1 = (const float*)d_in[6];
    const float* mW2 = (const float*)d_in[7];
    const float* mb2 = (const float*)d_in[8];
    const float* gk  = (const float*)d_in[9];
    const float* gr  = (const float*)d_in[10];
    const float* gb  = (const float*)d_in[11];
    const float* rW1 = (const float*)d_in[12];
    const float* rb1 = (const float*)d_in[13];
    const float* rW2 = (const float*)d_in[14];
    const float* rb2 = (const float*)d_in[15];
    const float* rW3 = (const float*)d_in[16];
    const float* rb3 = (const float*)d_in[17];
    float* out = (float*)d_out;

    const int M = in_sizes[1];
    const int E = in_sizes[3] <= EMAX ? in_sizes[3] : EMAX;

    float *link, *edges, *gs;
    __half *w1h, *w2h, *wgh;
    cudaGetSymbolAddress((void**)&link,  g_link);
    cudaGetSymbolAddress((void**)&edges, g_edges);
    cudaGetSymbolAddress((void**)&gs,    g_gs);
    cudaGetSymbolAddress((void**)&w1h,   g_w1h);
    cudaGetSymbolAddress((void**)&w2h,   g_w2h);
    cudaGetSymbolAddress((void**)&wgh,   g_wgh);

    cudaFuncSetAttribute(msg_mma_kernel, cudaFuncAttributeMaxDynamicSharedMemorySize, MSG_SMEM);
    cudaFuncSetAttribute(gru_mma_kernel, cudaFuncAttributeMaxDynamicSharedMemorySize, GRU_SMEM);

    const int n4 = E * (D / 4);
    copy_kernel<<<(n4 + 255) / 256, 256>>>((float4*)link, (const float4*)link0, n4);
    prep_all<<<768, 256>>>(mW1, mW2, gk, gr, w1h, w2h, wgh);

    const int mblocks = (M + 127) / 128;
    const int gblocks = (E + 63) / 64;
    for (int t = 0; t < TT; t++) {
        zero_kernel<<<(n4 + 255) / 256, 256>>>((float4*)edges, n4);
        msg_mma_kernel<<<mblocks, 512, MSG_SMEM>>>(link, sf, ss, w1h, mb1, w2h, mb2, edges, M);
        gru_mma_kernel<<<gblocks, 256, GRU_SMEM>>>(edges, link, wgh, gb, E);
    }

    const int gs4 = GG * D / 4;
    zero_kernel<<<(gs4 + 255) / 256, 256>>>((float4*)gs, gs4);
    graph_sum_kernel<<<(E + GSROWS - 1) / GSROWS, 128>>>(link, gid, gs, E);
    readout_kernel<<<GG, 256>>>(gs, rW1, rb1, rW2, rb2, rW3, rb3, out);
}

// round 8
// speedup vs baseline: 3.7644x; 1.0557x over previous
#include <cuda_runtime.h>
#include <cuda_fp16.h>
#include <math.h>
#include <stdint.h>

#define D    128
#define HH   256
#define TT   3
#define GG   64
#define EMAX 100000

#define XSU  132   // u32 stride of X/XH rows (264 halves)
#define WRU  36    // u32 stride of W chunk rows (64 halves + pad) -> 16B-group stride 9 (conflict-free)

// ---------------- device scratch (no allocations allowed) ----------------
__device__ float  g_link [EMAX * D];
__device__ float  g_edges[EMAX * D];
__device__ float  g_gs   [GG * D];
__device__ __half g_w1h  [256 * 256];   // mW1^T  [n][k] half
__device__ __half g_w2h  [128 * 256];   // mW2^T  [n][k] half
__device__ __half g_wgh  [384 * 256];   // GRU weights^T [n=384][k=256] half

// ---------------- PTX helpers ----------------
__device__ __forceinline__ uint32_t smem_u32(const void* p) {
    uint32_t a;
    asm("{ .reg .u64 t; cvta.to.shared.u64 t, %1; cvt.u32.u64 %0, t; }" : "=r"(a) : "l"(p));
    return a;
}
__device__ __forceinline__ uint32_t packh2(float a, float b) {
    __half2 h = __floats2half2_rn(a, b);
    return *(uint32_t*)&h;
}
#define CP16(dst, src) \
    asm volatile("cp.async.ca.shared.global [%0], [%1], 16;" :: "r"(dst), "l"(src) : "memory")
#define CP_COMMIT() asm volatile("cp.async.commit_group;" ::: "memory")
#define CP_WAIT0()  asm volatile("cp.async.wait_group 0;" ::: "memory")
#define REDV2(addr, a, b) \
    asm volatile("red.global.add.v2.f32 [%0], {%1, %2};" :: "l"(addr), "f"(a), "f"(b) : "memory")
#define LDSM4(r0, r1, r2, r3, addr) \
    asm volatile("ldmatrix.sync.aligned.m8n8.x4.shared.b16 {%0,%1,%2,%3}, [%4];" \
        : "=r"(r0), "=r"(r1), "=r"(r2), "=r"(r3) : "r"(addr))

__device__ __forceinline__ void mma_f16(float d[4],
                                        uint32_t a0, uint32_t a1, uint32_t a2, uint32_t a3,
                                        uint32_t b0, uint32_t b1) {
    asm volatile(
        "mma.sync.aligned.m16n8k16.row.col.f32.f16.f16.f32 "
        "{%0,%1,%2,%3}, {%4,%5,%6,%7}, {%8,%9}, {%0,%1,%2,%3};\n"
        : "+f"(d[0]), "+f"(d[1]), "+f"(d[2]), "+f"(d[3])
        : "r"(a0), "r"(a1), "r"(a2), "r"(a3), "r"(b0), "r"(b1));
}

// ---------------- utility kernels ----------------
__global__ void zero_kernel(float4* p, int n4) {
    int i = blockIdx.x * blockDim.x + threadIdx.x;
    if (i < n4) p[i] = make_float4(0.f, 0.f, 0.f, 0.f);
}
__global__ void copy_kernel(float4* dst, const float4* __restrict__ src, int n4) {
    int i = blockIdx.x * blockDim.x + threadIdx.x;
    if (i < n4) dst[i] = src[i];
}
__global__ void prep_all(const float* __restrict__ mW1, const float* __restrict__ mW2,
                         const float* __restrict__ gk,  const float* __restrict__ gr,
                         __half* __restrict__ w1h, __half* __restrict__ w2h,
                         __half* __restrict__ wgh) {
    int i = blockIdx.x * blockDim.x + threadIdx.x;
    if (i < 65536) {
        int k = i >> 8, n = i & 255;
        w1h[n * 256 + k] = __float2half_rn(mW1[k * 256 + n]);
    } else if (i < 98304) {
        int j = i - 65536;
        int k = j >> 7, n = j & 127;
        w2h[n * 256 + k] = __float2half_rn(mW2[k * 128 + n]);
    } else if (i < 196608) {
        int j = i - 98304;
        int n = j >> 8, k = j & 255;
        float v = (k < 128) ? gk[k * 384 + n] : gr[(k - 128) * 384 + n];
        wgh[n * 256 + k] = __float2half_rn(v);
    }
}

// =====================================================================
// message MLP: 512 threads, 128-msg tile, 64-k W chunks (4 barriers/GEMM)
// smem: hdr 2560 | X [128][264h] 67584 | W 2x[256][144B] 73728  = 143872
// =====================================================================
#define MSG_SMEM (2560 + 128 * XSU * 4 + 2 * 256 * WRU * 4)
__global__ __launch_bounds__(512, 1) void msg_mma_kernel(
    const float*  __restrict__ link,
    const int*    __restrict__ sf,
    const int*    __restrict__ ss,
    const __half* __restrict__ w1h, const float* __restrict__ b1,
    const __half* __restrict__ w2h, const float* __restrict__ b2,
    float*        __restrict__ edges, int M)
{
    extern __shared__ __align__(16) char smem[];
    int*      s_sf = (int*)smem;
    int*      s_ss = (int*)(smem + 512);
    float*    s_b1 = (float*)(smem + 1024);
    float*    s_b2 = (float*)(smem + 2048);
    uint32_t* Xs   = (uint32_t*)(smem + 2560);
    const uint32_t u_base = smem_u32(smem);
    const uint32_t u_X = u_base + 2560;
    const uint32_t u_W = u_base + 2560 + 128 * XSU * 4;

    const int tid  = threadIdx.x;
    const int lane = tid & 31;
    const int gid  = lane >> 2, tin = lane & 3;
    const int lrow = (lane & 7) + ((lane >> 3) & 1) * 8;
    const int lcol = (lane >> 4) * 4;
    const int wid  = tid >> 5;
    const int wm   = wid & 1;
    const int wn   = wid >> 1;
    const int m0   = blockIdx.x * 128;

    if (tid < 128) {
        int mg = m0 + tid;
        s_sf[tid] = (mg < M) ? sf[mg] : -1;
        s_ss[tid] = (mg < M) ? ss[mg] : -1;
    }
    if (tid < 256) s_b1[tid] = b1[tid];
    if (tid < 128) s_b2[tid] = b2[tid];
    __syncthreads();

    // ---- gather X[128][256] -> half ----
    const float4* link4 = (const float4*)link;
    #pragma unroll
    for (int it = 0; it < 16; it++) {
        int idx = it * 512 + tid;
        int m = idx >> 6, q = idx & 63;
        int e = (q < 32) ? s_sf[m] : s_ss[m];
        float4 v = make_float4(0.f, 0.f, 0.f, 0.f);
        if (e >= 0) v = link4[e * 32 + (q & 31)];
        uint2 t;
        t.x = packh2(v.x, v.y);
        t.y = packh2(v.z, v.w);
        *(uint2*)&Xs[m * XSU + q * 2] = t;
    }

    // 64-k chunk loaders
    auto ldW1 = [&](int c, int buf) {       // 256 rows x 8 segs -> 4/thread
        #pragma unroll
        for (int i = 0; i < 4; i++) {
            int idx = i * 512 + tid;
            int row = idx >> 3, seg = idx & 7;
            uint32_t dst = u_W + (uint32_t)buf * (256 * WRU * 4)
                         + (uint32_t)(row * WRU * 4 + seg * 16);
            CP16(dst, (const char*)w1h + (row * 256 + c * 64 + seg * 8) * 2);
        }
    };
    auto ldW2 = [&](int c, int buf) {       // 128 rows x 8 segs -> 2/thread
        #pragma unroll
        for (int i = 0; i < 2; i++) {
            int idx = i * 512 + tid;
            int row = idx >> 3, seg = idx & 7;
            uint32_t dst = u_W + (uint32_t)buf * (256 * WRU * 4)
                         + (uint32_t)(row * WRU * 4 + seg * 16);
            CP16(dst, (const char*)w2h + (row * 256 + c * 64 + seg * 8) * 2);
        }
    };

    const uint32_t u_A = u_X + (uint32_t)((wm * 64 + lrow) * XSU + lcol) * 4;

    // ================= GEMM1: H1[128,256] = X @ W1 =================
    float acc[4][4][4];
    #pragma unroll
    for (int a = 0; a < 4; a++)
        #pragma unroll
        for (int b = 0; b < 4; b++)
            #pragma unroll
            for (int i = 0; i < 4; i++) acc[a][b][i] = 0.f;

    ldW1(0, 0); CP_COMMIT();
    for (int c = 0; c < 4; c++) {
        CP_WAIT0(); __syncthreads();
        if (c < 3) { ldW1(c + 1, (c + 1) & 1); CP_COMMIT(); }
        else       { ldW2(0, 0); CP_COMMIT(); }
        const uint32_t u_Wc = u_W + (uint32_t)(c & 1) * (256 * WRU * 4);
        #pragma unroll
        for (int ks = 0; ks < 4; ks++) {
            const int ku = c * 32 + ks * 8;
            const int kl = ks * 8;
            uint32_t afr[4][4];
            #pragma unroll
            for (int mt = 0; mt < 4; mt++)
                LDSM4(afr[mt][0], afr[mt][1], afr[mt][2], afr[mt][3],
                      u_A + (uint32_t)(mt * 16 * XSU + ku) * 4);
            uint32_t bfr[4][2];
            #pragma unroll
            for (int np = 0; np < 2; np++) {
                int n0 = wn * 32 + np * 16;
                uint32_t r0, r1, r2, r3;
                LDSM4(r0, r1, r2, r3,
                      u_Wc + (uint32_t)((n0 + lrow) * WRU + kl + lcol) * 4);
                bfr[2 * np][0] = r0; bfr[2 * np + 1][0] = r1;
                bfr[2 * np][1] = r2; bfr[2 * np + 1][1] = r3;
            }
            #pragma unroll
            for (int nt = 0; nt < 4; nt++)
                #pragma unroll
                for (int mt = 0; mt < 4; mt++)
                    mma_f16(acc[mt][nt], afr[mt][0], afr[mt][1], afr[mt][2], afr[mt][3],
                            bfr[nt][0], bfr[nt][1]);
        }
    }
    __syncthreads();

    // ---- epilogue1: H1 = half(relu(acc + b1)) back into Xs ----
    #pragma unroll
    for (int mt = 0; mt < 4; mt++)
        #pragma unroll
        for (int nt = 0; nt < 4; nt++) {
            int r  = wm * 64 + mt * 16 + gid;
            int cb = wn * 32 + nt * 8 + tin * 2;
            int cu = cb >> 1;
            Xs[r * XSU + cu]       = packh2(fmaxf(acc[mt][nt][0] + s_b1[cb], 0.f),
                                            fmaxf(acc[mt][nt][1] + s_b1[cb + 1], 0.f));
            Xs[(r + 8) * XSU + cu] = packh2(fmaxf(acc[mt][nt][2] + s_b1[cb], 0.f),
                                            fmaxf(acc[mt][nt][3] + s_b1[cb + 1], 0.f));
        }
    __syncthreads();

    // ================= GEMM2: OUT[128,128] = H1 @ W2 =================
    float ac2[4][2][4];
    #pragma unroll
    for (int a = 0; a < 4; a++)
        #pragma unroll
        for (int b = 0; b < 2; b++)
            #pragma unroll
            for (int i = 0; i < 4; i++) ac2[a][b][i] = 0.f;

    for (int c = 0; c < 4; c++) {
        CP_WAIT0(); __syncthreads();
        if (c < 3) { ldW2(c + 1, (c + 1) & 1); CP_COMMIT(); }
        const uint32_t u_Wc = u_W + (uint32_t)(c & 1) * (256 * WRU * 4);
        #pragma unroll
        for (int ks = 0; ks < 4; ks++) {
            const int ku = c * 32 + ks * 8;
            const int kl = ks * 8;
            uint32_t afr[4][4];
            #pragma unroll
            for (int mt = 0; mt < 4; mt++)
                LDSM4(afr[mt][0], afr[mt][1], afr[mt][2], afr[mt][3],
                      u_A + (uint32_t)(mt * 16 * XSU + ku) * 4);
            uint32_t bfr[2][2];
            {
                int n0 = wn * 16;
                uint32_t r0, r1, r2, r3;
                LDSM4(r0, r1, r2, r3,
                      u_Wc + (uint32_t)((n0 + lrow) * WRU + kl + lcol) * 4);
                bfr[0][0] = r0; bfr[1][0] = r1;
                bfr[0][1] = r2; bfr[1][1] = r3;
            }
            #pragma unroll
            for (int nt = 0; nt < 2; nt++)
                #pragma unroll
                for (int mt = 0; mt < 4; mt++)
                    mma_f16(ac2[mt][nt], afr[mt][0], afr[mt][1], afr[mt][2], afr[mt][3],
                            bfr[nt][0], bfr[nt][1]);
        }
    }

    // ---- epilogue2: relu + bias + vector red scatter ----
    #pragma unroll
    for (int mt = 0; mt < 4; mt++)
        #pragma unroll
        for (int nt = 0; nt < 2; nt++) {
            int r  = wm * 64 + mt * 16 + gid;
            int cb = wn * 16 + nt * 8 + tin * 2;
            int e0 = s_ss[r], e1 = s_ss[r + 8];
            if (e0 >= 0) {
                float v0 = fmaxf(ac2[mt][nt][0] + s_b2[cb], 0.f);
                float v1 = fmaxf(ac2[mt][nt][1] + s_b2[cb + 1], 0.f);
                REDV2(&edges[e0 * D + cb], v0, v1);
            }
            if (e1 >= 0) {
                float v0 = fmaxf(ac2[mt][nt][2] + s_b2[cb], 0.f);
                float v1 = fmaxf(ac2[mt][nt][3] + s_b2[cb + 1], 0.f);
                REDV2(&edges[e1 * D + cb], v0, v1);
            }
        }
}

// =====================================================================
// GRU: 256 threads, 64-row tile, SINGLE merged k-loop over [384][64k] chunks
// (z|r -> acc1, h-gate -> accA for k<128 / accB for k>=128); 4 barriers total
// smem: biases 2048 | XH [64][264h] 33792 | W 2x[384][144B] 110592 = 146432
// =====================================================================
#define GRU_SMEM (2048 + 64 * XSU * 4 + 2 * 384 * WRU * 4)
__global__ __launch_bounds__(256, 1) void gru_mma_kernel(
    const float*  __restrict__ x,
    float*        __restrict__ h,
    const __half* __restrict__ wgh,
    const float*  __restrict__ gbias,
    int E)
{
    extern __shared__ __align__(16) char smem[];
    float*    s_bz  = (float*)smem;
    float*    s_br  = (float*)(smem + 512);
    float*    s_bah = (float*)(smem + 1024);
    float*    s_bbh = (float*)(smem + 1536);
    uint32_t* XH    = (uint32_t*)(smem + 2048);
    const uint32_t u_base = smem_u32(smem);
    const uint32_t u_X = u_base + 2048;
    const uint32_t u_W = u_base + 2048 + 64 * XSU * 4;

    const int tid  = threadIdx.x;
    const int lane = tid & 31;
    const int gid  = lane >> 2, tin = lane & 3;
    const int lrow = (lane & 7) + ((lane >> 3) & 1) * 8;
    const int lcol = (lane >> 4) * 4;
    const int wid  = tid >> 5;
    const int wm   = wid & 1;
    const int wn   = wid >> 1;
    const int e0   = blockIdx.x * 64;

    if (tid < 128) {
        s_bz[tid]  = gbias[tid]       + gbias[384 + tid];
        s_br[tid]  = gbias[128 + tid] + gbias[512 + tid];
        s_bah[tid] = gbias[256 + tid];
        s_bbh[tid] = gbias[640 + tid];
    }

    const float4* xe4 = (const float4*)x;
    const float4* ln4 = (const float4*)h;
    #pragma unroll
    for (int it = 0; it < 16; it++) {
        int idx = it * 256 + tid;
        int m = idx >> 6, q = idx & 63;
        int e = e0 + m;
        float4 v = make_float4(0.f, 0.f, 0.f, 0.f);
        if (e < E) v = (q < 32) ? xe4[e * 32 + q] : ln4[e * 32 + (q - 32)];
        uint2 t;
        t.x = packh2(v.x, v.y);
        t.y = packh2(v.z, v.w);
        *(uint2*)&XH[m * XSU + q * 2] = t;
    }

    // all-weights chunk loader: 384 rows x 8 segs = 3072 -> 12/thread
    auto ldP = [&](int c, int buf) {
        #pragma unroll
        for (int i = 0; i < 12; i++) {
            int idx = i * 256 + tid;
            int row = idx >> 3, seg = idx & 7;
            uint32_t dst = u_W + (uint32_t)buf * (384 * WRU * 4)
                         + (uint32_t)(row * WRU * 4 + seg * 16);
            CP16(dst, (const char*)wgh + (row * 256 + c * 64 + seg * 8) * 2);
        }
    };

    const uint32_t u_A = u_X + (uint32_t)((wm * 32 + lrow) * XSU + lcol) * 4;

    float acc1[2][8][4], accA[2][4][4], accB[2][4][4];
    #pragma unroll
    for (int a = 0; a < 2; a++) {
        #pragma unroll
        for (int b = 0; b < 8; b++)
            #pragma unroll
            for (int i = 0; i < 4; i++) acc1[a][b][i] = 0.f;
        #pragma unroll
        for (int b = 0; b < 4; b++)
            #pragma unroll
            for (int i = 0; i < 4; i++) { accA[a][b][i] = 0.f; accB[a][b][i] = 0.f; }
    }

    ldP(0, 0); CP_COMMIT();
    for (int c = 0; c < 4; c++) {
        CP_WAIT0(); __syncthreads();
        if (c < 3) { ldP(c + 1, (c + 1) & 1); CP_COMMIT(); }
        const uint32_t u_Wc = u_W + (uint32_t)(c & 1) * (384 * WRU * 4);
        #pragma unroll
        for (int ks = 0; ks < 4; ks++) {
            const int ku = c * 32 + ks * 8;
            const int kl = ks * 8;
            uint32_t afr[2][4];
            #pragma unroll
            for (int mt = 0; mt < 2; mt++)
                LDSM4(afr[mt][0], afr[mt][1], afr[mt][2], afr[mt][3],
                      u_A + (uint32_t)(mt * 16 * XSU + ku) * 4);
            // B frags: 8 z|r tiles + 4 h tiles
            uint32_t bfr[12][2];
            #pragma unroll
            for (int jp = 0; jp < 4; jp++) {
                int n0 = (jp < 2) ? (wn * 32 + jp * 16)
                                  : (128 + wn * 32 + (jp - 2) * 16);
                uint32_t r0, r1, r2, r3;
                LDSM4(r0, r1, r2, r3,
                      u_Wc + (uint32_t)((n0 + lrow) * WRU + kl + lcol) * 4);
                bfr[2 * jp][0] = r0; bfr[2 * jp + 1][0] = r1;
                bfr[2 * jp][1] = r2; bfr[2 * jp + 1][1] = r3;
            }
            #pragma unroll
            for (int np = 0; np < 2; np++) {
                int n0 = 256 + wn * 32 + np * 16;
                uint32_t r0, r1, r2, r3;
                LDSM4(r0, r1, r2, r3,
                      u_Wc + (uint32_t)((n0 + lrow) * WRU + kl + lcol) * 4);
                bfr[8 + 2 * np][0] = r0; bfr[8 + 2 * np + 1][0] = r1;
                bfr[8 + 2 * np][1] = r2; bfr[8 + 2 * np + 1][1] = r3;
            }
            #pragma unroll
            for (int j = 0; j < 8; j++)
                #pragma unroll
                for (int mt = 0; mt < 2; mt++)
                    mma_f16(acc1[mt][j], afr[mt][0], afr[mt][1], afr[mt][2], afr[mt][3],
                            bfr[j][0], bfr[j][1]);
            if (c < 2) {
                #pragma unroll
                for (int nt = 0; nt < 4; nt++)
                    #pragma unroll
                    for (int mt = 0; mt < 2; mt++)
                        mma_f16(accA[mt][nt], afr[mt][0], afr[mt][1], afr[mt][2], afr[mt][3],
                                bfr[8 + nt][0], bfr[8 + nt][1]);
            } else {
                #pragma unroll
                for (int nt = 0; nt < 4; nt++)
                    #pragma unroll
                    for (int mt = 0; mt < 2; mt++)
                        mma_f16(accB[mt][nt], afr[mt][0], afr[mt][1], afr[mt][2], afr[mt][3],
                                bfr[8 + nt][0], bfr[8 + nt][1]);
            }
        }
    }

    // ---- gate math + in-place update ----
    #pragma unroll
    for (int mt = 0; mt < 2; mt++)
        #pragma unroll
        for (int nt = 0; nt < 4; nt++) {
            int cb = wn * 32 + nt * 8 + tin * 2;
            #pragma unroll
            for (int half_ = 0; half_ < 2; half_++) {
                int r = wm * 32 + mt * 16 + gid + half_ * 8;
                int e = e0 + r;
                if (e < E) {
                    int i0 = half_ * 2;
                    float2 ho = *(const float2*)&h[e * D + cb];
                    float z0 = 1.f / (1.f + expf(-(acc1[mt][nt][i0]         + s_bz[cb])));
                    float z1 = 1.f / (1.f + expf(-(acc1[mt][nt][i0 + 1]     + s_bz[cb + 1])));
                    float r0 = 1.f / (1.f + expf(-(acc1[mt][nt + 4][i0]     + s_br[cb])));
                    float r1 = 1.f / (1.f + expf(-(acc1[mt][nt + 4][i0 + 1] + s_br[cb + 1])));
                    float h0 = tanhf(accA[mt][nt][i0]     + s_bah[cb]     + r0 * (accB[mt][nt][i0]     + s_bbh[cb]));
                    float h1 = tanhf(accA[mt][nt][i0 + 1] + s_bah[cb + 1] + r1 * (accB[mt][nt][i0 + 1] + s_bbh[cb + 1]));
                    float2 o;
                    o.x = z0 * ho.x + (1.f - z0) * h0;
                    o.y = z1 * ho.y + (1.f - z1) * h1;
                    *(float2*)&h[e * D + cb] = o;
                }
            }
        }
}

// ---------------- graph segment-sum (sorted graph ids) ----------------
#define GSROWS 512
__global__ __launch_bounds__(128) void graph_sum_kernel(
    const float* __restrict__ link, const int* __restrict__ gid,
    float* __restrict__ gs, int E)
{
    int tid = threadIdx.x;
    int r0 = blockIdx.x * GSROWS;
    if (r0 >= E) return;
    int r1 = min(r0 + GSROWS, E);
    float acc = 0.f;
    int cur = gid[r0];
    for (int r = r0; r < r1; r++) {
        int g = gid[r];
        if (g != cur) {
            atomicAdd(&gs[cur * D + tid], acc);
            acc = 0.f;
            cur = g;
        }
        acc += link[r * D + tid];
    }
    atomicAdd(&gs[cur * D + tid], acc);
}

// ---------------- readout MLP ----------------
__global__ __launch_bounds__(256) void readout_kernel(
    const float* __restrict__ gs,
    const float* __restrict__ rW1, const float* __restrict__ rb1,
    const float* __restrict__ rW2, const float* __restrict__ rb2,
    const float* __restrict__ rW3, const float* __restrict__ rb3,
    float* __restrict__ out)
{
    __shared__ float s_in[D];
    __shared__ float s_r1[HH];
    __shared__ float s_r2[HH];
    const int g = blockIdx.x;
    const int t = threadIdx.x;

    if (t < D) s_in[t] = gs[g * D + t];
    __syncthreads();

    float a = rb1[t];
    #pragma unroll 4
    for (int k = 0; k < D; k++) a = fmaf(s_in[k], rW1[k * HH + t], a);
    s_r1[t] = fmaxf(a, 0.f);
    __syncthreads();

    float b = rb2[t];
    #pragma unroll 4
    for (int k = 0; k < HH; k++) b = fmaf(s_r1[k], rW2[k * HH + t], b);
    s_r2[t] = fmaxf(b, 0.f) * rW3[t];
    __syncthreads();

    for (int s = 128; s > 0; s >>= 1) {
        if (t < s) s_r2[t] += s_r2[t + s];
        __syncthreads();
    }
    if (t == 0) out[g] = s_r2[0] + rb3[0];
}

// ---------------- launch ----------------
extern "C" void kernel_launch(void* const* d_in, const int* in_sizes, int n_in,
                              void* d_out, int out_size)
{
    const float* link0 = (const float*)d_in[0];
    const int*   sf    = (const int*)  d_in[1];
    const int*   ss    = (const int*)  d_in[2];
    const int*   gid   = (const int*)  d_in[3];
    const float* mW1 = (const float*)d_in[5];
    const float* mb1 = (const float*)d_in[6];
    const float* mW2 = (const float*)d_in[7];
    const float* mb2 = (const float*)d_in[8];
    const float* gk  = (const float*)d_in[9];
    const float* gr  = (const float*)d_in[10];
    const float* gb  = (const float*)d_in[11];
    const float* rW1 = (const float*)d_in[12];
    const float* rb1 = (const float*)d_in[13];
    const float* rW2 = (const float*)d_in[14];
    const float* rb2 = (const float*)d_in[15];
    const float* rW3 = (const float*)d_in[16];
    const float* rb3 = (const float*)d_in[17];
    float* out = (float*)d_out;

    const int M = in_sizes[1];
    const int E = in_sizes[3] <= EMAX ? in_sizes[3] : EMAX;

    float *link, *edges, *gs;
    __half *w1h, *w2h, *wgh;
    cudaGetSymbolAddress((void**)&link,  g_link);
    cudaGetSymbolAddress((void**)&edges, g_edges);
    cudaGetSymbolAddress((void**)&gs,    g_gs);
    cudaGetSymbolAddress((void**)&w1h,   g_w1h);
    cudaGetSymbolAddress((void**)&w2h,   g_w2h);
    cudaGetSymbolAddress((void**)&wgh,   g_wgh);

    cudaFuncSetAttribute(msg_mma_kernel, cudaFuncAttributeMaxDynamicSharedMemorySize, MSG_SMEM);
    cudaFuncSetAttribute(gru_mma_kernel, cudaFuncAttributeMaxDynamicSharedMemorySize, GRU_SMEM);

    const int n4 = E * (D / 4);
    copy_kernel<<<(n4 + 255) / 256, 256>>>((float4*)link, (const float4*)link0, n4);
    prep_all<<<768, 256>>>(mW1, mW2, gk, gr, w1h, w2h, wgh);

    const int mblocks = (M + 127) / 128;
    const int gblocks = (E + 63) / 64;
    for (int t = 0; t < TT; t++) {
        zero_kernel<<<(n4 + 255) / 256, 256>>>((float4*)edges, n4);
        msg_mma_kernel<<<mblocks, 512, MSG_SMEM>>>(link, sf, ss, w1h, mb1, w2h, mb2, edges, M);
        gru_mma_kernel<<<gblocks, 256, GRU_SMEM>>>(edges, link, wgh, gb, E);
    }

    const int gs4 = GG * D / 4;
    zero_kernel<<<(gs4 + 255) / 256, 256>>>((float4*)gs, gs4);
    graph_sum_kernel<<<(E + GSROWS - 1) / GSROWS, 128>>>(link, gid, gs, E);
    readout_kernel<<<GG, 256>>>(gs, rW1, rb1, rW2, rb2, rW3, rb3, out);
}

// round 9
// speedup vs baseline: 3.9611x; 1.0523x over previous
#include <cuda_runtime.h>
#include <cuda_fp16.h>
#include <math.h>
#include <stdint.h>

#define D    128
#define HH   256
#define TT   3
#define GG   64
#define EMAX 100000

#define XSU  132   // u32 stride of X/XH rows (264 halves)
#define WRU  36    // u32 stride of W chunk rows (64 halves + pad)

// ---------------- device scratch (no allocations allowed) ----------------
__device__ float  g_link [EMAX * D];
__device__ float  g_edges[EMAX * D];
__device__ float  g_gs   [GG * D];
__device__ __half g_w1h  [256 * 256];   // mW1^T  [n][k] half
__device__ __half g_w2h  [128 * 256];   // mW2^T  [n][k] half
__device__ __half g_wgh  [384 * 256];   // GRU weights^T [n=384][k=256] half

// ---------------- PTX helpers ----------------
__device__ __forceinline__ uint32_t smem_u32(const void* p) {
    uint32_t a;
    asm("{ .reg .u64 t; cvta.to.shared.u64 t, %1; cvt.u32.u64 %0, t; }" : "=r"(a) : "l"(p));
    return a;
}
__device__ __forceinline__ uint32_t packh2(float a, float b) {
    __half2 h = __floats2half2_rn(a, b);
    return *(uint32_t*)&h;
}
#define CP16(dst, src) \
    asm volatile("cp.async.ca.shared.global [%0], [%1], 16;" :: "r"(dst), "l"(src) : "memory")
#define CP_COMMIT() asm volatile("cp.async.commit_group;" ::: "memory")
#define CP_WAIT0()  asm volatile("cp.async.wait_group 0;" ::: "memory")
#define REDV2(addr, a, b) \
    asm volatile("red.global.add.v2.f32 [%0], {%1, %2};" :: "l"(addr), "f"(a), "f"(b) : "memory")
#define LDSM4(r0, r1, r2, r3, addr) \
    asm volatile("ldmatrix.sync.aligned.m8n8.x4.shared.b16 {%0,%1,%2,%3}, [%4];" \
        : "=r"(r0), "=r"(r1), "=r"(r2), "=r"(r3) : "r"(addr))

__device__ __forceinline__ void mma_f16(float d[4],
                                        uint32_t a0, uint32_t a1, uint32_t a2, uint32_t a3,
                                        uint32_t b0, uint32_t b1) {
    asm volatile(
        "mma.sync.aligned.m16n8k16.row.col.f32.f16.f16.f32 "
        "{%0,%1,%2,%3}, {%4,%5,%6,%7}, {%8,%9}, {%0,%1,%2,%3};\n"
        : "+f"(d[0]), "+f"(d[1]), "+f"(d[2]), "+f"(d[3])
        : "r"(a0), "r"(a1), "r"(a2), "r"(a3), "r"(b0), "r"(b1));
}

// ---------------- utility kernels ----------------
__global__ void zero_kernel(float4* p, int n4) {
    int i = blockIdx.x * blockDim.x + threadIdx.x;
    if (i < n4) p[i] = make_float4(0.f, 0.f, 0.f, 0.f);
}
__global__ void copy_kernel(float4* dst, const float4* __restrict__ src, int n4) {
    int i = blockIdx.x * blockDim.x + threadIdx.x;
    if (i < n4) dst[i] = src[i];
}
__global__ void prep_all(const float* __restrict__ mW1, const float* __restrict__ mW2,
                         const float* __restrict__ gk,  const float* __restrict__ gr,
                         __half* __restrict__ w1h, __half* __restrict__ w2h,
                         __half* __restrict__ wgh) {
    int i = blockIdx.x * blockDim.x + threadIdx.x;
    if (i < 65536) {
        int k = i >> 8, n = i & 255;
        w1h[n * 256 + k] = __float2half_rn(mW1[k * 256 + n]);
    } else if (i < 98304) {
        int j = i - 65536;
        int k = j >> 7, n = j & 127;
        w2h[n * 256 + k] = __float2half_rn(mW2[k * 128 + n]);
    } else if (i < 196608) {
        int j = i - 98304;
        int n = j >> 8, k = j & 255;
        float v = (k < 128) ? gk[k * 384 + n] : gr[(k - 128) * 384 + n];
        wgh[n * 256 + k] = __float2half_rn(v);
    }
}

// =====================================================================
// message MLP: 256 threads, 64-msg tile, 2 CTAs/SM (phase overlap)
// smem: hdr 2048 | X [64][264h] 33792 | W 2x[256][144B] 73728 = 109568
// =====================================================================
#define MSG_SMEM (2048 + 64 * XSU * 4 + 2 * 256 * WRU * 4)
__global__ __launch_bounds__(256, 2) void msg_mma_kernel(
    const float*  __restrict__ link,
    const int*    __restrict__ sf,
    const int*    __restrict__ ss,
    const __half* __restrict__ w1h, const float* __restrict__ b1,
    const __half* __restrict__ w2h, const float* __restrict__ b2,
    float*        __restrict__ edges, int M)
{
    extern __shared__ __align__(16) char smem[];
    int*      s_sf = (int*)smem;                    // [64]
    int*      s_ss = (int*)(smem + 256);            // [64]
    float*    s_b1 = (float*)(smem + 512);          // [256]
    float*    s_b2 = (float*)(smem + 1536);         // [128]
    uint32_t* Xs   = (uint32_t*)(smem + 2048);
    const uint32_t u_base = smem_u32(smem);
    const uint32_t u_X = u_base + 2048;
    const uint32_t u_W = u_base + 2048 + 64 * XSU * 4;

    const int tid  = threadIdx.x;
    const int lane = tid & 31;
    const int gid  = lane >> 2, tin = lane & 3;
    const int lrow = (lane & 7) + ((lane >> 3) & 1) * 8;
    const int lcol = (lane >> 4) * 4;
    const int wid  = tid >> 5;
    const int wm   = wid & 1;       // 32-row half
    const int wn   = wid >> 1;      // 0..3
    const int m0   = blockIdx.x * 64;

    if (tid < 64) {
        int mg = m0 + tid;
        s_sf[tid] = (mg < M) ? sf[mg] : -1;
        s_ss[tid] = (mg < M) ? ss[mg] : -1;
    }
    if (tid < 128) { s_b1[tid] = b1[tid]; s_b1[128 + tid] = b1[128 + tid]; s_b2[tid] = b2[tid]; }
    __syncthreads();

    // ---- gather X[64][256] -> half ----
    const float4* link4 = (const float4*)link;
    #pragma unroll
    for (int it = 0; it < 16; it++) {
        int idx = it * 256 + tid;           // 4096 = 64 rows x 64 f4
        int m = idx >> 6, q = idx & 63;
        int e = (q < 32) ? s_sf[m] : s_ss[m];
        float4 v = make_float4(0.f, 0.f, 0.f, 0.f);
        if (e >= 0) v = link4[e * 32 + (q & 31)];
        uint2 t;
        t.x = packh2(v.x, v.y);
        t.y = packh2(v.z, v.w);
        *(uint2*)&Xs[m * XSU + q * 2] = t;
    }

    // 64-k chunk loaders
    auto ldW1 = [&](int c, int buf) {       // 256 rows x 8 segs -> 8/thread
        #pragma unroll
        for (int i = 0; i < 8; i++) {
            int idx = i * 256 + tid;
            int row = idx >> 3, seg = idx & 7;
            uint32_t dst = u_W + (uint32_t)buf * (256 * WRU * 4)
                         + (uint32_t)(row * WRU * 4 + seg * 16);
            CP16(dst, (const char*)w1h + (row * 256 + c * 64 + seg * 8) * 2);
        }
    };
    auto ldW2 = [&](int c, int buf) {       // 128 rows x 8 segs -> 4/thread
        #pragma unroll
        for (int i = 0; i < 4; i++) {
            int idx = i * 256 + tid;
            int row = idx >> 3, seg = idx & 7;
            uint32_t dst = u_W + (uint32_t)buf * (256 * WRU * 4)
                         + (uint32_t)(row * WRU * 4 + seg * 16);
            CP16(dst, (const char*)w2h + (row * 256 + c * 64 + seg * 8) * 2);
        }
    };

    const uint32_t u_A = u_X + (uint32_t)((wm * 32 + lrow) * XSU + lcol) * 4;

    // ================= GEMM1: H1[64,256] = X @ W1 (warp: 32 rows x 64 cols) ====
    float acc[2][8][4];
    #pragma unroll
    for (int a = 0; a < 2; a++)
        #pragma unroll
        for (int b = 0; b < 8; b++)
            #pragma unroll
            for (int i = 0; i < 4; i++) acc[a][b][i] = 0.f;

    ldW1(0, 0); CP_COMMIT();
    for (int c = 0; c < 4; c++) {
        CP_WAIT0(); __syncthreads();
        if (c < 3) { ldW1(c + 1, (c + 1) & 1); CP_COMMIT(); }
        else       { ldW2(0, 0); CP_COMMIT(); }
        const uint32_t u_Wc = u_W + (uint32_t)(c & 1) * (256 * WRU * 4);
        #pragma unroll
        for (int ks = 0; ks < 4; ks++) {
            const int ku = c * 32 + ks * 8;
            const int kl = ks * 8;
            uint32_t afr[2][4];
            #pragma unroll
            for (int mt = 0; mt < 2; mt++)
                LDSM4(afr[mt][0], afr[mt][1], afr[mt][2], afr[mt][3],
                      u_A + (uint32_t)(mt * 16 * XSU + ku) * 4);
            uint32_t bfr[8][2];
            #pragma unroll
            for (int np = 0; np < 4; np++) {
                int n0 = wn * 64 + np * 16;
                uint32_t r0, r1, r2, r3;
                LDSM4(r0, r1, r2, r3,
                      u_Wc + (uint32_t)((n0 + lrow) * WRU + kl + lcol) * 4);
                bfr[2 * np][0] = r0; bfr[2 * np + 1][0] = r1;
                bfr[2 * np][1] = r2; bfr[2 * np + 1][1] = r3;
            }
            #pragma unroll
            for (int nt = 0; nt < 8; nt++)
                #pragma unroll
                for (int mt = 0; mt < 2; mt++)
                    mma_f16(acc[mt][nt], afr[mt][0], afr[mt][1], afr[mt][2], afr[mt][3],
                            bfr[nt][0], bfr[nt][1]);
        }
    }
    __syncthreads();

    // ---- epilogue1: H1 = half(relu(acc + b1)) back into Xs ----
    #pragma unroll
    for (int mt = 0; mt < 2; mt++)
        #pragma unroll
        for (int nt = 0; nt < 8; nt++) {
            int r  = wm * 32 + mt * 16 + gid;
            int cb = wn * 64 + nt * 8 + tin * 2;
            int cu = cb >> 1;
            Xs[r * XSU + cu]       = packh2(fmaxf(acc[mt][nt][0] + s_b1[cb], 0.f),
                                            fmaxf(acc[mt][nt][1] + s_b1[cb + 1], 0.f));
            Xs[(r + 8) * XSU + cu] = packh2(fmaxf(acc[mt][nt][2] + s_b1[cb], 0.f),
                                            fmaxf(acc[mt][nt][3] + s_b1[cb + 1], 0.f));
        }
    __syncthreads();

    // ================= GEMM2: OUT[64,128] = H1 @ W2 (warp: 32 rows x 32 cols) ==
    float ac2[2][4][4];
    #pragma unroll
    for (int a = 0; a < 2; a++)
        #pragma unroll
        for (int b = 0; b < 4; b++)
            #pragma unroll
            for (int i = 0; i < 4; i++) ac2[a][b][i] = 0.f;

    for (int c = 0; c < 4; c++) {
        CP_WAIT0(); __syncthreads();
        if (c < 3) { ldW2(c + 1, (c + 1) & 1); CP_COMMIT(); }
        const uint32_t u_Wc = u_W + (uint32_t)(c & 1) * (256 * WRU * 4);
        #pragma unroll
        for (int ks = 0; ks < 4; ks++) {
            const int ku = c * 32 + ks * 8;
            const int kl = ks * 8;
            uint32_t afr[2][4];
            #pragma unroll
            for (int mt = 0; mt < 2; mt++)
                LDSM4(afr[mt][0], afr[mt][1], afr[mt][2], afr[mt][3],
                      u_A + (uint32_t)(mt * 16 * XSU + ku) * 4);
            uint32_t bfr[4][2];
            #pragma unroll
            for (int np = 0; np < 2; np++) {
                int n0 = wn * 32 + np * 16;
                uint32_t r0, r1, r2, r3;
                LDSM4(r0, r1, r2, r3,
                      u_Wc + (uint32_t)((n0 + lrow) * WRU + kl + lcol) * 4);
                bfr[2 * np][0] = r0; bfr[2 * np + 1][0] = r1;
                bfr[2 * np][1] = r2; bfr[2 * np + 1][1] = r3;
            }
            #pragma unroll
            for (int nt = 0; nt < 4; nt++)
                #pragma unroll
                for (int mt = 0; mt < 2; mt++)
                    mma_f16(ac2[mt][nt], afr[mt][0], afr[mt][1], afr[mt][2], afr[mt][3],
                            bfr[nt][0], bfr[nt][1]);
        }
    }

    // ---- epilogue2: relu + bias + vector red scatter ----
    #pragma unroll
    for (int mt = 0; mt < 2; mt++)
        #pragma unroll
        for (int nt = 0; nt < 4; nt++) {
            int r  = wm * 32 + mt * 16 + gid;
            int cb = wn * 32 + nt * 8 + tin * 2;
            int e0 = s_ss[r], e1 = s_ss[r + 8];
            if (e0 >= 0) {
                float v0 = fmaxf(ac2[mt][nt][0] + s_b2[cb], 0.f);
                float v1 = fmaxf(ac2[mt][nt][1] + s_b2[cb + 1], 0.f);
                REDV2(&edges[e0 * D + cb], v0, v1);
            }
            if (e1 >= 0) {
                float v0 = fmaxf(ac2[mt][nt][2] + s_b2[cb], 0.f);
                float v1 = fmaxf(ac2[mt][nt][3] + s_b2[cb + 1], 0.f);
                REDV2(&edges[e1 * D + cb], v0, v1);
            }
        }
}

// =====================================================================
// GRU: 256 threads, 64-row tile, single merged k-loop (unchanged from R8)
// =====================================================================
#define GRU_SMEM (2048 + 64 * XSU * 4 + 2 * 384 * WRU * 4)
__global__ __launch_bounds__(256, 1) void gru_mma_kernel(
    const float*  __restrict__ x,
    float*        __restrict__ h,
    const __half* __restrict__ wgh,
    const float*  __restrict__ gbias,
    int E)
{
    extern __shared__ __align__(16) char smem[];
    float*    s_bz  = (float*)smem;
    float*    s_br  = (float*)(smem + 512);
    float*    s_bah = (float*)(smem + 1024);
    float*    s_bbh = (float*)(smem + 1536);
    uint32_t* XH    = (uint32_t*)(smem + 2048);
    const uint32_t u_base = smem_u32(smem);
    const uint32_t u_X = u_base + 2048;
    const uint32_t u_W = u_base + 2048 + 64 * XSU * 4;

    const int tid  = threadIdx.x;
    const int lane = tid & 31;
    const int gid  = lane >> 2, tin = lane & 3;
    const int lrow = (lane & 7) + ((lane >> 3) & 1) * 8;
    const int lcol = (lane >> 4) * 4;
    const int wid  = tid >> 5;
    const int wm   = wid & 1;
    const int wn   = wid >> 1;
    const int e0   = blockIdx.x * 64;

    if (tid < 128) {
        s_bz[tid]  = gbias[tid]       + gbias[384 + tid];
        s_br[tid]  = gbias[128 + tid] + gbias[512 + tid];
        s_bah[tid] = gbias[256 + tid];
        s_bbh[tid] = gbias[640 + tid];
    }

    const float4* xe4 = (const float4*)x;
    const float4* ln4 = (const float4*)h;
    #pragma unroll
    for (int it = 0; it < 16; it++) {
        int idx = it * 256 + tid;
        int m = idx >> 6, q = idx & 63;
        int e = e0 + m;
        float4 v = make_float4(0.f, 0.f, 0.f, 0.f);
        if (e < E) v = (q < 32) ? xe4[e * 32 + q] : ln4[e * 32 + (q - 32)];
        uint2 t;
        t.x = packh2(v.x, v.y);
        t.y = packh2(v.z, v.w);
        *(uint2*)&XH[m * XSU + q * 2] = t;
    }

    auto ldP = [&](int c, int buf) {
        #pragma unroll
        for (int i = 0; i < 12; i++) {
            int idx = i * 256 + tid;
            int row = idx >> 3, seg = idx & 7;
            uint32_t dst = u_W + (uint32_t)buf * (384 * WRU * 4)
                         + (uint32_t)(row * WRU * 4 + seg * 16);
            CP16(dst, (const char*)wgh + (row * 256 + c * 64 + seg * 8) * 2);
        }
    };

    const uint32_t u_A = u_X + (uint32_t)((wm * 32 + lrow) * XSU + lcol) * 4;

    float acc1[2][8][4], accA[2][4][4], accB[2][4][4];
    #pragma unroll
    for (int a = 0; a < 2; a++) {
        #pragma unroll
        for (int b = 0; b < 8; b++)
            #pragma unroll
            for (int i = 0; i < 4; i++) acc1[a][b][i] = 0.f;
        #pragma unroll
        for (int b = 0; b < 4; b++)
            #pragma unroll
            for (int i = 0; i < 4; i++) { accA[a][b][i] = 0.f; accB[a][b][i] = 0.f; }
    }

    ldP(0, 0); CP_COMMIT();
    for (int c = 0; c < 4; c++) {
        CP_WAIT0(); __syncthreads();
        if (c < 3) { ldP(c + 1, (c + 1) & 1); CP_COMMIT(); }
        const uint32_t u_Wc = u_W + (uint32_t)(c & 1) * (384 * WRU * 4);
        #pragma unroll
        for (int ks = 0; ks < 4; ks++) {
            const int ku = c * 32 + ks * 8;
            const int kl = ks * 8;
            uint32_t afr[2][4];
            #pragma unroll
            for (int mt = 0; mt < 2; mt++)
                LDSM4(afr[mt][0], afr[mt][1], afr[mt][2], afr[mt][3],
                      u_A + (uint32_t)(mt * 16 * XSU + ku) * 4);
            uint32_t bfr[12][2];
            #pragma unroll
            for (int jp = 0; jp < 4; jp++) {
                int n0 = (jp < 2) ? (wn * 32 + jp * 16)
                                  : (128 + wn * 32 + (jp - 2) * 16);
                uint32_t r0, r1, r2, r3;
                LDSM4(r0, r1, r2, r3,
                      u_Wc + (uint32_t)((n0 + lrow) * WRU + kl + lcol) * 4);
                bfr[2 * jp][0] = r0; bfr[2 * jp + 1][0] = r1;
                bfr[2 * jp][1] = r2; bfr[2 * jp + 1][1] = r3;
            }
            #pragma unroll
            for (int np = 0; np < 2; np++) {
                int n0 = 256 + wn * 32 + np * 16;
                uint32_t r0, r1, r2, r3;
                LDSM4(r0, r1, r2, r3,
                      u_Wc + (uint32_t)((n0 + lrow) * WRU + kl + lcol) * 4);
                bfr[8 + 2 * np][0] = r0; bfr[8 + 2 * np + 1][0] = r1;
                bfr[8 + 2 * np][1] = r2; bfr[8 + 2 * np + 1][1] = r3;
            }
            #pragma unroll
            for (int j = 0; j < 8; j++)
                #pragma unroll
                for (int mt = 0; mt < 2; mt++)
                    mma_f16(acc1[mt][j], afr[mt][0], afr[mt][1], afr[mt][2], afr[mt][3],
                            bfr[j][0], bfr[j][1]);
            if (c < 2) {
                #pragma unroll
                for (int nt = 0; nt < 4; nt++)
                    #pragma unroll
                    for (int mt = 0; mt < 2; mt++)
                        mma_f16(accA[mt][nt], afr[mt][0], afr[mt][1], afr[mt][2], afr[mt][3],
                                bfr[8 + nt][0], bfr[8 + nt][1]);
            } else {
                #pragma unroll
                for (int nt = 0; nt < 4; nt++)
                    #pragma unroll
                    for (int mt = 0; mt < 2; mt++)
                        mma_f16(accB[mt][nt], afr[mt][0], afr[mt][1], afr[mt][2], afr[mt][3],
                                bfr[8 + nt][0], bfr[8 + nt][1]);
            }
        }
    }

    // ---- gate math + in-place update ----
    #pragma unroll
    for (int mt = 0; mt < 2; mt++)
        #pragma unroll
        for (int nt = 0; nt < 4; nt++) {
            int cb = wn * 32 + nt * 8 + tin * 2;
            #pragma unroll
            for (int half_ = 0; half_ < 2; half_++) {
                int r = wm * 32 + mt * 16 + gid + half_ * 8;
                int e = e0 + r;
                if (e < E) {
                    int i0 = half_ * 2;
                    float2 ho = *(const float2*)&h[e * D + cb];
                    float z0 = 1.f / (1.f + expf(-(acc1[mt][nt][i0]         + s_bz[cb])));
                    float z1 = 1.f / (1.f + expf(-(acc1[mt][nt][i0 + 1]     + s_bz[cb + 1])));
                    float r0 = 1.f / (1.f + expf(-(acc1[mt][nt + 4][i0]     + s_br[cb])));
                    float r1 = 1.f / (1.f + expf(-(acc1[mt][nt + 4][i0 + 1] + s_br[cb + 1])));
                    float h0 = tanhf(accA[mt][nt][i0]     + s_bah[cb]     + r0 * (accB[mt][nt][i0]     + s_bbh[cb]));
                    float h1 = tanhf(accA[mt][nt][i0 + 1] + s_bah[cb + 1] + r1 * (accB[mt][nt][i0 + 1] + s_bbh[cb + 1]));
                    float2 o;
                    o.x = z0 * ho.x + (1.f - z0) * h0;
                    o.y = z1 * ho.y + (1.f - z1) * h1;
                    *(float2*)&h[e * D + cb] = o;
                }
            }
        }
}

// ---------------- graph segment-sum (sorted graph ids) ----------------
#define GSROWS 512
__global__ __launch_bounds__(128) void graph_sum_kernel(
    const float* __restrict__ link, const int* __restrict__ gid,
    float* __restrict__ gs, int E)
{
    int tid = threadIdx.x;
    int r0 = blockIdx.x * GSROWS;
    if (r0 >= E) return;
    int r1 = min(r0 + GSROWS, E);
    float acc = 0.f;
    int cur = gid[r0];
    for (int r = r0; r < r1; r++) {
        int g = gid[r];
        if (g != cur) {
            atomicAdd(&gs[cur * D + tid], acc);
            acc = 0.f;
            cur = g;
        }
        acc += link[r * D + tid];
    }
    atomicAdd(&gs[cur * D + tid], acc);
}

// ---------------- readout MLP ----------------
__global__ __launch_bounds__(256) void readout_kernel(
    const float* __restrict__ gs,
    const float* __restrict__ rW1, const float* __restrict__ rb1,
    const float* __restrict__ rW2, const float* __restrict__ rb2,
    const float* __restrict__ rW3, const float* __restrict__ rb3,
    float* __restrict__ out)
{
    __shared__ float s_in[D];
    __shared__ float s_r1[HH];
    __shared__ float s_r2[HH];
    const int g = blockIdx.x;
    const int t = threadIdx.x;

    if (t < D) s_in[t] = gs[g * D + t];
    __syncthreads();

    float a = rb1[t];
    #pragma unroll 4
    for (int k = 0; k < D; k++) a = fmaf(s_in[k], rW1[k * HH + t], a);
    s_r1[t] = fmaxf(a, 0.f);
    __syncthreads();

    float b = rb2[t];
    #pragma unroll 4
    for (int k = 0; k < HH; k++) b = fmaf(s_r1[k], rW2[k * HH + t], b);
    s_r2[t] = fmaxf(b, 0.f) * rW3[t];
    __syncthreads();

    for (int s = 128; s > 0; s >>= 1) {
        if (t < s) s_r2[t] += s_r2[t + s];
        __syncthreads();
    }
    if (t == 0) out[g] = s_r2[0] + rb3[0];
}

// ---------------- launch ----------------
extern "C" void kernel_launch(void* const* d_in, const int* in_sizes, int n_in,
                              void* d_out, int out_size)
{
    const float* link0 = (const float*)d_in[0];
    const int*   sf    = (const int*)  d_in[1];
    const int*   ss    = (const int*)  d_in[2];
    const int*   gid   = (const int*)  d_in[3];
    const float* mW1 = (const float*)d_in[5];
    const float* mb1 = (const float*)d_in[6];
    const float* mW2 = (const float*)d_in[7];
    const float* mb2 = (const float*)d_in[8];
    const float* gk  = (const float*)d_in[9];
    const float* gr  = (const float*)d_in[10];
    const float* gb  = (const float*)d_in[11];
    const float* rW1 = (const float*)d_in[12];
    const float* rb1 = (const float*)d_in[13];
    const float* rW2 = (const float*)d_in[14];
    const float* rb2 = (const float*)d_in[15];
    const float* rW3 = (const float*)d_in[16];
    const float* rb3 = (const float*)d_in[17];
    float* out = (float*)d_out;

    const int M = in_sizes[1];
    const int E = in_sizes[3] <= EMAX ? in_sizes[3] : EMAX;

    float *link, *edges, *gs;
    __half *w1h, *w2h, *wgh;
    cudaGetSymbolAddress((void**)&link,  g_link);
    cudaGetSymbolAddress((void**)&edges, g_edges);
    cudaGetSymbolAddress((void**)&gs,    g_gs);
    cudaGetSymbolAddress((void**)&w1h,   g_w1h);
    cudaGetSymbolAddress((void**)&w2h,   g_w2h);
    cudaGetSymbolAddress((void**)&wgh,   g_wgh);

    cudaFuncSetAttribute(msg_mma_kernel, cudaFuncAttributeMaxDynamicSharedMemorySize, MSG_SMEM);
    cudaFuncSetAttribute(gru_mma_kernel, cudaFuncAttributeMaxDynamicSharedMemorySize, GRU_SMEM);

    const int n4 = E * (D / 4);
    copy_kernel<<<(n4 + 255) / 256, 256>>>((float4*)link, (const float4*)link0, n4);
    prep_all<<<768, 256>>>(mW1, mW2, gk, gr, w1h, w2h, wgh);

    const int mblocks = (M + 63) / 64;
    const int gblocks = (E + 63) / 64;
    for (int t = 0; t < TT; t++) {
        zero_kernel<<<(n4 + 255) / 256, 256>>>((float4*)edges, n4);
        msg_mma_kernel<<<mblocks, 256, MSG_SMEM>>>(link, sf, ss, w1h, mb1, w2h, mb2, edges, M);
        gru_mma_kernel<<<gblocks, 256, GRU_SMEM>>>(edges, link, wgh, gb, E);
    }

    const int gs4 = GG * D / 4;
    zero_kernel<<<(gs4 + 255) / 256, 256>>>((float4*)gs, gs4);
    graph_sum_kernel<<<(E + GSROWS - 1) / GSROWS, 128>>>(link, gid, gs, E);
    readout_kernel<<<GG, 256>>>(gs, rW1, rb1, rW2, rb2, rW3, rb3, out);
}

// round 10
// speedup vs baseline: 4.4443x; 1.1220x over previous
#include <cuda_runtime.h>
#include <cuda_fp16.h>
#include <math.h>
#include <stdint.h>

#define D    128
#define HH   256
#define TT   3
#define GG   64
#define EMAX 100000

#define XSU  132   // u32 stride of X/XH rows (264 halves)
#define WRU  36    // u32 stride of W chunk rows (64 halves + pad)

// ---------------- device scratch (no allocations allowed) ----------------
__device__ float  g_link [EMAX * D];
__device__ float  g_edges[EMAX * D];
__device__ float  g_gs   [GG * D];
__device__ __half g_w1h  [256 * 256];   // mW1^T  [n][k] half
__device__ __half g_w2h  [128 * 256];   // mW2^T  [n][k] half
__device__ __half g_wgh  [384 * 256];   // GRU weights^T [n=384][k=256] half

// ---------------- PTX helpers ----------------
__device__ __forceinline__ uint32_t smem_u32(const void* p) {
    uint32_t a;
    asm("{ .reg .u64 t; cvta.to.shared.u64 t, %1; cvt.u32.u64 %0, t; }" : "=r"(a) : "l"(p));
    return a;
}
__device__ __forceinline__ uint32_t packh2(float a, float b) {
    __half2 h = __floats2half2_rn(a, b);
    return *(uint32_t*)&h;
}
#define CP16(dst, src) \
    asm volatile("cp.async.ca.shared.global [%0], [%1], 16;" :: "r"(dst), "l"(src) : "memory")
#define CP_COMMIT() asm volatile("cp.async.commit_group;" ::: "memory")
#define CP_WAIT0()  asm volatile("cp.async.wait_group 0;" ::: "memory")
#define REDV2(addr, a, b) \
    asm volatile("red.global.add.v2.f32 [%0], {%1, %2};" :: "l"(addr), "f"(a), "f"(b) : "memory")
#define LDSM4(r0, r1, r2, r3, addr) \
    asm volatile("ldmatrix.sync.aligned.m8n8.x4.shared.b16 {%0,%1,%2,%3}, [%4];" \
        : "=r"(r0), "=r"(r1), "=r"(r2), "=r"(r3) : "r"(addr))

__device__ __forceinline__ void mma_f16(float d[4],
                                        uint32_t a0, uint32_t a1, uint32_t a2, uint32_t a3,
                                        uint32_t b0, uint32_t b1) {
    asm volatile(
        "mma.sync.aligned.m16n8k16.row.col.f32.f16.f16.f32 "
        "{%0,%1,%2,%3}, {%4,%5,%6,%7}, {%8,%9}, {%0,%1,%2,%3};\n"
        : "+f"(d[0]), "+f"(d[1]), "+f"(d[2]), "+f"(d[3])
        : "r"(a0), "r"(a1), "r"(a2), "r"(a3), "r"(b0), "r"(b1));
}

// ---------------- utility kernels ----------------
__global__ void zero_kernel(float4* p, int n4) {
    int i = blockIdx.x * blockDim.x + threadIdx.x;
    if (i < n4) p[i] = make_float4(0.f, 0.f, 0.f, 0.f);
}
__global__ void copy_kernel(float4* dst, const float4* __restrict__ src, int n4) {
    int i = blockIdx.x * blockDim.x + threadIdx.x;
    if (i < n4) dst[i] = src[i];
}
__global__ void prep_all(const float* __restrict__ mW1, const float* __restrict__ mW2,
                         const float* __restrict__ gk,  const float* __restrict__ gr,
                         __half* __restrict__ w1h, __half* __restrict__ w2h,
                         __half* __restrict__ wgh) {
    int i = blockIdx.x * blockDim.x + threadIdx.x;
    if (i < 65536) {
        int k = i >> 8, n = i & 255;
        w1h[n * 256 + k] = __float2half_rn(mW1[k * 256 + n]);
    } else if (i < 98304) {
        int j = i - 65536;
        int k = j >> 7, n = j & 127;
        w2h[n * 256 + k] = __float2half_rn(mW2[k * 128 + n]);
    } else if (i < 196608) {
        int j = i - 98304;
        int n = j >> 8, k = j & 255;
        float v = (k < 128) ? gk[k * 384 + n] : gr[(k - 128) * 384 + n];
        wgh[n * 256 + k] = __float2half_rn(v);
    }
}

// =====================================================================
// message MLP: 256 threads, 64-msg tile, 2 CTAs/SM (unchanged from R9)
// =====================================================================
#define MSG_SMEM (2048 + 64 * XSU * 4 + 2 * 256 * WRU * 4)
__global__ __launch_bounds__(256, 2) void msg_mma_kernel(
    const float*  __restrict__ link,
    const int*    __restrict__ sf,
    const int*    __restrict__ ss,
    const __half* __restrict__ w1h, const float* __restrict__ b1,
    const __half* __restrict__ w2h, const float* __restrict__ b2,
    float*        __restrict__ edges, int M)
{
    extern __shared__ __align__(16) char smem[];
    int*      s_sf = (int*)smem;
    int*      s_ss = (int*)(smem + 256);
    float*    s_b1 = (float*)(smem + 512);
    float*    s_b2 = (float*)(smem + 1536);
    uint32_t* Xs   = (uint32_t*)(smem + 2048);
    const uint32_t u_base = smem_u32(smem);
    const uint32_t u_X = u_base + 2048;
    const uint32_t u_W = u_base + 2048 + 64 * XSU * 4;

    const int tid  = threadIdx.x;
    const int lane = tid & 31;
    const int gid  = lane >> 2, tin = lane & 3;
    const int lrow = (lane & 7) + ((lane >> 3) & 1) * 8;
    const int lcol = (lane >> 4) * 4;
    const int wid  = tid >> 5;
    const int wm   = wid & 1;
    const int wn   = wid >> 1;
    const int m0   = blockIdx.x * 64;

    if (tid < 64) {
        int mg = m0 + tid;
        s_sf[tid] = (mg < M) ? sf[mg] : -1;
        s_ss[tid] = (mg < M) ? ss[mg] : -1;
    }
    if (tid < 128) { s_b1[tid] = b1[tid]; s_b1[128 + tid] = b1[128 + tid]; s_b2[tid] = b2[tid]; }
    __syncthreads();

    const float4* link4 = (const float4*)link;
    #pragma unroll
    for (int it = 0; it < 16; it++) {
        int idx = it * 256 + tid;
        int m = idx >> 6, q = idx & 63;
        int e = (q < 32) ? s_sf[m] : s_ss[m];
        float4 v = make_float4(0.f, 0.f, 0.f, 0.f);
        if (e >= 0) v = link4[e * 32 + (q & 31)];
        uint2 t;
        t.x = packh2(v.x, v.y);
        t.y = packh2(v.z, v.w);
        *(uint2*)&Xs[m * XSU + q * 2] = t;
    }

    auto ldW1 = [&](int c, int buf) {
        #pragma unroll
        for (int i = 0; i < 8; i++) {
            int idx = i * 256 + tid;
            int row = idx >> 3, seg = idx & 7;
            uint32_t dst = u_W + (uint32_t)buf * (256 * WRU * 4)
                         + (uint32_t)(row * WRU * 4 + seg * 16);
            CP16(dst, (const char*)w1h + (row * 256 + c * 64 + seg * 8) * 2);
        }
    };
    auto ldW2 = [&](int c, int buf) {
        #pragma unroll
        for (int i = 0; i < 4; i++) {
            int idx = i * 256 + tid;
            int row = idx >> 3, seg = idx & 7;
            uint32_t dst = u_W + (uint32_t)buf * (256 * WRU * 4)
                         + (uint32_t)(row * WRU * 4 + seg * 16);
            CP16(dst, (const char*)w2h + (row * 256 + c * 64 + seg * 8) * 2);
        }
    };

    const uint32_t u_A = u_X + (uint32_t)((wm * 32 + lrow) * XSU + lcol) * 4;

    // ================= GEMM1 =================
    float acc[2][8][4];
    #pragma unroll
    for (int a = 0; a < 2; a++)
        #pragma unroll
        for (int b = 0; b < 8; b++)
            #pragma unroll
            for (int i = 0; i < 4; i++) acc[a][b][i] = 0.f;

    ldW1(0, 0); CP_COMMIT();
    for (int c = 0; c < 4; c++) {
        CP_WAIT0(); __syncthreads();
        if (c < 3) { ldW1(c + 1, (c + 1) & 1); CP_COMMIT(); }
        else       { ldW2(0, 0); CP_COMMIT(); }
        const uint32_t u_Wc = u_W + (uint32_t)(c & 1) * (256 * WRU * 4);
        #pragma unroll
        for (int ks = 0; ks < 4; ks++) {
            const int ku = c * 32 + ks * 8;
            const int kl = ks * 8;
            uint32_t afr[2][4];
            #pragma unroll
            for (int mt = 0; mt < 2; mt++)
                LDSM4(afr[mt][0], afr[mt][1], afr[mt][2], afr[mt][3],
                      u_A + (uint32_t)(mt * 16 * XSU + ku) * 4);
            uint32_t bfr[8][2];
            #pragma unroll
            for (int np = 0; np < 4; np++) {
                int n0 = wn * 64 + np * 16;
                uint32_t r0, r1, r2, r3;
                LDSM4(r0, r1, r2, r3,
                      u_Wc + (uint32_t)((n0 + lrow) * WRU + kl + lcol) * 4);
                bfr[2 * np][0] = r0; bfr[2 * np + 1][0] = r1;
                bfr[2 * np][1] = r2; bfr[2 * np + 1][1] = r3;
            }
            #pragma unroll
            for (int nt = 0; nt < 8; nt++)
                #pragma unroll
                for (int mt = 0; mt < 2; mt++)
                    mma_f16(acc[mt][nt], afr[mt][0], afr[mt][1], afr[mt][2], afr[mt][3],
                            bfr[nt][0], bfr[nt][1]);
        }
    }
    __syncthreads();

    #pragma unroll
    for (int mt = 0; mt < 2; mt++)
        #pragma unroll
        for (int nt = 0; nt < 8; nt++) {
            int r  = wm * 32 + mt * 16 + gid;
            int cb = wn * 64 + nt * 8 + tin * 2;
            int cu = cb >> 1;
            Xs[r * XSU + cu]       = packh2(fmaxf(acc[mt][nt][0] + s_b1[cb], 0.f),
                                            fmaxf(acc[mt][nt][1] + s_b1[cb + 1], 0.f));
            Xs[(r + 8) * XSU + cu] = packh2(fmaxf(acc[mt][nt][2] + s_b1[cb], 0.f),
                                            fmaxf(acc[mt][nt][3] + s_b1[cb + 1], 0.f));
        }
    __syncthreads();

    // ================= GEMM2 =================
    float ac2[2][4][4];
    #pragma unroll
    for (int a = 0; a < 2; a++)
        #pragma unroll
        for (int b = 0; b < 4; b++)
            #pragma unroll
            for (int i = 0; i < 4; i++) ac2[a][b][i] = 0.f;

    for (int c = 0; c < 4; c++) {
        CP_WAIT0(); __syncthreads();
        if (c < 3) { ldW2(c + 1, (c + 1) & 1); CP_COMMIT(); }
        const uint32_t u_Wc = u_W + (uint32_t)(c & 1) * (256 * WRU * 4);
        #pragma unroll
        for (int ks = 0; ks < 4; ks++) {
            const int ku = c * 32 + ks * 8;
            const int kl = ks * 8;
            uint32_t afr[2][4];
            #pragma unroll
            for (int mt = 0; mt < 2; mt++)
                LDSM4(afr[mt][0], afr[mt][1], afr[mt][2], afr[mt][3],
                      u_A + (uint32_t)(mt * 16 * XSU + ku) * 4);
            uint32_t bfr[4][2];
            #pragma unroll
            for (int np = 0; np < 2; np++) {
                int n0 = wn * 32 + np * 16;
                uint32_t r0, r1, r2, r3;
                LDSM4(r0, r1, r2, r3,
                      u_Wc + (uint32_t)((n0 + lrow) * WRU + kl + lcol) * 4);
                bfr[2 * np][0] = r0; bfr[2 * np + 1][0] = r1;
                bfr[2 * np][1] = r2; bfr[2 * np + 1][1] = r3;
            }
            #pragma unroll
            for (int nt = 0; nt < 4; nt++)
                #pragma unroll
                for (int mt = 0; mt < 2; mt++)
                    mma_f16(ac2[mt][nt], afr[mt][0], afr[mt][1], afr[mt][2], afr[mt][3],
                            bfr[nt][0], bfr[nt][1]);
        }
    }

    #pragma unroll
    for (int mt = 0; mt < 2; mt++)
        #pragma unroll
        for (int nt = 0; nt < 4; nt++) {
            int r  = wm * 32 + mt * 16 + gid;
            int cb = wn * 32 + nt * 8 + tin * 2;
            int e0 = s_ss[r], e1 = s_ss[r + 8];
            if (e0 >= 0) {
                float v0 = fmaxf(ac2[mt][nt][0] + s_b2[cb], 0.f);
                float v1 = fmaxf(ac2[mt][nt][1] + s_b2[cb + 1], 0.f);
                REDV2(&edges[e0 * D + cb], v0, v1);
            }
            if (e1 >= 0) {
                float v0 = fmaxf(ac2[mt][nt][2] + s_b2[cb], 0.f);
                float v1 = fmaxf(ac2[mt][nt][3] + s_b2[cb + 1], 0.f);
                REDV2(&edges[e1 * D + cb], v0, v1);
            }
        }
}

// =====================================================================
// GRU: 384 threads (12 warps), 96-row tile, merged k-loop, tight frags
// smem: biases 2048 | XH [96][264h] 50688 | W 2x[384][144B] 110592 = 163328
// =====================================================================
#define GRU_SMEM (2048 + 96 * XSU * 4 + 2 * 384 * WRU * 4)
__global__ __launch_bounds__(384, 1) void gru_mma_kernel(
    const float*  __restrict__ x,
    float*        __restrict__ h,
    const __half* __restrict__ wgh,
    const float*  __restrict__ gbias,
    int E)
{
    extern __shared__ __align__(16) char smem[];
    float*    s_bz  = (float*)smem;
    float*    s_br  = (float*)(smem + 512);
    float*    s_bah = (float*)(smem + 1024);
    float*    s_bbh = (float*)(smem + 1536);
    uint32_t* XH    = (uint32_t*)(smem + 2048);
    const uint32_t u_base = smem_u32(smem);
    const uint32_t u_X = u_base + 2048;
    const uint32_t u_W = u_base + 2048 + 96 * XSU * 4;

    const int tid  = threadIdx.x;
    const int lane = tid & 31;
    const int gid  = lane >> 2, tin = lane & 3;
    const int lrow = (lane & 7) + ((lane >> 3) & 1) * 8;
    const int lcol = (lane >> 4) * 4;
    const int wid  = tid >> 5;       // 0..11
    const int wm   = wid >> 2;       // 0..2  (32-row group)
    const int wn   = wid & 3;        // 0..3  (32-col group)
    const int e0   = blockIdx.x * 96;

    if (tid < 128) {
        s_bz[tid]  = gbias[tid]       + gbias[384 + tid];
        s_br[tid]  = gbias[128 + tid] + gbias[512 + tid];
        s_bah[tid] = gbias[256 + tid];
        s_bbh[tid] = gbias[640 + tid];
    }

    const float4* xe4 = (const float4*)x;
    const float4* ln4 = (const float4*)h;
    #pragma unroll
    for (int it = 0; it < 16; it++) {
        int idx = it * 384 + tid;          // 6144 = 96 rows x 64 f4
        int m = idx >> 6, q = idx & 63;
        int e = e0 + m;
        float4 v = make_float4(0.f, 0.f, 0.f, 0.f);
        if (e < E) v = (q < 32) ? xe4[e * 32 + q] : ln4[e * 32 + (q - 32)];
        uint2 t;
        t.x = packh2(v.x, v.y);
        t.y = packh2(v.z, v.w);
        *(uint2*)&XH[m * XSU + q * 2] = t;
    }

    // all-weights chunk loader: 384 rows x 8 segs = 3072 -> 8/thread
    auto ldP = [&](int c, int buf) {
        #pragma unroll
        for (int i = 0; i < 8; i++) {
            int idx = i * 384 + tid;
            int row = idx >> 3, seg = idx & 7;
            uint32_t dst = u_W + (uint32_t)buf * (384 * WRU * 4)
                         + (uint32_t)(row * WRU * 4 + seg * 16);
            CP16(dst, (const char*)wgh + (row * 256 + c * 64 + seg * 8) * 2);
        }
    };

    const uint32_t u_A = u_X + (uint32_t)((wm * 32 + lrow) * XSU + lcol) * 4;

    float acc1[2][8][4], accA[2][4][4], accB[2][4][4];
    #pragma unroll
    for (int a = 0; a < 2; a++) {
        #pragma unroll
        for (int b = 0; b < 8; b++)
            #pragma unroll
            for (int i = 0; i < 4; i++) acc1[a][b][i] = 0.f;
        #pragma unroll
        for (int b = 0; b < 4; b++)
            #pragma unroll
            for (int i = 0; i < 4; i++) { accA[a][b][i] = 0.f; accB[a][b][i] = 0.f; }
    }

    ldP(0, 0); CP_COMMIT();
    for (int c = 0; c < 4; c++) {
        CP_WAIT0(); __syncthreads();
        if (c < 3) { ldP(c + 1, (c + 1) & 1); CP_COMMIT(); }
        const uint32_t u_Wc = u_W + (uint32_t)(c & 1) * (384 * WRU * 4);
        #pragma unroll
        for (int ks = 0; ks < 4; ks++) {
            const int ku = c * 32 + ks * 8;
            const int kl = ks * 8;
            uint32_t afr[2][4];
            #pragma unroll
            for (int mt = 0; mt < 2; mt++)
                LDSM4(afr[mt][0], afr[mt][1], afr[mt][2], afr[mt][3],
                      u_A + (uint32_t)(mt * 16 * XSU + ku) * 4);
            // tight fragment scheduling: each LDSM4 -> its 4 MMAs immediately
            #pragma unroll
            for (int jp = 0; jp < 4; jp++) {           // z (jp 0-1), r (jp 2-3)
                int n0 = (jp < 2) ? (wn * 32 + jp * 16)
                                  : (128 + wn * 32 + (jp - 2) * 16);
                uint32_t r0, r1, r2, r3;
                LDSM4(r0, r1, r2, r3,
                      u_Wc + (uint32_t)((n0 + lrow) * WRU + kl + lcol) * 4);
                #pragma unroll
                for (int mt = 0; mt < 2; mt++) {
                    mma_f16(acc1[mt][2 * jp],     afr[mt][0], afr[mt][1], afr[mt][2], afr[mt][3], r0, r2);
                    mma_f16(acc1[mt][2 * jp + 1], afr[mt][0], afr[mt][1], afr[mt][2], afr[mt][3], r1, r3);
                }
            }
            #pragma unroll
            for (int np = 0; np < 2; np++) {           // h-gate
                int n0 = 256 + wn * 32 + np * 16;
                uint32_t r0, r1, r2, r3;
                LDSM4(r0, r1, r2, r3,
                      u_Wc + (uint32_t)((n0 + lrow) * WRU + kl + lcol) * 4);
                if (c < 2) {
                    #pragma unroll
                    for (int mt = 0; mt < 2; mt++) {
                        mma_f16(accA[mt][2 * np],     afr[mt][0], afr[mt][1], afr[mt][2], afr[mt][3], r0, r2);
                        mma_f16(accA[mt][2 * np + 1], afr[mt][0], afr[mt][1], afr[mt][2], afr[mt][3], r1, r3);
                    }
                } else {
                    #pragma unroll
                    for (int mt = 0; mt < 2; mt++) {
                        mma_f16(accB[mt][2 * np],     afr[mt][0], afr[mt][1], afr[mt][2], afr[mt][3], r0, r2);
                        mma_f16(accB[mt][2 * np + 1], afr[mt][0], afr[mt][1], afr[mt][2], afr[mt][3], r1, r3);
                    }
                }
            }
        }
    }

    // ---- gate math + in-place update ----
    #pragma unroll
    for (int mt = 0; mt < 2; mt++)
        #pragma unroll
        for (int nt = 0; nt < 4; nt++) {
            int cb = wn * 32 + nt * 8 + tin * 2;
            #pragma unroll
            for (int half_ = 0; half_ < 2; half_++) {
                int r = wm * 32 + mt * 16 + gid + half_ * 8;
                int e = e0 + r;
                if (e < E) {
                    int i0 = half_ * 2;
                    float2 ho = *(const float2*)&h[e * D + cb];
                    float z0 = 1.f / (1.f + expf(-(acc1[mt][nt][i0]         + s_bz[cb])));
                    float z1 = 1.f / (1.f + expf(-(acc1[mt][nt][i0 + 1]     + s_bz[cb + 1])));
                    float r0 = 1.f / (1.f + expf(-(acc1[mt][nt + 4][i0]     + s_br[cb])));
                    float r1 = 1.f / (1.f + expf(-(acc1[mt][nt + 4][i0 + 1] + s_br[cb + 1])));
                    float h0 = tanhf(accA[mt][nt][i0]     + s_bah[cb]     + r0 * (accB[mt][nt][i0]     + s_bbh[cb]));
                    float h1 = tanhf(accA[mt][nt][i0 + 1] + s_bah[cb + 1] + r1 * (accB[mt][nt][i0 + 1] + s_bbh[cb + 1]));
                    float2 o;
                    o.x = z0 * ho.x + (1.f - z0) * h0;
                    o.y = z1 * ho.y + (1.f - z1) * h1;
                    *(float2*)&h[e * D + cb] = o;
                }
            }
        }
}

// ---------------- graph segment-sum (sorted graph ids) ----------------
#define GSROWS 512
__global__ __launch_bounds__(128) void graph_sum_kernel(
    const float* __restrict__ link, const int* __restrict__ gid,
    float* __restrict__ gs, int E)
{
    int tid = threadIdx.x;
    int r0 = blockIdx.x * GSROWS;
    if (r0 >= E) return;
    int r1 = min(r0 + GSROWS, E);
    float acc = 0.f;
    int cur = gid[r0];
    for (int r = r0; r < r1; r++) {
        int g = gid[r];
        if (g != cur) {
            atomicAdd(&gs[cur * D + tid], acc);
            acc = 0.f;
            cur = g;
        }
        acc += link[r * D + tid];
    }
    atomicAdd(&gs[cur * D + tid], acc);
}

// ---------------- readout MLP ----------------
__global__ __launch_bounds__(256) void readout_kernel(
    const float* __restrict__ gs,
    const float* __restrict__ rW1, const float* __restrict__ rb1,
    const float* __restrict__ rW2, const float* __restrict__ rb2,
    const float* __restrict__ rW3, const float* __restrict__ rb3,
    float* __restrict__ out)
{
    __shared__ float s_in[D];
    __shared__ float s_r1[HH];
    __shared__ float s_r2[HH];
    const int g = blockIdx.x;
    const int t = threadIdx.x;

    if (t < D) s_in[t] = gs[g * D + t];
    __syncthreads();

    float a = rb1[t];
    #pragma unroll 4
    for (int k = 0; k < D; k++) a = fmaf(s_in[k], rW1[k * HH + t], a);
    s_r1[t] = fmaxf(a, 0.f);
    __syncthreads();

    float b = rb2[t];
    #pragma unroll 4
    for (int k = 0; k < HH; k++) b = fmaf(s_r1[k], rW2[k * HH + t], b);
    s_r2[t] = fmaxf(b, 0.f) * rW3[t];
    __syncthreads();

    for (int s = 128; s > 0; s >>= 1) {
        if (t < s) s_r2[t] += s_r2[t + s];
        __syncthreads();
    }
    if (t == 0) out[g] = s_r2[0] + rb3[0];
}

// ---------------- launch ----------------
extern "C" void kernel_launch(void* const* d_in, const int* in_sizes, int n_in,
                              void* d_out, int out_size)
{
    const float* link0 = (const float*)d_in[0];
    const int*   sf    = (const int*)  d_in[1];
    const int*   ss    = (const int*)  d_in[2];
    const int*   gid   = (const int*)  d_in[3];
    const float* mW1 = (const float*)d_in[5];
    const float* mb1 = (const float*)d_in[6];
    const float* mW2 = (const float*)d_in[7];
    const float* mb2 = (const float*)d_in[8];
    const float* gk  = (const float*)d_in[9];
    const float* gr  = (const float*)d_in[10];
    const float* gb  = (const float*)d_in[11];
    const float* rW1 = (const float*)d_in[12];
    const float* rb1 = (const float*)d_in[13];
    const float* rW2 = (const float*)d_in[14];
    const float* rb2 = (const float*)d_in[15];
    const float* rW3 = (const float*)d_in[16];
    const float* rb3 = (const float*)d_in[17];
    float* out = (float*)d_out;

    const int M = in_sizes[1];
    const int E = in_sizes[3] <= EMAX ? in_sizes[3] : EMAX;

    float *link, *edges, *gs;
    __half *w1h, *w2h, *wgh;
    cudaGetSymbolAddress((void**)&link,  g_link);
    cudaGetSymbolAddress((void**)&edges, g_edges);
    cudaGetSymbolAddress((void**)&gs,    g_gs);
    cudaGetSymbolAddress((void**)&w1h,   g_w1h);
    cudaGetSymbolAddress((void**)&w2h,   g_w2h);
    cudaGetSymbolAddress((void**)&wgh,   g_wgh);

    cudaFuncSetAttribute(msg_mma_kernel, cudaFuncAttributeMaxDynamicSharedMemorySize, MSG_SMEM);
    cudaFuncSetAttribute(gru_mma_kernel, cudaFuncAttributeMaxDynamicSharedMemorySize, GRU_SMEM);

    const int n4 = E * (D / 4);
    copy_kernel<<<(n4 + 255) / 256, 256>>>((float4*)link, (const float4*)link0, n4);
    prep_all<<<768, 256>>>(mW1, mW2, gk, gr, w1h, w2h, wgh);

    const int mblocks = (M + 63) / 64;
    const int gblocks = (E + 95) / 96;
    for (int t = 0; t < TT; t++) {
        zero_kernel<<<(n4 + 255) / 256, 256>>>((float4*)edges, n4);
        msg_mma_kernel<<<mblocks, 256, MSG_SMEM>>>(link, sf, ss, w1h, mb1, w2h, mb2, edges, M);
        gru_mma_kernel<<<gblocks, 384, GRU_SMEM>>>(edges, link, wgh, gb, E);
    }

    const int gs4 = GG * D / 4;
    zero_kernel<<<(gs4 + 255) / 256, 256>>>((float4*)gs, gs4);
    graph_sum_kernel<<<(E + GSROWS - 1) / GSROWS, 128>>>(link, gid, gs, E);
    readout_kernel<<<GG, 256>>>(gs, rW1, rb1, rW2, rb2, rW3, rb3, out);
}